// round 1
// baseline (speedup 1.0000x reference)
#include <cuda_runtime.h>
#include <cstdint>

// Problem constants
#define Bb  4
#define Tt  2048
#define Dd  1024
#define Hh  16
#define HDh 64
#define Mm  (Bb * Tt)   // 8192 rows

// Scratch (device globals: allocation-free rule)
__device__ float g_Q[(size_t)Mm * Dd];
__device__ float g_K[(size_t)Mm * Dd];
__device__ float g_V[(size_t)Mm * Dd];
__device__ float g_C[(size_t)Mm * Dd];

// ----------------------------------------------------------------------------
// C[m,n] = sum_k A[m,k] * W[n,k] + bias[n]   (torch Linear: y = x @ W^T + b)
// BM=BN=128, BK=8, 8x8 per thread, 256 threads.
// ----------------------------------------------------------------------------
__global__ __launch_bounds__(256) void sgemm_nt_kernel(
    const float* __restrict__ A, const float* __restrict__ W,
    const float* __restrict__ bias, float* __restrict__ C,
    int Msz, int Nsz, int Ksz)
{
    __shared__ float As[8][128];
    __shared__ float Bs[8][128];

    const int tid = threadIdx.x;
    const int tr = tid >> 4;     // 0..15 -> C-row group
    const int tc = tid & 15;     // 0..15 -> C-col group

    const float* Ab = A + (size_t)blockIdx.y * 128 * Ksz;
    const float* Wb = W + (size_t)blockIdx.x * 128 * Ksz;

    const int lr = tid >> 1;          // 0..127 row within tile
    const int lk = (tid & 1) * 4;     // 0 or 4

    float acc[8][8];
#pragma unroll
    for (int i = 0; i < 8; i++)
#pragma unroll
        for (int j = 0; j < 8; j++) acc[i][j] = 0.f;

    for (int k0 = 0; k0 < Ksz; k0 += 8) {
        float4 a = *(const float4*)(Ab + (size_t)lr * Ksz + k0 + lk);
        float4 w = *(const float4*)(Wb + (size_t)lr * Ksz + k0 + lk);
        __syncthreads();   // previous iteration's reads done
        As[lk + 0][lr] = a.x; As[lk + 1][lr] = a.y;
        As[lk + 2][lr] = a.z; As[lk + 3][lr] = a.w;
        Bs[lk + 0][lr] = w.x; Bs[lk + 1][lr] = w.y;
        Bs[lk + 2][lr] = w.z; Bs[lk + 3][lr] = w.w;
        __syncthreads();
#pragma unroll
        for (int kk = 0; kk < 8; kk++) {
            float ra[8], rb[8];
            *(float4*)(ra)     = *(const float4*)(&As[kk][tr * 8]);
            *(float4*)(ra + 4) = *(const float4*)(&As[kk][tr * 8 + 4]);
            *(float4*)(rb)     = *(const float4*)(&Bs[kk][tc * 8]);
            *(float4*)(rb + 4) = *(const float4*)(&Bs[kk][tc * 8 + 4]);
#pragma unroll
            for (int i = 0; i < 8; i++)
#pragma unroll
                for (int j = 0; j < 8; j++)
                    acc[i][j] = fmaf(ra[i], rb[j], acc[i][j]);
        }
    }

    const int row0 = blockIdx.y * 128 + tr * 8;
    const int col0 = blockIdx.x * 128 + tc * 8;
#pragma unroll
    for (int i = 0; i < 8; i++) {
#pragma unroll
        for (int j4 = 0; j4 < 8; j4 += 4) {
            float4 o;
            o.x = acc[i][j4 + 0] + bias[col0 + j4 + 0];
            o.y = acc[i][j4 + 1] + bias[col0 + j4 + 1];
            o.z = acc[i][j4 + 2] + bias[col0 + j4 + 2];
            o.w = acc[i][j4 + 3] + bias[col0 + j4 + 3];
            *(float4*)(C + (size_t)(row0 + i) * Nsz + col0 + j4) = o;
        }
    }
}

// ----------------------------------------------------------------------------
// Fused flash attention. Grid: (T/64, H, B). Block: 256 threads (16x16),
// each thread owns a 4x4 score tile and a 4x4 output tile.
// Dynamic smem layout (floats):
//   Qt[64][64]  d-major (transposed), pre-scaled by 1/sqrt(HD)
//   Kt[64][64]  d-major (transposed)
//   Vs[64][64]  kv-major
//   Ps[64][65]  probabilities, padded pitch
// ----------------------------------------------------------------------------
__global__ __launch_bounds__(256) void attn_kernel(
    const float* __restrict__ Qg, const float* __restrict__ Kg,
    const float* __restrict__ Vg, const int* __restrict__ mask,
    float* __restrict__ Og)
{
    extern __shared__ float sm[];
    float* Qt = sm;            // 4096
    float* Kt = sm + 4096;     // 4096
    float* Vs = sm + 8192;     // 4096
    float* Ps = sm + 12288;    // 64*65 = 4160

    const int tid = threadIdx.x;
    const int ty = tid >> 4;   // 0..15 -> query rows ty*4..+3
    const int tx = tid & 15;   // 0..15 -> kv cols / hd cols tx*4..+3
    const int b  = blockIdx.z;
    const int h  = blockIdx.y;
    const int q0 = blockIdx.x << 6;

    const float* Qb = Qg + ((size_t)(b * Tt + q0)) * Dd + h * HDh;
    const float* Kb = Kg + ((size_t)b * Tt) * Dd + h * HDh;
    const float* Vb = Vg + ((size_t)b * Tt) * Dd + h * HDh;
    const int*   mb = mask + b * Tt;

    // Load Q tile transposed (d-major), scaled by 1/8
#pragma unroll
    for (int it = 0; it < 4; it++) {
        int i = tid + it * 256;
        int q = i & 63, dc = i >> 6;
        float4 v = *(const float4*)(Qb + (size_t)q * Dd + dc * 4);
        Qt[(dc * 4 + 0) * 64 + q] = v.x * 0.125f;
        Qt[(dc * 4 + 1) * 64 + q] = v.y * 0.125f;
        Qt[(dc * 4 + 2) * 64 + q] = v.z * 0.125f;
        Qt[(dc * 4 + 3) * 64 + q] = v.w * 0.125f;
    }

    float mrow[4], lrow[4], acc[4][4];
#pragma unroll
    for (int i = 0; i < 4; i++) {
        mrow[i] = -1e30f; lrow[i] = 0.f;
#pragma unroll
        for (int j = 0; j < 4; j++) acc[i][j] = 0.f;
    }

    for (int kt = 0; kt < Tt / 64; kt++) {
        const int kv0 = kt << 6;
        __syncthreads();   // previous tile's GEMM2 reads done
        // Load K transposed + V natural
#pragma unroll
        for (int it = 0; it < 4; it++) {
            int i = tid + it * 256;
            int c = i & 63, dc = i >> 6;
            float4 v = *(const float4*)(Kb + (size_t)(kv0 + c) * Dd + dc * 4);
            Kt[(dc * 4 + 0) * 64 + c] = v.x;
            Kt[(dc * 4 + 1) * 64 + c] = v.y;
            Kt[(dc * 4 + 2) * 64 + c] = v.z;
            Kt[(dc * 4 + 3) * 64 + c] = v.w;
            int r = i >> 4, vc = i & 15;
            float4 vv = *(const float4*)(Vb + (size_t)(kv0 + r) * Dd + vc * 4);
            *(float4*)(Vs + r * 64 + vc * 4) = vv;
        }
        __syncthreads();

        // GEMM1: S = (Q*scale) @ K^T  (64x64x64)
        float s[4][4];
#pragma unroll
        for (int i = 0; i < 4; i++)
#pragma unroll
            for (int j = 0; j < 4; j++) s[i][j] = 0.f;
#pragma unroll 16
        for (int d = 0; d < 64; d++) {
            float rq[4], rk[4];
            *(float4*)rq = *(const float4*)(Qt + d * 64 + ty * 4);
            *(float4*)rk = *(const float4*)(Kt + d * 64 + tx * 4);
#pragma unroll
            for (int i = 0; i < 4; i++)
#pragma unroll
                for (int j = 0; j < 4; j++)
                    s[i][j] = fmaf(rq[i], rk[j], s[i][j]);
        }

        // Padding mask over key positions
#pragma unroll
        for (int j = 0; j < 4; j++) {
            if (mb[kv0 + tx * 4 + j] == 0) {
#pragma unroll
                for (int i = 0; i < 4; i++) s[i][j] = -1e30f;
            }
        }

        // Online softmax update (row stats reduced across the 16 tx lanes)
#pragma unroll
        for (int i = 0; i < 4; i++) {
            float mx = fmaxf(fmaxf(s[i][0], s[i][1]), fmaxf(s[i][2], s[i][3]));
            mx = fmaxf(mx, __shfl_xor_sync(0xffffffffu, mx, 1));
            mx = fmaxf(mx, __shfl_xor_sync(0xffffffffu, mx, 2));
            mx = fmaxf(mx, __shfl_xor_sync(0xffffffffu, mx, 4));
            mx = fmaxf(mx, __shfl_xor_sync(0xffffffffu, mx, 8));
            float mnew  = fmaxf(mrow[i], mx);
            float alpha = __expf(mrow[i] - mnew);
            mrow[i] = mnew;
            float rs = 0.f;
#pragma unroll
            for (int j = 0; j < 4; j++) {
                s[i][j] = __expf(s[i][j] - mnew);
                rs += s[i][j];
            }
            rs += __shfl_xor_sync(0xffffffffu, rs, 1);
            rs += __shfl_xor_sync(0xffffffffu, rs, 2);
            rs += __shfl_xor_sync(0xffffffffu, rs, 4);
            rs += __shfl_xor_sync(0xffffffffu, rs, 8);
            lrow[i] = lrow[i] * alpha + rs;
#pragma unroll
            for (int j = 0; j < 4; j++) acc[i][j] *= alpha;
        }

        // Stage P to smem for the second GEMM
#pragma unroll
        for (int i = 0; i < 4; i++)
#pragma unroll
            for (int j = 0; j < 4; j++)
                Ps[(ty * 4 + i) * 65 + tx * 4 + j] = s[i][j];
        __syncthreads();

        // GEMM2: acc += P @ V  (64x64x64)
#pragma unroll 16
        for (int kk = 0; kk < 64; kk++) {
            float rv[4];
            *(float4*)rv = *(const float4*)(Vs + kk * 64 + tx * 4);
            float rp[4];
#pragma unroll
            for (int i = 0; i < 4; i++) rp[i] = Ps[(ty * 4 + i) * 65 + kk];
#pragma unroll
            for (int i = 0; i < 4; i++)
#pragma unroll
                for (int j = 0; j < 4; j++)
                    acc[i][j] = fmaf(rp[i], rv[j], acc[i][j]);
        }
    }

    // Epilogue: normalize and write ctx in (B,T,D) layout
#pragma unroll
    for (int i = 0; i < 4; i++) {
        float inv = 1.0f / lrow[i];
        float4 o;
        o.x = acc[i][0] * inv;
        o.y = acc[i][1] * inv;
        o.z = acc[i][2] * inv;
        o.w = acc[i][3] * inv;
        *(float4*)(Og + ((size_t)(b * Tt + q0 + ty * 4 + i)) * Dd + h * HDh + tx * 4) = o;
    }
}

// ----------------------------------------------------------------------------
extern "C" void kernel_launch(void* const* d_in, const int* in_sizes, int n_in,
                              void* d_out, int out_size)
{
    const float* x  = (const float*)d_in[0];
    const float* Wq = (const float*)d_in[1];
    const float* bq = (const float*)d_in[2];
    const float* Wk = (const float*)d_in[3];
    const float* bk = (const float*)d_in[4];
    const float* Wv = (const float*)d_in[5];
    const float* bv = (const float*)d_in[6];
    const float* Wo = (const float*)d_in[7];
    const float* bo = (const float*)d_in[8];
    const int* mask = (const int*)d_in[9];
    float* out = (float*)d_out;

    float *qp, *kp, *vp, *cp;
    cudaGetSymbolAddress((void**)&qp, g_Q);
    cudaGetSymbolAddress((void**)&kp, g_K);
    cudaGetSymbolAddress((void**)&vp, g_V);
    cudaGetSymbolAddress((void**)&cp, g_C);

    dim3 gemm_grid(Dd / 128, Mm / 128);   // (8, 64)

    // QKV projections
    sgemm_nt_kernel<<<gemm_grid, 256>>>(x, Wq, bq, qp, Mm, Dd, Dd);
    sgemm_nt_kernel<<<gemm_grid, 256>>>(x, Wk, bk, kp, Mm, Dd, Dd);
    sgemm_nt_kernel<<<gemm_grid, 256>>>(x, Wv, bv, vp, Mm, Dd, Dd);

    // Fused attention
    const int smem = (3 * 4096 + 64 * 65) * (int)sizeof(float);  // 65792 B
    cudaFuncSetAttribute(attn_kernel, cudaFuncAttributeMaxDynamicSharedMemorySize, smem);
    attn_kernel<<<dim3(Tt / 64, Hh, Bb), 256, smem>>>(qp, kp, vp, mask, cp);

    // Output projection
    sgemm_nt_kernel<<<gemm_grid, 256>>>(cp, Wo, bo, out, Mm, Dd, Dd);
}

// round 3
// speedup vs baseline: 1.3696x; 1.3696x over previous
#include <cuda_runtime.h>
#include <cuda_bf16.h>
#include <cstdint>

// Problem constants
#define Bb  4
#define Tt  2048
#define Dd  1024
#define Hh  16
#define HDh 64
#define Mm  (Bb * Tt)   // 8192 rows

// ---------------------------------------------------------------------------
// Scratch (device globals: allocation-free rule)
// ---------------------------------------------------------------------------
__device__ float g_Q[(size_t)Mm * Dd];
__device__ float g_K[(size_t)Mm * Dd];
__device__ float g_V[(size_t)Mm * Dd];
__device__ float g_C[(size_t)Mm * Dd];

__device__ __nv_bfloat16 g_xh[(size_t)Mm * Dd];
__device__ __nv_bfloat16 g_xl[(size_t)Mm * Dd];
__device__ __nv_bfloat16 g_ch[(size_t)Mm * Dd];
__device__ __nv_bfloat16 g_cl[(size_t)Mm * Dd];
__device__ __nv_bfloat16 g_wh[4 * (size_t)Dd * Dd];
__device__ __nv_bfloat16 g_wl[4 * (size_t)Dd * Dd];

// ---------------------------------------------------------------------------
// sm_100-base helpers: cp.async + mma.sync (NO tcgen05 — not available on
// this toolchain's sm_100 target).
// ---------------------------------------------------------------------------
__device__ __forceinline__ uint32_t smem_to_u32(const void* p) {
    uint32_t a;
    asm("{ .reg .u64 t; cvta.to.shared.u64 t, %1; cvt.u32.u64 %0, t; }"
        : "=r"(a) : "l"(p));
    return a;
}

__device__ __forceinline__ void cp_async16(uint32_t smem_addr, const void* gptr) {
    asm volatile("cp.async.cg.shared.global [%0], [%1], 16;"
                 :: "r"(smem_addr), "l"(gptr));
}
__device__ __forceinline__ void cp_commit() {
    asm volatile("cp.async.commit_group;");
}
template <int N>
__device__ __forceinline__ void cp_wait() {
    asm volatile("cp.async.wait_group %0;" :: "n"(N));
}

// D += A * B  (m16n8k16, bf16 inputs, fp32 accum; A row-major, B col-major)
__device__ __forceinline__ void mma16816(float* d, const uint32_t* a, const uint32_t* b) {
    asm volatile(
        "mma.sync.aligned.m16n8k16.row.col.f32.bf16.bf16.f32 "
        "{%0,%1,%2,%3}, {%4,%5,%6,%7}, {%8,%9}, {%0,%1,%2,%3};"
        : "+f"(d[0]), "+f"(d[1]), "+f"(d[2]), "+f"(d[3])
        : "r"(a[0]), "r"(a[1]), "r"(a[2]), "r"(a[3]), "r"(b[0]), "r"(b[1]));
}

// ---------------------------------------------------------------------------
// Split fp32 -> (bf16 hi, bf16 lo).  n4 = elements / 4.
// ---------------------------------------------------------------------------
__global__ __launch_bounds__(256) void split_kernel(
    const float* __restrict__ src,
    __nv_bfloat16* __restrict__ hi, __nv_bfloat16* __restrict__ lo, int n4)
{
    int i = blockIdx.x * blockDim.x + threadIdx.x;
    if (i >= n4) return;
    float4 v = ((const float4*)src)[i];
    __nv_bfloat16 h0 = __float2bfloat16(v.x);
    __nv_bfloat16 h1 = __float2bfloat16(v.y);
    __nv_bfloat16 h2 = __float2bfloat16(v.z);
    __nv_bfloat16 h3 = __float2bfloat16(v.w);
    __nv_bfloat16 l0 = __float2bfloat16(v.x - __bfloat162float(h0));
    __nv_bfloat16 l1 = __float2bfloat16(v.y - __bfloat162float(h1));
    __nv_bfloat16 l2 = __float2bfloat16(v.z - __bfloat162float(h2));
    __nv_bfloat16 l3 = __float2bfloat16(v.w - __bfloat162float(h3));
    union { __nv_bfloat16 b[4]; uint2 u; } ph, pl;
    ph.b[0] = h0; ph.b[1] = h1; ph.b[2] = h2; ph.b[3] = h3;
    pl.b[0] = l0; pl.b[1] = l1; pl.b[2] = l2; pl.b[3] = l3;
    ((uint2*)hi)[i] = ph.u;
    ((uint2*)lo)[i] = pl.u;
}

// ---------------------------------------------------------------------------
// bf16x3 mma.sync GEMM:  C[m,n] = sum_k A[m,k]*W[n,k] + bias[n]
//   (C = Ah*Bh + Ah*Bl + Al*Bh, fp32 accumulate; Al*Bl dropped ~2^-16)
// Tile 128x128, BK=32, 8 warps (4 over M x 2 over N), warp tile 32x64.
// 2-stage cp.async pipeline. Smem rows padded to 40 bf16 (20 words) for
// conflict-free fragment loads.
// ---------------------------------------------------------------------------
#define GPITCH 40                       // bf16 elems per smem row
#define GTILE_B (128 * GPITCH * 2)      // 10240 B per tile
#define GSTAGE_B (4 * GTILE_B)          // Ah, Al, Bh, Bl
#define GSMEM_B (2 * GSTAGE_B)          // 81920 B

__global__ __launch_bounds__(256, 1) void gemm_bf16x3_mma(
    const __nv_bfloat16* __restrict__ Ah, const __nv_bfloat16* __restrict__ Al,
    const __nv_bfloat16* __restrict__ Bh, const __nv_bfloat16* __restrict__ Bl,
    const float* __restrict__ bias, float* __restrict__ C)
{
    extern __shared__ __align__(128) uint8_t smem[];
    const int tid  = threadIdx.x;
    const int wid  = tid >> 5;
    const int lane = tid & 31;
    const int wm   = wid & 3;      // warp row block (32 rows each)
    const int wn   = wid >> 2;     // warp col block (64 cols each)
    const int gm0  = blockIdx.y * 128;
    const int gn0  = blockIdx.x * 128;
    const uint32_t sbase = smem_to_u32(smem);

    const __nv_bfloat16* srcs[4] = { Ah, Al, Bh, Bl };

    // ---- async stage issue: stage s <- K-chunk c (32 wide)
    auto issue = [&](int s, int c) {
        const int k0 = c * 32;
#pragma unroll
        for (int t = 0; t < 4; ++t) {
            const __nv_bfloat16* src = srcs[t];
            const int rbase = (t < 2) ? gm0 : gn0;
#pragma unroll
            for (int j = 0; j < 2; ++j) {
                const int i = tid + j * 256;           // 0..511
                const int row = i >> 2, chunk = i & 3; // 4x16B per 64B row
                const uint32_t sa = sbase + s * GSTAGE_B + t * GTILE_B
                                  + (uint32_t)(row * GPITCH + chunk * 8) * 2;
                const void* g = src + (size_t)(rbase + row) * Dd + k0 + chunk * 8;
                cp_async16(sa, g);
            }
        }
        cp_commit();
    };

    float acc[2][8][4];
#pragma unroll
    for (int mt = 0; mt < 2; ++mt)
#pragma unroll
        for (int nt = 0; nt < 8; ++nt)
#pragma unroll
            for (int q = 0; q < 4; ++q) acc[mt][nt][q] = 0.f;

    const int r   = lane >> 2;        // 0..7
    const int cp2 = (lane & 3) * 2;   // 0,2,4,6

    issue(0, 0);

    for (int c = 0; c < 32; ++c) {
        const int s = c & 1;
        if (c + 1 < 32) { issue((c + 1) & 1, c + 1); cp_wait<1>(); }
        else            { cp_wait<0>(); }
        __syncthreads();

        const uint8_t* stg = smem + s * GSTAGE_B;
        const uint8_t* pAh = stg;
        const uint8_t* pAl = stg + GTILE_B;
        const uint8_t* pBh = stg + 2 * GTILE_B;
        const uint8_t* pBl = stg + 3 * GTILE_B;

#pragma unroll
        for (int ks = 0; ks < 2; ++ks) {
            const int kk = ks * 16;
            uint32_t ah[2][4], al[2][4];
#pragma unroll
            for (int mt = 0; mt < 2; ++mt) {
                const int row = wm * 32 + mt * 16 + r;
                const uint32_t o00 = (uint32_t)(row * GPITCH + kk + cp2) * 2;
                const uint32_t o10 = (uint32_t)((row + 8) * GPITCH + kk + cp2) * 2;
                ah[mt][0] = *(const uint32_t*)(pAh + o00);
                ah[mt][1] = *(const uint32_t*)(pAh + o10);
                ah[mt][2] = *(const uint32_t*)(pAh + o00 + 16);
                ah[mt][3] = *(const uint32_t*)(pAh + o10 + 16);
                al[mt][0] = *(const uint32_t*)(pAl + o00);
                al[mt][1] = *(const uint32_t*)(pAl + o10);
                al[mt][2] = *(const uint32_t*)(pAl + o00 + 16);
                al[mt][3] = *(const uint32_t*)(pAl + o10 + 16);
            }
#pragma unroll
            for (int nt = 0; nt < 8; ++nt) {
                const int n = wn * 64 + nt * 8 + r;
                const uint32_t ob = (uint32_t)(n * GPITCH + kk + cp2) * 2;
                uint32_t bh[2], bl[2];
                bh[0] = *(const uint32_t*)(pBh + ob);
                bh[1] = *(const uint32_t*)(pBh + ob + 16);
                bl[0] = *(const uint32_t*)(pBl + ob);
                bl[1] = *(const uint32_t*)(pBl + ob + 16);
                mma16816(acc[0][nt], ah[0], bh);
                mma16816(acc[1][nt], ah[1], bh);
                mma16816(acc[0][nt], ah[0], bl);
                mma16816(acc[1][nt], ah[1], bl);
                mma16816(acc[0][nt], al[0], bh);
                mma16816(acc[1][nt], al[1], bh);
            }
        }
        __syncthreads();
    }

    // Epilogue: bias add + fp32 store
#pragma unroll
    for (int mt = 0; mt < 2; ++mt) {
        const int row0 = gm0 + wm * 32 + mt * 16 + r;
#pragma unroll
        for (int nt = 0; nt < 8; ++nt) {
            const int col = gn0 + wn * 64 + nt * 8 + cp2;
            const float b0 = bias[col], b1 = bias[col + 1];
            float2 v0, v1;
            v0.x = acc[mt][nt][0] + b0; v0.y = acc[mt][nt][1] + b1;
            v1.x = acc[mt][nt][2] + b0; v1.y = acc[mt][nt][3] + b1;
            *(float2*)(C + (size_t)row0 * Dd + col)       = v0;
            *(float2*)(C + (size_t)(row0 + 8) * Dd + col) = v1;
        }
    }
}

// ---------------------------------------------------------------------------
// Fused flash attention (unchanged from Round 1 — verified correct).
// ---------------------------------------------------------------------------
__global__ __launch_bounds__(256) void attn_kernel(
    const float* __restrict__ Qg, const float* __restrict__ Kg,
    const float* __restrict__ Vg, const int* __restrict__ mask,
    float* __restrict__ Og)
{
    extern __shared__ float sm[];
    float* Qt = sm;
    float* Kt = sm + 4096;
    float* Vs = sm + 8192;
    float* Ps = sm + 12288;

    const int tid = threadIdx.x;
    const int ty = tid >> 4;
    const int tx = tid & 15;
    const int b  = blockIdx.z;
    const int h  = blockIdx.y;
    const int q0 = blockIdx.x << 6;

    const float* Qb = Qg + ((size_t)(b * Tt + q0)) * Dd + h * HDh;
    const float* Kb = Kg + ((size_t)b * Tt) * Dd + h * HDh;
    const float* Vb = Vg + ((size_t)b * Tt) * Dd + h * HDh;
    const int*   mb = mask + b * Tt;

#pragma unroll
    for (int it = 0; it < 4; it++) {
        int i = tid + it * 256;
        int q = i & 63, dc = i >> 6;
        float4 v = *(const float4*)(Qb + (size_t)q * Dd + dc * 4);
        Qt[(dc * 4 + 0) * 64 + q] = v.x * 0.125f;
        Qt[(dc * 4 + 1) * 64 + q] = v.y * 0.125f;
        Qt[(dc * 4 + 2) * 64 + q] = v.z * 0.125f;
        Qt[(dc * 4 + 3) * 64 + q] = v.w * 0.125f;
    }

    float mrow[4], lrow[4], acc[4][4];
#pragma unroll
    for (int i = 0; i < 4; i++) {
        mrow[i] = -1e30f; lrow[i] = 0.f;
#pragma unroll
        for (int j = 0; j < 4; j++) acc[i][j] = 0.f;
    }

    for (int kt = 0; kt < Tt / 64; kt++) {
        const int kv0 = kt << 6;
        __syncthreads();
#pragma unroll
        for (int it = 0; it < 4; it++) {
            int i = tid + it * 256;
            int cidx = i & 63, dc = i >> 6;
            float4 v = *(const float4*)(Kb + (size_t)(kv0 + cidx) * Dd + dc * 4);
            Kt[(dc * 4 + 0) * 64 + cidx] = v.x;
            Kt[(dc * 4 + 1) * 64 + cidx] = v.y;
            Kt[(dc * 4 + 2) * 64 + cidx] = v.z;
            Kt[(dc * 4 + 3) * 64 + cidx] = v.w;
            int rr = i >> 4, vc = i & 15;
            float4 vv = *(const float4*)(Vb + (size_t)(kv0 + rr) * Dd + vc * 4);
            *(float4*)(Vs + rr * 64 + vc * 4) = vv;
        }
        __syncthreads();

        float s[4][4];
#pragma unroll
        for (int i = 0; i < 4; i++)
#pragma unroll
            for (int j = 0; j < 4; j++) s[i][j] = 0.f;
#pragma unroll 16
        for (int d = 0; d < 64; d++) {
            float rq[4], rk[4];
            *(float4*)rq = *(const float4*)(Qt + d * 64 + ty * 4);
            *(float4*)rk = *(const float4*)(Kt + d * 64 + tx * 4);
#pragma unroll
            for (int i = 0; i < 4; i++)
#pragma unroll
                for (int j = 0; j < 4; j++)
                    s[i][j] = fmaf(rq[i], rk[j], s[i][j]);
        }

#pragma unroll
        for (int j = 0; j < 4; j++) {
            if (mb[kv0 + tx * 4 + j] == 0) {
#pragma unroll
                for (int i = 0; i < 4; i++) s[i][j] = -1e30f;
            }
        }

#pragma unroll
        for (int i = 0; i < 4; i++) {
            float mx = fmaxf(fmaxf(s[i][0], s[i][1]), fmaxf(s[i][2], s[i][3]));
            mx = fmaxf(mx, __shfl_xor_sync(0xffffffffu, mx, 1));
            mx = fmaxf(mx, __shfl_xor_sync(0xffffffffu, mx, 2));
            mx = fmaxf(mx, __shfl_xor_sync(0xffffffffu, mx, 4));
            mx = fmaxf(mx, __shfl_xor_sync(0xffffffffu, mx, 8));
            float mnew  = fmaxf(mrow[i], mx);
            float alpha = __expf(mrow[i] - mnew);
            mrow[i] = mnew;
            float rs = 0.f;
#pragma unroll
            for (int j = 0; j < 4; j++) {
                s[i][j] = __expf(s[i][j] - mnew);
                rs += s[i][j];
            }
            rs += __shfl_xor_sync(0xffffffffu, rs, 1);
            rs += __shfl_xor_sync(0xffffffffu, rs, 2);
            rs += __shfl_xor_sync(0xffffffffu, rs, 4);
            rs += __shfl_xor_sync(0xffffffffu, rs, 8);
            lrow[i] = lrow[i] * alpha + rs;
#pragma unroll
            for (int j = 0; j < 4; j++) acc[i][j] *= alpha;
        }

#pragma unroll
        for (int i = 0; i < 4; i++)
#pragma unroll
            for (int j = 0; j < 4; j++)
                Ps[(ty * 4 + i) * 65 + tx * 4 + j] = s[i][j];
        __syncthreads();

#pragma unroll 16
        for (int kk = 0; kk < 64; kk++) {
            float rv[4];
            *(float4*)rv = *(const float4*)(Vs + kk * 64 + tx * 4);
            float rp[4];
#pragma unroll
            for (int i = 0; i < 4; i++) rp[i] = Ps[(ty * 4 + i) * 65 + kk];
#pragma unroll
            for (int i = 0; i < 4; i++)
#pragma unroll
                for (int j = 0; j < 4; j++)
                    acc[i][j] = fmaf(rp[i], rv[j], acc[i][j]);
        }
    }

#pragma unroll
    for (int i = 0; i < 4; i++) {
        float inv = 1.0f / lrow[i];
        float4 o;
        o.x = acc[i][0] * inv;
        o.y = acc[i][1] * inv;
        o.z = acc[i][2] * inv;
        o.w = acc[i][3] * inv;
        *(float4*)(Og + ((size_t)(b * Tt + q0 + ty * 4 + i)) * Dd + h * HDh + tx * 4) = o;
    }
}

// ---------------------------------------------------------------------------
extern "C" void kernel_launch(void* const* d_in, const int* in_sizes, int n_in,
                              void* d_out, int out_size)
{
    const float* x  = (const float*)d_in[0];
    const float* Wq = (const float*)d_in[1];
    const float* bq = (const float*)d_in[2];
    const float* Wk = (const float*)d_in[3];
    const float* bk = (const float*)d_in[4];
    const float* Wv = (const float*)d_in[5];
    const float* bv = (const float*)d_in[6];
    const float* Wo = (const float*)d_in[7];
    const float* bo = (const float*)d_in[8];
    const int* mask = (const int*)d_in[9];
    float* out = (float*)d_out;

    float *qp, *kp, *vp, *cp;
    cudaGetSymbolAddress((void**)&qp, g_Q);
    cudaGetSymbolAddress((void**)&kp, g_K);
    cudaGetSymbolAddress((void**)&vp, g_V);
    cudaGetSymbolAddress((void**)&cp, g_C);
    __nv_bfloat16 *xh, *xl, *ch, *cl, *wh, *wl;
    cudaGetSymbolAddress((void**)&xh, g_xh);
    cudaGetSymbolAddress((void**)&xl, g_xl);
    cudaGetSymbolAddress((void**)&ch, g_ch);
    cudaGetSymbolAddress((void**)&cl, g_cl);
    cudaGetSymbolAddress((void**)&wh, g_wh);
    cudaGetSymbolAddress((void**)&wl, g_wl);

    const size_t WSZ = (size_t)Dd * Dd;
    const int n4x = (Mm * Dd) / 4;
    const int n4w = (int)(WSZ / 4);

    // Split inputs to bf16 hi/lo
    split_kernel<<<(n4x + 255) / 256, 256>>>(x, xh, xl, n4x);
    split_kernel<<<(n4w + 255) / 256, 256>>>(Wq, wh + 0 * WSZ, wl + 0 * WSZ, n4w);
    split_kernel<<<(n4w + 255) / 256, 256>>>(Wk, wh + 1 * WSZ, wl + 1 * WSZ, n4w);
    split_kernel<<<(n4w + 255) / 256, 256>>>(Wv, wh + 2 * WSZ, wl + 2 * WSZ, n4w);
    split_kernel<<<(n4w + 255) / 256, 256>>>(Wo, wh + 3 * WSZ, wl + 3 * WSZ, n4w);

    // QKV projections on mma.sync bf16x3
    cudaFuncSetAttribute(gemm_bf16x3_mma,
                         cudaFuncAttributeMaxDynamicSharedMemorySize, GSMEM_B);
    dim3 ggrid(Dd / 128, Mm / 128);   // (8, 64)
    gemm_bf16x3_mma<<<ggrid, 256, GSMEM_B>>>(xh, xl, wh + 0 * WSZ, wl + 0 * WSZ, bq, qp);
    gemm_bf16x3_mma<<<ggrid, 256, GSMEM_B>>>(xh, xl, wh + 1 * WSZ, wl + 1 * WSZ, bk, kp);
    gemm_bf16x3_mma<<<ggrid, 256, GSMEM_B>>>(xh, xl, wh + 2 * WSZ, wl + 2 * WSZ, bv, vp);

    // Fused attention (fp32 SIMT)
    const int asmem = (3 * 4096 + 64 * 65) * (int)sizeof(float);
    cudaFuncSetAttribute(attn_kernel, cudaFuncAttributeMaxDynamicSharedMemorySize, asmem);
    attn_kernel<<<dim3(Tt / 64, Hh, Bb), 256, asmem>>>(qp, kp, vp, mask, cp);

    // Split ctx, output projection
    split_kernel<<<(n4x + 255) / 256, 256>>>(cp, ch, cl, n4x);
    gemm_bf16x3_mma<<<ggrid, 256, GSMEM_B>>>(ch, cl, wh + 3 * WSZ, wl + 3 * WSZ, bo, out);
}

// round 5
// speedup vs baseline: 2.6537x; 1.9375x over previous
#include <cuda_runtime.h>
#include <cuda_bf16.h>
#include <cstdint>

// Problem constants
#define Bb  4
#define Tt  2048
#define Dd  1024
#define Hh  16
#define HDh 64
#define Mm  (Bb * Tt)   // 8192 rows

// ---------------------------------------------------------------------------
// Scratch (device globals: allocation-free rule)
// ---------------------------------------------------------------------------
__device__ __nv_bfloat16 g_xh[(size_t)Mm * Dd];
__device__ __nv_bfloat16 g_xl[(size_t)Mm * Dd];
__device__ __nv_bfloat16 g_qh[(size_t)Mm * Dd];
__device__ __nv_bfloat16 g_ql[(size_t)Mm * Dd];
__device__ __nv_bfloat16 g_kh[(size_t)Mm * Dd];
__device__ __nv_bfloat16 g_kl[(size_t)Mm * Dd];
__device__ __nv_bfloat16 g_vh[(size_t)Mm * Dd];
__device__ __nv_bfloat16 g_vl[(size_t)Mm * Dd];
__device__ __nv_bfloat16 g_ch[(size_t)Mm * Dd];
__device__ __nv_bfloat16 g_cl[(size_t)Mm * Dd];
__device__ __nv_bfloat16 g_wh[4 * (size_t)Dd * Dd];
__device__ __nv_bfloat16 g_wl[4 * (size_t)Dd * Dd];

// ---------------------------------------------------------------------------
// sm_100-base helpers: cp.async + mma.sync (tcgen05 unavailable on this target)
// ---------------------------------------------------------------------------
__device__ __forceinline__ uint32_t smem_to_u32(const void* p) {
    uint32_t a;
    asm("{ .reg .u64 t; cvta.to.shared.u64 t, %1; cvt.u32.u64 %0, t; }"
        : "=r"(a) : "l"(p));
    return a;
}
__device__ __forceinline__ void cp_async16(uint32_t smem_addr, const void* gptr) {
    asm volatile("cp.async.cg.shared.global [%0], [%1], 16;"
                 :: "r"(smem_addr), "l"(gptr));
}
__device__ __forceinline__ void cp_commit() {
    asm volatile("cp.async.commit_group;");
}
template <int N>
__device__ __forceinline__ void cp_wait() {
    asm volatile("cp.async.wait_group %0;" :: "n"(N));
}
__device__ __forceinline__ void mma16816(float* d, const uint32_t* a, const uint32_t* b) {
    asm volatile(
        "mma.sync.aligned.m16n8k16.row.col.f32.bf16.bf16.f32 "
        "{%0,%1,%2,%3}, {%4,%5,%6,%7}, {%8,%9}, {%0,%1,%2,%3};"
        : "+f"(d[0]), "+f"(d[1]), "+f"(d[2]), "+f"(d[3])
        : "r"(a[0]), "r"(a[1]), "r"(a[2]), "r"(a[3]), "r"(b[0]), "r"(b[1]));
}
__device__ __forceinline__ uint32_t bf2_bits(__nv_bfloat162 v) {
    union { __nv_bfloat162 b; uint32_t u; } cv; cv.b = v; return cv.u;
}

// ---------------------------------------------------------------------------
// Split fp32 -> (bf16 hi, bf16 lo).
// ---------------------------------------------------------------------------
__global__ __launch_bounds__(256) void split_kernel(
    const float* __restrict__ src,
    __nv_bfloat16* __restrict__ hi, __nv_bfloat16* __restrict__ lo, int n4)
{
    int i = blockIdx.x * blockDim.x + threadIdx.x;
    if (i >= n4) return;
    float4 v = ((const float4*)src)[i];
    __nv_bfloat16 h0 = __float2bfloat16(v.x);
    __nv_bfloat16 h1 = __float2bfloat16(v.y);
    __nv_bfloat16 h2 = __float2bfloat16(v.z);
    __nv_bfloat16 h3 = __float2bfloat16(v.w);
    __nv_bfloat16 l0 = __float2bfloat16(v.x - __bfloat162float(h0));
    __nv_bfloat16 l1 = __float2bfloat16(v.y - __bfloat162float(h1));
    __nv_bfloat16 l2 = __float2bfloat16(v.z - __bfloat162float(h2));
    __nv_bfloat16 l3 = __float2bfloat16(v.w - __bfloat162float(h3));
    union { __nv_bfloat16 b[4]; uint2 u; } ph, pl;
    ph.b[0] = h0; ph.b[1] = h1; ph.b[2] = h2; ph.b[3] = h3;
    pl.b[0] = l0; pl.b[1] = l1; pl.b[2] = l2; pl.b[3] = l3;
    ((uint2*)hi)[i] = ph.u;
    ((uint2*)lo)[i] = pl.u;
}

// ---------------------------------------------------------------------------
// bf16x3 mma.sync GEMM:  C = A @ W^T + bias.
// Epilogue: if Oh != nullptr -> write bf16 hi/lo (scaled); else fp32 Cf32.
// ---------------------------------------------------------------------------
#define GPITCH 40
#define GTILE_B (128 * GPITCH * 2)
#define GSTAGE_B (4 * GTILE_B)
#define GSMEM_B (2 * GSTAGE_B)

__global__ __launch_bounds__(256, 1) void gemm_bf16x3_mma(
    const __nv_bfloat16* __restrict__ Ah, const __nv_bfloat16* __restrict__ Al,
    const __nv_bfloat16* __restrict__ Bh, const __nv_bfloat16* __restrict__ Bl,
    const float* __restrict__ bias, float* __restrict__ Cf32,
    __nv_bfloat16* __restrict__ Oh, __nv_bfloat16* __restrict__ Ol, float scale)
{
    extern __shared__ __align__(128) uint8_t smem[];
    const int tid  = threadIdx.x;
    const int wid  = tid >> 5;
    const int lane = tid & 31;
    const int wm   = wid & 3;
    const int wn   = wid >> 2;
    const int gm0  = blockIdx.y * 128;
    const int gn0  = blockIdx.x * 128;
    const uint32_t sbase = smem_to_u32(smem);

    const __nv_bfloat16* srcs[4] = { Ah, Al, Bh, Bl };

    auto issue = [&](int s, int c) {
        const int k0 = c * 32;
#pragma unroll
        for (int t = 0; t < 4; ++t) {
            const __nv_bfloat16* src = srcs[t];
            const int rbase = (t < 2) ? gm0 : gn0;
#pragma unroll
            for (int j = 0; j < 2; ++j) {
                const int i = tid + j * 256;
                const int row = i >> 2, chunk = i & 3;
                const uint32_t sa = sbase + s * GSTAGE_B + t * GTILE_B
                                  + (uint32_t)(row * GPITCH + chunk * 8) * 2;
                const void* g = src + (size_t)(rbase + row) * Dd + k0 + chunk * 8;
                cp_async16(sa, g);
            }
        }
        cp_commit();
    };

    float acc[2][8][4];
#pragma unroll
    for (int mt = 0; mt < 2; ++mt)
#pragma unroll
        for (int nt = 0; nt < 8; ++nt)
#pragma unroll
            for (int q = 0; q < 4; ++q) acc[mt][nt][q] = 0.f;

    const int r   = lane >> 2;
    const int cp2 = (lane & 3) * 2;

    issue(0, 0);

    for (int c = 0; c < 32; ++c) {
        const int s = c & 1;
        if (c + 1 < 32) { issue((c + 1) & 1, c + 1); cp_wait<1>(); }
        else            { cp_wait<0>(); }
        __syncthreads();

        const uint8_t* stg = smem + s * GSTAGE_B;
        const uint8_t* pAh = stg;
        const uint8_t* pAl = stg + GTILE_B;
        const uint8_t* pBh = stg + 2 * GTILE_B;
        const uint8_t* pBl = stg + 3 * GTILE_B;

#pragma unroll
        for (int ks = 0; ks < 2; ++ks) {
            const int kk = ks * 16;
            uint32_t ah[2][4], al[2][4];
#pragma unroll
            for (int mt = 0; mt < 2; ++mt) {
                const int row = wm * 32 + mt * 16 + r;
                const uint32_t o00 = (uint32_t)(row * GPITCH + kk + cp2) * 2;
                const uint32_t o10 = (uint32_t)((row + 8) * GPITCH + kk + cp2) * 2;
                ah[mt][0] = *(const uint32_t*)(pAh + o00);
                ah[mt][1] = *(const uint32_t*)(pAh + o10);
                ah[mt][2] = *(const uint32_t*)(pAh + o00 + 16);
                ah[mt][3] = *(const uint32_t*)(pAh + o10 + 16);
                al[mt][0] = *(const uint32_t*)(pAl + o00);
                al[mt][1] = *(const uint32_t*)(pAl + o10);
                al[mt][2] = *(const uint32_t*)(pAl + o00 + 16);
                al[mt][3] = *(const uint32_t*)(pAl + o10 + 16);
            }
#pragma unroll
            for (int nt = 0; nt < 8; ++nt) {
                const int n = wn * 64 + nt * 8 + r;
                const uint32_t ob = (uint32_t)(n * GPITCH + kk + cp2) * 2;
                uint32_t bh[2], bl[2];
                bh[0] = *(const uint32_t*)(pBh + ob);
                bh[1] = *(const uint32_t*)(pBh + ob + 16);
                bl[0] = *(const uint32_t*)(pBl + ob);
                bl[1] = *(const uint32_t*)(pBl + ob + 16);
                mma16816(acc[0][nt], ah[0], bh);
                mma16816(acc[1][nt], ah[1], bh);
                mma16816(acc[0][nt], ah[0], bl);
                mma16816(acc[1][nt], ah[1], bl);
                mma16816(acc[0][nt], al[0], bh);
                mma16816(acc[1][nt], al[1], bh);
            }
        }
        __syncthreads();
    }

    // Epilogue
#pragma unroll
    for (int mt = 0; mt < 2; ++mt) {
        const int row0 = gm0 + wm * 32 + mt * 16 + r;
#pragma unroll
        for (int nt = 0; nt < 8; ++nt) {
            const int col = gn0 + wn * 64 + nt * 8 + cp2;
            const float b0 = bias[col], b1 = bias[col + 1];
            float v0 = acc[mt][nt][0] + b0, v1 = acc[mt][nt][1] + b1;
            float v2 = acc[mt][nt][2] + b0, v3 = acc[mt][nt][3] + b1;
            if (Oh) {
                v0 *= scale; v1 *= scale; v2 *= scale; v3 *= scale;
                __nv_bfloat162 h01 = __floats2bfloat162_rn(v0, v1);
                __nv_bfloat162 h23 = __floats2bfloat162_rn(v2, v3);
                __nv_bfloat162 l01 = __floats2bfloat162_rn(
                    v0 - __bfloat162float(h01.x), v1 - __bfloat162float(h01.y));
                __nv_bfloat162 l23 = __floats2bfloat162_rn(
                    v2 - __bfloat162float(h23.x), v3 - __bfloat162float(h23.y));
                *(uint32_t*)(Oh + (size_t)row0 * Dd + col)       = bf2_bits(h01);
                *(uint32_t*)(Ol + (size_t)row0 * Dd + col)       = bf2_bits(l01);
                *(uint32_t*)(Oh + (size_t)(row0 + 8) * Dd + col) = bf2_bits(h23);
                *(uint32_t*)(Ol + (size_t)(row0 + 8) * Dd + col) = bf2_bits(l23);
            } else {
                float2 w0, w1;
                w0.x = v0; w0.y = v1; w1.x = v2; w1.y = v3;
                *(float2*)(Cf32 + (size_t)row0 * Dd + col)       = w0;
                *(float2*)(Cf32 + (size_t)(row0 + 8) * Dd + col) = w1;
            }
        }
    }
}

// ---------------------------------------------------------------------------
// Flash attention on mma.sync bf16x3.
// Grid (T/128, H, B), 256 threads = 8 warps; warp w owns q rows [16w,16w+16).
// Q pre-scaled by 1/8 (done in Q projection epilogue).
// ---------------------------------------------------------------------------
#define QPITCH 72     // bf16; pitch%64==8 -> conflict-free frag loads
#define VPITCH 136
#define AT_QH   0
#define AT_QL   18432
#define AT_K0   36864          // + s*36864; hi at +0, lo at +18432
#define AT_VH   110592
#define AT_VL   128000
#define AT_BIAS 145408
#define AT_SMEM 145920

__global__ __launch_bounds__(256, 1) void attn_mma_kernel(
    const __nv_bfloat16* __restrict__ qh, const __nv_bfloat16* __restrict__ ql,
    const __nv_bfloat16* __restrict__ kh, const __nv_bfloat16* __restrict__ kl,
    const __nv_bfloat16* __restrict__ vh, const __nv_bfloat16* __restrict__ vl,
    const int* __restrict__ mask,
    __nv_bfloat16* __restrict__ och, __nv_bfloat16* __restrict__ ocl)
{
    extern __shared__ __align__(128) uint8_t sm[];
    const uint32_t sb = smem_to_u32(sm);
    const int tid = threadIdx.x, wid = tid >> 5, lane = tid & 31;
    const int r = lane >> 2, c2 = (lane & 3) * 2;
    const int b = blockIdx.z, h = blockIdx.y;
    const int q0 = blockIdx.x * 128;
    const size_t gq = ((size_t)(b * Tt + q0)) * Dd + h * HDh;
    const size_t gk = ((size_t)(b * Tt)) * Dd + h * HDh;
    const int* mb = mask + b * Tt;

    // ---- preamble: stage Q (hi/lo) and K tile 0 via cp.async
#pragma unroll
    for (int j = 0; j < 4; ++j) {
        const int i = tid + j * 256, row = i >> 3, seg = i & 7;
        const uint32_t so = (uint32_t)((row * QPITCH + seg * 8) * 2);
        const size_t go = (size_t)row * Dd + seg * 8;
        cp_async16(sb + AT_QH + so, qh + gq + go);
        cp_async16(sb + AT_QL + so, ql + gq + go);
        cp_async16(sb + AT_K0 + so, kh + gk + go);
        cp_async16(sb + AT_K0 + 18432 + so, kl + gk + go);
    }
    cp_commit();

    // ---- V register prefetch: thread -> kv rows 2vj,2vj+1, hd quarter vq*16
    const int vj = tid >> 2;
    const int vq = tid & 3;
    uint4 vr_h[2][2], vr_l[2][2];
    {
#pragma unroll
        for (int rr = 0; rr < 2; ++rr) {
            const size_t g = ((size_t)(b * Tt + 2 * vj + rr)) * Dd + h * HDh + vq * 16;
            vr_h[rr][0] = *(const uint4*)(vh + g);
            vr_h[rr][1] = *(const uint4*)(vh + g + 8);
            vr_l[rr][0] = *(const uint4*)(vl + g);
            vr_l[rr][1] = *(const uint4*)(vl + g + 8);
        }
    }

    float cacc[8][4];
#pragma unroll
    for (int nt = 0; nt < 8; ++nt)
#pragma unroll
        for (int q = 0; q < 4; ++q) cacc[nt][q] = 0.f;
    float m0 = -1e30f, m1 = -1e30f, l0 = 0.f, l1 = 0.f;
    uint32_t qAh[4][4], qAl[4][4];

    for (int c = 0; c < 16; ++c) {
        const int kv0 = c * 128;
        const int s = c & 1;
        cp_wait<0>();
        __syncthreads();   // K(c) visible; prev iter's Vt/K reads done

        // stage V^T(c) from regs (packed pairs via prmt) + mask bias
#pragma unroll
        for (int w = 0; w < 8; ++w) {
            const uint32_t a0 = ((const uint32_t*)&vr_h[0])[w];
            const uint32_t a1 = ((const uint32_t*)&vr_h[1])[w];
            const uint32_t b0 = ((const uint32_t*)&vr_l[0])[w];
            const uint32_t b1 = ((const uint32_t*)&vr_l[1])[w];
            const int hd = vq * 16 + 2 * w;
            *(uint32_t*)(sm + AT_VH + ((hd)     * VPITCH + 2 * vj) * 2) = __byte_perm(a0, a1, 0x5410);
            *(uint32_t*)(sm + AT_VH + ((hd + 1) * VPITCH + 2 * vj) * 2) = __byte_perm(a0, a1, 0x7632);
            *(uint32_t*)(sm + AT_VL + ((hd)     * VPITCH + 2 * vj) * 2) = __byte_perm(b0, b1, 0x5410);
            *(uint32_t*)(sm + AT_VL + ((hd + 1) * VPITCH + 2 * vj) * 2) = __byte_perm(b0, b1, 0x7632);
        }
        if (tid < 128)
            ((float*)(sm + AT_BIAS))[tid] = (mb[kv0 + tid] == 0) ? -1e30f : 0.f;

        // prefetch V(c+1) into regs
        if (c + 1 < 16) {
#pragma unroll
            for (int rr = 0; rr < 2; ++rr) {
                const size_t g = ((size_t)(b * Tt + kv0 + 128 + 2 * vj + rr)) * Dd + h * HDh + vq * 16;
                vr_h[rr][0] = *(const uint4*)(vh + g);
                vr_h[rr][1] = *(const uint4*)(vh + g + 8);
                vr_l[rr][0] = *(const uint4*)(vl + g);
                vr_l[rr][1] = *(const uint4*)(vl + g + 8);
            }
        }

        if (c == 0) {   // Q A-frags, hoisted
#pragma unroll
            for (int kt = 0; kt < 4; ++kt) {
                const uint32_t o  = (uint32_t)(((wid * 16 + r) * QPITCH + kt * 16 + c2) * 2);
                const uint32_t o8 = o + 8 * QPITCH * 2;
                qAh[kt][0] = *(const uint32_t*)(sm + AT_QH + o);
                qAh[kt][1] = *(const uint32_t*)(sm + AT_QH + o8);
                qAh[kt][2] = *(const uint32_t*)(sm + AT_QH + o + 16);
                qAh[kt][3] = *(const uint32_t*)(sm + AT_QH + o8 + 16);
                qAl[kt][0] = *(const uint32_t*)(sm + AT_QL + o);
                qAl[kt][1] = *(const uint32_t*)(sm + AT_QL + o8);
                qAl[kt][2] = *(const uint32_t*)(sm + AT_QL + o + 16);
                qAl[kt][3] = *(const uint32_t*)(sm + AT_QL + o8 + 16);
            }
        }

        // prefetch K(c+1) -> stage s^1 (safe: all warps past sync above)
        if (c + 1 < 16) {
#pragma unroll
            for (int j = 0; j < 4; ++j) {
                const int i = tid + j * 256, row = i >> 3, seg = i & 7;
                const uint32_t so = (uint32_t)((row * QPITCH + seg * 8) * 2);
                const size_t g = gk + (size_t)(kv0 + 128 + row) * Dd + seg * 8;
                cp_async16(sb + AT_K0 + (s ^ 1) * 36864 + so, kh + g);
                cp_async16(sb + AT_K0 + (s ^ 1) * 36864 + 18432 + so, kl + g);
            }
        }
        cp_commit();
        __syncthreads();   // Vt(c), bias visible

        // ---- S = Q K^T (bf16x3)
        const uint8_t* Ksh = sm + AT_K0 + s * 36864;
        const uint8_t* Ksl = Ksh + 18432;
        float sacc[16][4];
#pragma unroll
        for (int nt = 0; nt < 16; ++nt)
#pragma unroll
            for (int q = 0; q < 4; ++q) sacc[nt][q] = 0.f;
#pragma unroll
        for (int kt = 0; kt < 4; ++kt) {
#pragma unroll
            for (int nt = 0; nt < 16; ++nt) {
                const uint32_t o = (uint32_t)(((nt * 8 + r) * QPITCH + kt * 16 + c2) * 2);
                uint32_t bh2[2], bl2[2];
                bh2[0] = *(const uint32_t*)(Ksh + o);
                bh2[1] = *(const uint32_t*)(Ksh + o + 16);
                bl2[0] = *(const uint32_t*)(Ksl + o);
                bl2[1] = *(const uint32_t*)(Ksl + o + 16);
                mma16816(sacc[nt], qAh[kt], bh2);
                mma16816(sacc[nt], qAl[kt], bh2);
                mma16816(sacc[nt], qAh[kt], bl2);
            }
        }

        // ---- mask bias + online softmax
        const float* bias = (const float*)(sm + AT_BIAS);
        float tmax0 = -1e30f, tmax1 = -1e30f;
#pragma unroll
        for (int nt = 0; nt < 16; ++nt) {
            const float2 bv = *(const float2*)(bias + nt * 8 + c2);
            sacc[nt][0] += bv.x; sacc[nt][1] += bv.y;
            sacc[nt][2] += bv.x; sacc[nt][3] += bv.y;
            tmax0 = fmaxf(tmax0, fmaxf(sacc[nt][0], sacc[nt][1]));
            tmax1 = fmaxf(tmax1, fmaxf(sacc[nt][2], sacc[nt][3]));
        }
        tmax0 = fmaxf(tmax0, __shfl_xor_sync(0xffffffffu, tmax0, 1));
        tmax0 = fmaxf(tmax0, __shfl_xor_sync(0xffffffffu, tmax0, 2));
        tmax1 = fmaxf(tmax1, __shfl_xor_sync(0xffffffffu, tmax1, 1));
        tmax1 = fmaxf(tmax1, __shfl_xor_sync(0xffffffffu, tmax1, 2));
        const float mn0 = fmaxf(m0, tmax0), mn1 = fmaxf(m1, tmax1);
        const float al0 = __expf(m0 - mn0), al1 = __expf(m1 - mn1);
        m0 = mn0; m1 = mn1;
        float rs0 = 0.f, rs1 = 0.f;
#pragma unroll
        for (int nt = 0; nt < 16; ++nt) {
            sacc[nt][0] = __expf(sacc[nt][0] - mn0);
            sacc[nt][1] = __expf(sacc[nt][1] - mn0);
            sacc[nt][2] = __expf(sacc[nt][2] - mn1);
            sacc[nt][3] = __expf(sacc[nt][3] - mn1);
            rs0 += sacc[nt][0] + sacc[nt][1];
            rs1 += sacc[nt][2] + sacc[nt][3];
        }
        rs0 += __shfl_xor_sync(0xffffffffu, rs0, 1);
        rs0 += __shfl_xor_sync(0xffffffffu, rs0, 2);
        rs1 += __shfl_xor_sync(0xffffffffu, rs1, 1);
        rs1 += __shfl_xor_sync(0xffffffffu, rs1, 2);
        l0 = l0 * al0 + rs0;
        l1 = l1 * al1 + rs1;
#pragma unroll
        for (int nt = 0; nt < 8; ++nt) {
            cacc[nt][0] *= al0; cacc[nt][1] *= al0;
            cacc[nt][2] *= al1; cacc[nt][3] *= al1;
        }

        // ---- PV: P frags from S accums (hi/lo split), V^T from smem
#pragma unroll
        for (int kt = 0; kt < 8; ++kt) {
            uint32_t aPh[4], aPl[4];
#pragma unroll
            for (int u = 0; u < 2; ++u) {
                const float p0 = sacc[2 * kt + u][0], p1 = sacc[2 * kt + u][1];
                const float p2 = sacc[2 * kt + u][2], p3 = sacc[2 * kt + u][3];
                const __nv_bfloat162 h01 = __floats2bfloat162_rn(p0, p1);
                const __nv_bfloat162 h23 = __floats2bfloat162_rn(p2, p3);
                const __nv_bfloat162 q01 = __floats2bfloat162_rn(
                    p0 - __bfloat162float(h01.x), p1 - __bfloat162float(h01.y));
                const __nv_bfloat162 q23 = __floats2bfloat162_rn(
                    p2 - __bfloat162float(h23.x), p3 - __bfloat162float(h23.y));
                aPh[2 * u + 0] = bf2_bits(h01);
                aPh[2 * u + 1] = bf2_bits(h23);
                aPl[2 * u + 0] = bf2_bits(q01);
                aPl[2 * u + 1] = bf2_bits(q23);
            }
#pragma unroll
            for (int nt = 0; nt < 8; ++nt) {
                const uint32_t o = (uint32_t)(((nt * 8 + r) * VPITCH + kt * 16 + c2) * 2);
                uint32_t bh2[2], bl2[2];
                bh2[0] = *(const uint32_t*)(sm + AT_VH + o);
                bh2[1] = *(const uint32_t*)(sm + AT_VH + o + 16);
                bl2[0] = *(const uint32_t*)(sm + AT_VL + o);
                bl2[1] = *(const uint32_t*)(sm + AT_VL + o + 16);
                mma16816(cacc[nt], aPh, bh2);
                mma16816(cacc[nt], aPl, bh2);
                mma16816(cacc[nt], aPh, bl2);
            }
        }
    }

    // ---- epilogue: normalize, split to bf16 hi/lo, write ctx
    const float inv0 = 1.0f / l0, inv1 = 1.0f / l1;
    const int row0 = q0 + wid * 16 + r;
    const size_t ob = ((size_t)(b * Tt) + row0) * Dd + h * HDh;
#pragma unroll
    for (int nt = 0; nt < 8; ++nt) {
        const int col = nt * 8 + c2;
        const float v0 = cacc[nt][0] * inv0, v1 = cacc[nt][1] * inv0;
        const float v2 = cacc[nt][2] * inv1, v3 = cacc[nt][3] * inv1;
        const __nv_bfloat162 h01 = __floats2bfloat162_rn(v0, v1);
        const __nv_bfloat162 h23 = __floats2bfloat162_rn(v2, v3);
        const __nv_bfloat162 q01 = __floats2bfloat162_rn(
            v0 - __bfloat162float(h01.x), v1 - __bfloat162float(h01.y));
        const __nv_bfloat162 q23 = __floats2bfloat162_rn(
            v2 - __bfloat162float(h23.x), v3 - __bfloat162float(h23.y));
        *(uint32_t*)(och + ob + col)            = bf2_bits(h01);
        *(uint32_t*)(ocl + ob + col)            = bf2_bits(q01);
        *(uint32_t*)(och + ob + 8 * Dd + col)   = bf2_bits(h23);
        *(uint32_t*)(ocl + ob + 8 * Dd + col)   = bf2_bits(q23);
    }
}

// ---------------------------------------------------------------------------
extern "C" void kernel_launch(void* const* d_in, const int* in_sizes, int n_in,
                              void* d_out, int out_size)
{
    const float* x  = (const float*)d_in[0];
    const float* Wq = (const float*)d_in[1];
    const float* bq = (const float*)d_in[2];
    const float* Wk = (const float*)d_in[3];
    const float* bk = (const float*)d_in[4];
    const float* Wv = (const float*)d_in[5];
    const float* bv = (const float*)d_in[6];
    const float* Wo = (const float*)d_in[7];
    const float* bo = (const float*)d_in[8];
    const int* mask = (const int*)d_in[9];
    float* out = (float*)d_out;

    __nv_bfloat16 *xh, *xl, *qhp, *qlp, *khp, *klp, *vhp, *vlp, *chp, *clp, *wh, *wl;
    cudaGetSymbolAddress((void**)&xh, g_xh);
    cudaGetSymbolAddress((void**)&xl, g_xl);
    cudaGetSymbolAddress((void**)&qhp, g_qh);
    cudaGetSymbolAddress((void**)&qlp, g_ql);
    cudaGetSymbolAddress((void**)&khp, g_kh);
    cudaGetSymbolAddress((void**)&klp, g_kl);
    cudaGetSymbolAddress((void**)&vhp, g_vh);
    cudaGetSymbolAddress((void**)&vlp, g_vl);
    cudaGetSymbolAddress((void**)&chp, g_ch);
    cudaGetSymbolAddress((void**)&clp, g_cl);
    cudaGetSymbolAddress((void**)&wh, g_wh);
    cudaGetSymbolAddress((void**)&wl, g_wl);

    const size_t WSZ = (size_t)Dd * Dd;
    const int n4x = (Mm * Dd) / 4;
    const int n4w = (int)(WSZ / 4);

    split_kernel<<<(n4x + 255) / 256, 256>>>(x, xh, xl, n4x);
    split_kernel<<<(n4w + 255) / 256, 256>>>(Wq, wh + 0 * WSZ, wl + 0 * WSZ, n4w);
    split_kernel<<<(n4w + 255) / 256, 256>>>(Wk, wh + 1 * WSZ, wl + 1 * WSZ, n4w);
    split_kernel<<<(n4w + 255) / 256, 256>>>(Wv, wh + 2 * WSZ, wl + 2 * WSZ, n4w);
    split_kernel<<<(n4w + 255) / 256, 256>>>(Wo, wh + 3 * WSZ, wl + 3 * WSZ, n4w);

    cudaFuncSetAttribute(gemm_bf16x3_mma,
                         cudaFuncAttributeMaxDynamicSharedMemorySize, GSMEM_B);
    dim3 ggrid(Dd / 128, Mm / 128);
    // Q/K/V projections -> bf16 hi/lo (Q pre-scaled by 1/sqrt(HD)=1/8)
    gemm_bf16x3_mma<<<ggrid, 256, GSMEM_B>>>(xh, xl, wh + 0 * WSZ, wl + 0 * WSZ, bq,
                                             nullptr, qhp, qlp, 0.125f);
    gemm_bf16x3_mma<<<ggrid, 256, GSMEM_B>>>(xh, xl, wh + 1 * WSZ, wl + 1 * WSZ, bk,
                                             nullptr, khp, klp, 1.0f);
    gemm_bf16x3_mma<<<ggrid, 256, GSMEM_B>>>(xh, xl, wh + 2 * WSZ, wl + 2 * WSZ, bv,
                                             nullptr, vhp, vlp, 1.0f);

    // Fused attention on tensor cores
    cudaFuncSetAttribute(attn_mma_kernel,
                         cudaFuncAttributeMaxDynamicSharedMemorySize, AT_SMEM);
    attn_mma_kernel<<<dim3(Tt / 128, Hh, Bb), 256, AT_SMEM>>>(
        qhp, qlp, khp, klp, vhp, vlp, mask, chp, clp);

    // Output projection -> fp32
    gemm_bf16x3_mma<<<ggrid, 256, GSMEM_B>>>(chp, clp, wh + 3 * WSZ, wl + 3 * WSZ, bo,
                                             out, nullptr, nullptr, 1.0f);
}

// round 8
// speedup vs baseline: 2.9977x; 1.1296x over previous
#include <cuda_runtime.h>
#include <cuda_fp16.h>
#include <cstdint>

// Problem constants
#define Bb  4
#define Tt  2048
#define Dd  1024
#define Hh  16
#define HDh 64
#define Mm  (Bb * Tt)   // 8192 rows

// ---------------------------------------------------------------------------
// Scratch (device globals: allocation-free rule). All fp16 now.
// ---------------------------------------------------------------------------
__device__ __half g_xh[(size_t)Mm * Dd];
__device__ __half g_xl[(size_t)Mm * Dd];
__device__ __half g_qh[(size_t)Mm * Dd];
__device__ __half g_ql[(size_t)Mm * Dd];
__device__ __half g_kh[(size_t)Mm * Dd];
__device__ __half g_kl[(size_t)Mm * Dd];
__device__ __half g_vh[(size_t)Mm * Dd];          // V single-rounded
__device__ __half g_ch[(size_t)Mm * Dd];
__device__ __half g_cl[(size_t)Mm * Dd];
__device__ __half g_wh[4 * (size_t)Dd * Dd];
__device__ __half g_wl[4 * (size_t)Dd * Dd];

// ---------------------------------------------------------------------------
// sm_100-base helpers: cp.async + mma.sync fp16 (tcgen05 unavailable here)
// ---------------------------------------------------------------------------
__device__ __forceinline__ uint32_t smem_to_u32(const void* p) {
    uint32_t a;
    asm("{ .reg .u64 t; cvta.to.shared.u64 t, %1; cvt.u32.u64 %0, t; }"
        : "=r"(a) : "l"(p));
    return a;
}
__device__ __forceinline__ void cp_async16(uint32_t smem_addr, const void* gptr) {
    asm volatile("cp.async.cg.shared.global [%0], [%1], 16;"
                 :: "r"(smem_addr), "l"(gptr));
}
__device__ __forceinline__ void cp_commit() {
    asm volatile("cp.async.commit_group;");
}
template <int N>
__device__ __forceinline__ void cp_wait() {
    asm volatile("cp.async.wait_group %0;" :: "n"(N));
}
// D += A*B, m16n8k16 fp16 in / fp32 accum; A row-major, B col-major
__device__ __forceinline__ void mma16816(float* d, const uint32_t* a, const uint32_t* b) {
    asm volatile(
        "mma.sync.aligned.m16n8k16.row.col.f32.f16.f16.f32 "
        "{%0,%1,%2,%3}, {%4,%5,%6,%7}, {%8,%9}, {%0,%1,%2,%3};"
        : "+f"(d[0]), "+f"(d[1]), "+f"(d[2]), "+f"(d[3])
        : "r"(a[0]), "r"(a[1]), "r"(a[2]), "r"(a[3]), "r"(b[0]), "r"(b[1]));
}
__device__ __forceinline__ uint32_t h2_bits(__half2 v) {
    union { __half2 h; uint32_t u; } cv; cv.h = v; return cv.u;
}
// hi/lo split of one float into two fp16
__device__ __forceinline__ void split_h(float v, __half& hi, __half& lo) {
    hi = __float2half_rn(v);
    lo = __float2half_rn(v - __half2float(hi));
}

// ---------------------------------------------------------------------------
// Split kernels (fp32 -> fp16 hi/lo)
// ---------------------------------------------------------------------------
__global__ __launch_bounds__(256) void split_x_kernel(
    const float* __restrict__ src,
    __half* __restrict__ hi, __half* __restrict__ lo, int n4)
{
    int i = blockIdx.x * blockDim.x + threadIdx.x;
    if (i >= n4) return;
    float4 v = ((const float4*)src)[i];
    __half h0, h1, h2, h3, l0, l1, l2, l3;
    split_h(v.x, h0, l0); split_h(v.y, h1, l1);
    split_h(v.z, h2, l2); split_h(v.w, h3, l3);
    union { __half b[4]; uint2 u; } ph, pl;
    ph.b[0] = h0; ph.b[1] = h1; ph.b[2] = h2; ph.b[3] = h3;
    pl.b[0] = l0; pl.b[1] = l1; pl.b[2] = l2; pl.b[3] = l3;
    ((uint2*)hi)[i] = ph.u;
    ((uint2*)lo)[i] = pl.u;
}

// all 4 weight matrices in one launch; dest arrays are contiguous per-matrix
__global__ __launch_bounds__(256) void split_w4_kernel(
    const float* __restrict__ w0, const float* __restrict__ w1,
    const float* __restrict__ w2, const float* __restrict__ w3,
    __half* __restrict__ hi, __half* __restrict__ lo, int n4_each)
{
    int i = blockIdx.x * blockDim.x + threadIdx.x;
    if (i >= 4 * n4_each) return;
    const int m = i / n4_each, j = i - m * n4_each;
    const float* src = (m == 0) ? w0 : (m == 1) ? w1 : (m == 2) ? w2 : w3;
    float4 v = ((const float4*)src)[j];
    __half h0, h1, h2, h3, l0, l1, l2, l3;
    split_h(v.x, h0, l0); split_h(v.y, h1, l1);
    split_h(v.z, h2, l2); split_h(v.w, h3, l3);
    union { __half b[4]; uint2 u; } ph, pl;
    ph.b[0] = h0; ph.b[1] = h1; ph.b[2] = h2; ph.b[3] = h3;
    pl.b[0] = l0; pl.b[1] = l1; pl.b[2] = l2; pl.b[3] = l3;
    ((uint2*)hi)[i] = ph.u;
    ((uint2*)lo)[i] = pl.u;
}

// ---------------------------------------------------------------------------
// fp16 split mma.sync GEMM:  C = A @ W^T + bias.
//   3-pass (use_bl=1): Ah*Bh + Al*Bh + Ah*Bl  (error ~2^-22)
//   2-pass (use_bl=0): Ah*Bh + Al*Bh          (error = B rounding ~2^-12)
// Epilogue: Cf32 -> fp32; else Oh/Ol -> fp16 hi/lo (scaled); Ol==null -> single.
// ---------------------------------------------------------------------------
#define GPITCH 40
#define GTILE_B (128 * GPITCH * 2)
#define GSTAGE_B (4 * GTILE_B)
#define GSMEM_B (2 * GSTAGE_B)

__global__ __launch_bounds__(256, 1) void gemm_fp16s_mma(
    const __half* __restrict__ Ah, const __half* __restrict__ Al,
    const __half* __restrict__ Bh, const __half* __restrict__ Bl,
    const float* __restrict__ bias, float* __restrict__ Cf32,
    __half* __restrict__ Oh, __half* __restrict__ Ol, float scale, int use_bl)
{
    extern __shared__ __align__(128) uint8_t smem[];
    const int tid  = threadIdx.x;
    const int wid  = tid >> 5;
    const int lane = tid & 31;
    const int wm   = wid & 3;
    const int wn   = wid >> 2;
    const int gm0  = blockIdx.y * 128;
    const int gn0  = blockIdx.x * 128;
    const uint32_t sbase = smem_to_u32(smem);

    const __half* srcs[4] = { Ah, Al, Bh, Bl };

    auto issue = [&](int s, int c) {
        const int k0 = c * 32;
#pragma unroll
        for (int t = 0; t < 4; ++t) {
            if (t == 3 && !use_bl) continue;
            const __half* src = srcs[t];
            const int rbase = (t < 2) ? gm0 : gn0;
#pragma unroll
            for (int j = 0; j < 2; ++j) {
                const int i = tid + j * 256;
                const int row = i >> 2, chunk = i & 3;
                const uint32_t sa = sbase + s * GSTAGE_B + t * GTILE_B
                                  + (uint32_t)(row * GPITCH + chunk * 8) * 2;
                const void* g = src + (size_t)(rbase + row) * Dd + k0 + chunk * 8;
                cp_async16(sa, g);
            }
        }
        cp_commit();
    };

    float acc[2][8][4];
#pragma unroll
    for (int mt = 0; mt < 2; ++mt)
#pragma unroll
        for (int nt = 0; nt < 8; ++nt)
#pragma unroll
            for (int q = 0; q < 4; ++q) acc[mt][nt][q] = 0.f;

    const int r   = lane >> 2;
    const int cp2 = (lane & 3) * 2;

    issue(0, 0);

    for (int c = 0; c < 32; ++c) {
        const int s = c & 1;
        if (c + 1 < 32) { issue((c + 1) & 1, c + 1); cp_wait<1>(); }
        else            { cp_wait<0>(); }
        __syncthreads();

        const uint8_t* stg = smem + s * GSTAGE_B;
        const uint8_t* pAh = stg;
        const uint8_t* pAl = stg + GTILE_B;
        const uint8_t* pBh = stg + 2 * GTILE_B;
        const uint8_t* pBl = stg + 3 * GTILE_B;

#pragma unroll
        for (int ks = 0; ks < 2; ++ks) {
            const int kk = ks * 16;
            uint32_t ah[2][4], al[2][4];
#pragma unroll
            for (int mt = 0; mt < 2; ++mt) {
                const int row = wm * 32 + mt * 16 + r;
                const uint32_t o00 = (uint32_t)(row * GPITCH + kk + cp2) * 2;
                const uint32_t o10 = (uint32_t)((row + 8) * GPITCH + kk + cp2) * 2;
                ah[mt][0] = *(const uint32_t*)(pAh + o00);
                ah[mt][1] = *(const uint32_t*)(pAh + o10);
                ah[mt][2] = *(const uint32_t*)(pAh + o00 + 16);
                ah[mt][3] = *(const uint32_t*)(pAh + o10 + 16);
                al[mt][0] = *(const uint32_t*)(pAl + o00);
                al[mt][1] = *(const uint32_t*)(pAl + o10);
                al[mt][2] = *(const uint32_t*)(pAl + o00 + 16);
                al[mt][3] = *(const uint32_t*)(pAl + o10 + 16);
            }
#pragma unroll
            for (int nt = 0; nt < 8; ++nt) {
                const int n = wn * 64 + nt * 8 + r;
                const uint32_t ob = (uint32_t)(n * GPITCH + kk + cp2) * 2;
                uint32_t bh[2];
                bh[0] = *(const uint32_t*)(pBh + ob);
                bh[1] = *(const uint32_t*)(pBh + ob + 16);
                mma16816(acc[0][nt], ah[0], bh);
                mma16816(acc[1][nt], ah[1], bh);
                mma16816(acc[0][nt], al[0], bh);
                mma16816(acc[1][nt], al[1], bh);
                if (use_bl) {
                    uint32_t bl[2];
                    bl[0] = *(const uint32_t*)(pBl + ob);
                    bl[1] = *(const uint32_t*)(pBl + ob + 16);
                    mma16816(acc[0][nt], ah[0], bl);
                    mma16816(acc[1][nt], ah[1], bl);
                }
            }
        }
        __syncthreads();
    }

    // Epilogue
#pragma unroll
    for (int mt = 0; mt < 2; ++mt) {
        const int row0 = gm0 + wm * 32 + mt * 16 + r;
#pragma unroll
        for (int nt = 0; nt < 8; ++nt) {
            const int col = gn0 + wn * 64 + nt * 8 + cp2;
            const float b0 = bias[col], b1 = bias[col + 1];
            float v0 = acc[mt][nt][0] + b0, v1 = acc[mt][nt][1] + b1;
            float v2 = acc[mt][nt][2] + b0, v3 = acc[mt][nt][3] + b1;
            if (Oh) {
                v0 *= scale; v1 *= scale; v2 *= scale; v3 *= scale;
                __half2 h01 = __floats2half2_rn(v0, v1);
                __half2 h23 = __floats2half2_rn(v2, v3);
                *(uint32_t*)(Oh + (size_t)row0 * Dd + col)       = h2_bits(h01);
                *(uint32_t*)(Oh + (size_t)(row0 + 8) * Dd + col) = h2_bits(h23);
                if (Ol) {
                    __half2 l01 = __floats2half2_rn(
                        v0 - __half2float(__low2half(h01)), v1 - __half2float(__high2half(h01)));
                    __half2 l23 = __floats2half2_rn(
                        v2 - __half2float(__low2half(h23)), v3 - __half2float(__high2half(h23)));
                    *(uint32_t*)(Ol + (size_t)row0 * Dd + col)       = h2_bits(l01);
                    *(uint32_t*)(Ol + (size_t)(row0 + 8) * Dd + col) = h2_bits(l23);
                }
            } else {
                float2 w0, w1;
                w0.x = v0; w0.y = v1; w1.x = v2; w1.y = v3;
                *(float2*)(Cf32 + (size_t)row0 * Dd + col)       = w0;
                *(float2*)(Cf32 + (size_t)(row0 + 8) * Dd + col) = w1;
            }
        }
    }
}

// ---------------------------------------------------------------------------
// Flash attention, fp16 mma.sync.
// S = (Qh+Ql)(Kh + lo-corr)  3-pass;  PV = (Ph+Pl)*Vh  2-pass, V single fp16.
// Grid (T/128, H, B), 256 threads = 8 warps; warp w owns q rows [16w,16w+16).
// Q pre-scaled by 1/8 in the Q projection epilogue.
// ---------------------------------------------------------------------------
#define QPITCH 72     // fp16; pitch%64==8 -> conflict-free frag loads
#define VPITCH 136
#define AT_QH   0
#define AT_QL   18432
#define AT_K0   36864          // + s*36864; hi at +0, lo at +18432
#define AT_VH   110592
#define AT_BIAS 128000
#define AT_SMEM 128512

__global__ __launch_bounds__(256, 1) void attn_mma_kernel(
    const __half* __restrict__ qh, const __half* __restrict__ ql,
    const __half* __restrict__ kh, const __half* __restrict__ kl,
    const __half* __restrict__ vh,
    const int* __restrict__ mask,
    __half* __restrict__ och, __half* __restrict__ ocl)
{
    extern __shared__ __align__(128) uint8_t sm[];
    const uint32_t sb = smem_to_u32(sm);
    const int tid = threadIdx.x, wid = tid >> 5, lane = tid & 31;
    const int r = lane >> 2, c2 = (lane & 3) * 2;
    const int b = blockIdx.z, h = blockIdx.y;
    const int q0 = blockIdx.x * 128;
    const size_t gq = ((size_t)(b * Tt + q0)) * Dd + h * HDh;
    const size_t gk = ((size_t)(b * Tt)) * Dd + h * HDh;
    const int* mb = mask + b * Tt;

    // ---- preamble: stage Q (hi/lo) and K tile 0 via cp.async
#pragma unroll
    for (int j = 0; j < 4; ++j) {
        const int i = tid + j * 256, row = i >> 3, seg = i & 7;
        const uint32_t so = (uint32_t)((row * QPITCH + seg * 8) * 2);
        const size_t go = (size_t)row * Dd + seg * 8;
        cp_async16(sb + AT_QH + so, qh + gq + go);
        cp_async16(sb + AT_QL + so, ql + gq + go);
        cp_async16(sb + AT_K0 + so, kh + gk + go);
        cp_async16(sb + AT_K0 + 18432 + so, kl + gk + go);
    }
    cp_commit();

    // ---- V register prefetch: thread -> kv rows 2vj,2vj+1, hd quarter vq*16
    const int vj = tid >> 2;
    const int vq = tid & 3;
    uint4 vr_h[2][2];
#pragma unroll
    for (int rr = 0; rr < 2; ++rr) {
        const size_t g = ((size_t)(b * Tt + 2 * vj + rr)) * Dd + h * HDh + vq * 16;
        vr_h[rr][0] = *(const uint4*)(vh + g);
        vr_h[rr][1] = *(const uint4*)(vh + g + 8);
    }

    float cacc[8][4];
#pragma unroll
    for (int nt = 0; nt < 8; ++nt)
#pragma unroll
        for (int q = 0; q < 4; ++q) cacc[nt][q] = 0.f;
    float m0 = -1e30f, m1 = -1e30f, l0 = 0.f, l1 = 0.f;
    uint32_t qAh[4][4], qAl[4][4];

    for (int c = 0; c < 16; ++c) {
        const int kv0 = c * 128;
        const int s = c & 1;
        cp_wait<0>();
        __syncthreads();   // K(c) visible; prev iter's Vt/K reads done

        // stage V^T(c) from regs (packed pairs via prmt) + mask bias
#pragma unroll
        for (int w = 0; w < 8; ++w) {
            const uint32_t a0 = ((const uint32_t*)&vr_h[0])[w];
            const uint32_t a1 = ((const uint32_t*)&vr_h[1])[w];
            const int hd = vq * 16 + 2 * w;
            *(uint32_t*)(sm + AT_VH + ((hd)     * VPITCH + 2 * vj) * 2) = __byte_perm(a0, a1, 0x5410);
            *(uint32_t*)(sm + AT_VH + ((hd + 1) * VPITCH + 2 * vj) * 2) = __byte_perm(a0, a1, 0x7632);
        }
        if (tid < 128)
            ((float*)(sm + AT_BIAS))[tid] = (mb[kv0 + tid] == 0) ? -1e30f : 0.f;

        // prefetch V(c+1) into regs
        if (c + 1 < 16) {
#pragma unroll
            for (int rr = 0; rr < 2; ++rr) {
                const size_t g = ((size_t)(b * Tt + kv0 + 128 + 2 * vj + rr)) * Dd + h * HDh + vq * 16;
                vr_h[rr][0] = *(const uint4*)(vh + g);
                vr_h[rr][1] = *(const uint4*)(vh + g + 8);
            }
        }

        if (c == 0) {   // Q A-frags, hoisted
#pragma unroll
            for (int kt = 0; kt < 4; ++kt) {
                const uint32_t o  = (uint32_t)(((wid * 16 + r) * QPITCH + kt * 16 + c2) * 2);
                const uint32_t o8 = o + 8 * QPITCH * 2;
                qAh[kt][0] = *(const uint32_t*)(sm + AT_QH + o);
                qAh[kt][1] = *(const uint32_t*)(sm + AT_QH + o8);
                qAh[kt][2] = *(const uint32_t*)(sm + AT_QH + o + 16);
                qAh[kt][3] = *(const uint32_t*)(sm + AT_QH + o8 + 16);
                qAl[kt][0] = *(const uint32_t*)(sm + AT_QL + o);
                qAl[kt][1] = *(const uint32_t*)(sm + AT_QL + o8);
                qAl[kt][2] = *(const uint32_t*)(sm + AT_QL + o + 16);
                qAl[kt][3] = *(const uint32_t*)(sm + AT_QL + o8 + 16);
            }
        }

        // prefetch K(c+1) -> stage s^1 (safe: all warps past sync above)
        if (c + 1 < 16) {
#pragma unroll
            for (int j = 0; j < 4; ++j) {
                const int i = tid + j * 256, row = i >> 3, seg = i & 7;
                const uint32_t so = (uint32_t)((row * QPITCH + seg * 8) * 2);
                const size_t g = gk + (size_t)(kv0 + 128 + row) * Dd + seg * 8;
                cp_async16(sb + AT_K0 + (s ^ 1) * 36864 + so, kh + g);
                cp_async16(sb + AT_K0 + (s ^ 1) * 36864 + 18432 + so, kl + g);
            }
        }
        cp_commit();
        __syncthreads();   // Vt(c), bias visible

        // ---- S = Q K^T (fp16, 3-pass)
        const uint8_t* Ksh = sm + AT_K0 + s * 36864;
        const uint8_t* Ksl = Ksh + 18432;
        float sacc[16][4];
#pragma unroll
        for (int nt = 0; nt < 16; ++nt)
#pragma unroll
            for (int q = 0; q < 4; ++q) sacc[nt][q] = 0.f;
#pragma unroll
        for (int kt = 0; kt < 4; ++kt) {
#pragma unroll
            for (int nt = 0; nt < 16; ++nt) {
                const uint32_t o = (uint32_t)(((nt * 8 + r) * QPITCH + kt * 16 + c2) * 2);
                uint32_t bh2[2], bl2[2];
                bh2[0] = *(const uint32_t*)(Ksh + o);
                bh2[1] = *(const uint32_t*)(Ksh + o + 16);
                bl2[0] = *(const uint32_t*)(Ksl + o);
                bl2[1] = *(const uint32_t*)(Ksl + o + 16);
                mma16816(sacc[nt], qAh[kt], bh2);
                mma16816(sacc[nt], qAl[kt], bh2);
                mma16816(sacc[nt], qAh[kt], bl2);
            }
        }

        // ---- mask bias + online softmax
        const float* bias = (const float*)(sm + AT_BIAS);
        float tmax0 = -1e30f, tmax1 = -1e30f;
#pragma unroll
        for (int nt = 0; nt < 16; ++nt) {
            const float2 bv = *(const float2*)(bias + nt * 8 + c2);
            sacc[nt][0] += bv.x; sacc[nt][1] += bv.y;
            sacc[nt][2] += bv.x; sacc[nt][3] += bv.y;
            tmax0 = fmaxf(tmax0, fmaxf(sacc[nt][0], sacc[nt][1]));
            tmax1 = fmaxf(tmax1, fmaxf(sacc[nt][2], sacc[nt][3]));
        }
        tmax0 = fmaxf(tmax0, __shfl_xor_sync(0xffffffffu, tmax0, 1));
        tmax0 = fmaxf(tmax0, __shfl_xor_sync(0xffffffffu, tmax0, 2));
        tmax1 = fmaxf(tmax1, __shfl_xor_sync(0xffffffffu, tmax1, 1));
        tmax1 = fmaxf(tmax1, __shfl_xor_sync(0xffffffffu, tmax1, 2));
        const float mn0 = fmaxf(m0, tmax0), mn1 = fmaxf(m1, tmax1);
        const float al0 = __expf(m0 - mn0), al1 = __expf(m1 - mn1);
        m0 = mn0; m1 = mn1;
        float rs0 = 0.f, rs1 = 0.f;
#pragma unroll
        for (int nt = 0; nt < 16; ++nt) {
            sacc[nt][0] = __expf(sacc[nt][0] - mn0);
            sacc[nt][1] = __expf(sacc[nt][1] - mn0);
            sacc[nt][2] = __expf(sacc[nt][2] - mn1);
            sacc[nt][3] = __expf(sacc[nt][3] - mn1);
            rs0 += sacc[nt][0] + sacc[nt][1];
            rs1 += sacc[nt][2] + sacc[nt][3];
        }
        rs0 += __shfl_xor_sync(0xffffffffu, rs0, 1);
        rs0 += __shfl_xor_sync(0xffffffffu, rs0, 2);
        rs1 += __shfl_xor_sync(0xffffffffu, rs1, 1);
        rs1 += __shfl_xor_sync(0xffffffffu, rs1, 2);
        l0 = l0 * al0 + rs0;
        l1 = l1 * al1 + rs1;
#pragma unroll
        for (int nt = 0; nt < 8; ++nt) {
            cacc[nt][0] *= al0; cacc[nt][1] *= al0;
            cacc[nt][2] *= al1; cacc[nt][3] *= al1;
        }

        // ---- PV: P frags (fp16 hi/lo) x V^T hi (2-pass)
#pragma unroll
        for (int kt = 0; kt < 8; ++kt) {
            uint32_t aPh[4], aPl[4];
#pragma unroll
            for (int u = 0; u < 2; ++u) {
                const float p0 = sacc[2 * kt + u][0], p1 = sacc[2 * kt + u][1];
                const float p2 = sacc[2 * kt + u][2], p3 = sacc[2 * kt + u][3];
                const __half2 h01 = __floats2half2_rn(p0, p1);
                const __half2 h23 = __floats2half2_rn(p2, p3);
                const __half2 q01 = __floats2half2_rn(
                    p0 - __half2float(__low2half(h01)), p1 - __half2float(__high2half(h01)));
                const __half2 q23 = __floats2half2_rn(
                    p2 - __half2float(__low2half(h23)), p3 - __half2float(__high2half(h23)));
                aPh[2 * u + 0] = h2_bits(h01);
                aPh[2 * u + 1] = h2_bits(h23);
                aPl[2 * u + 0] = h2_bits(q01);
                aPl[2 * u + 1] = h2_bits(q23);
            }
#pragma unroll
            for (int nt = 0; nt < 8; ++nt) {
                const uint32_t o = (uint32_t)(((nt * 8 + r) * VPITCH + kt * 16 + c2) * 2);
                uint32_t bh2[2];
                bh2[0] = *(const uint32_t*)(sm + AT_VH + o);
                bh2[1] = *(const uint32_t*)(sm + AT_VH + o + 16);
                mma16816(cacc[nt], aPh, bh2);
                mma16816(cacc[nt], aPl, bh2);
            }
        }
    }

    // ---- epilogue: normalize, split to fp16 hi/lo, write ctx
    const float inv0 = 1.0f / l0, inv1 = 1.0f / l1;
    const int row0 = q0 + wid * 16 + r;
    const size_t ob = ((size_t)(b * Tt) + row0) * Dd + h * HDh;
#pragma unroll
    for (int nt = 0; nt < 8; ++nt) {
        const int col = nt * 8 + c2;
        const float v0 = cacc[nt][0] * inv0, v1 = cacc[nt][1] * inv0;
        const float v2 = cacc[nt][2] * inv1, v3 = cacc[nt][3] * inv1;
        const __half2 h01 = __floats2half2_rn(v0, v1);
        const __half2 h23 = __floats2half2_rn(v2, v3);
        const __half2 q01 = __floats2half2_rn(
            v0 - __half2float(__low2half(h01)), v1 - __half2float(__high2half(h01)));
        const __half2 q23 = __floats2half2_rn(
            v2 - __half2float(__low2half(h23)), v3 - __half2float(__high2half(h23)));
        *(uint32_t*)(och + ob + col)            = h2_bits(h01);
        *(uint32_t*)(ocl + ob + col)            = h2_bits(q01);
        *(uint32_t*)(och + ob + 8 * Dd + col)   = h2_bits(h23);
        *(uint32_t*)(ocl + ob + 8 * Dd + col)   = h2_bits(q23);
    }
}

// ---------------------------------------------------------------------------
extern "C" void kernel_launch(void* const* d_in, const int* in_sizes, int n_in,
                              void* d_out, int out_size)
{
    const float* x  = (const float*)d_in[0];
    const float* Wq = (const float*)d_in[1];
    const float* bq = (const float*)d_in[2];
    const float* Wk = (const float*)d_in[3];
    const float* bk = (const float*)d_in[4];
    const float* Wv = (const float*)d_in[5];
    const float* bv = (const float*)d_in[6];
    const float* Wo = (const float*)d_in[7];
    const float* bo = (const float*)d_in[8];
    const int* mask = (const int*)d_in[9];
    float* out = (float*)d_out;

    __half *xh, *xl, *qhp, *qlp, *khp, *klp, *vhp, *chp, *clp, *wh, *wl;
    cudaGetSymbolAddress((void**)&xh, g_xh);
    cudaGetSymbolAddress((void**)&xl, g_xl);
    cudaGetSymbolAddress((void**)&qhp, g_qh);
    cudaGetSymbolAddress((void**)&qlp, g_ql);
    cudaGetSymbolAddress((void**)&khp, g_kh);
    cudaGetSymbolAddress((void**)&klp, g_kl);
    cudaGetSymbolAddress((void**)&vhp, g_vh);
    cudaGetSymbolAddress((void**)&chp, g_ch);
    cudaGetSymbolAddress((void**)&clp, g_cl);
    cudaGetSymbolAddress((void**)&wh, g_wh);
    cudaGetSymbolAddress((void**)&wl, g_wl);

    const size_t WSZ = (size_t)Dd * Dd;
    const int n4x = (Mm * Dd) / 4;
    const int n4w = (int)(WSZ / 4);

    // launch 0: split x; launch 1: split all weights
    split_x_kernel<<<(n4x + 255) / 256, 256>>>(x, xh, xl, n4x);
    split_w4_kernel<<<(4 * n4w + 255) / 256, 256>>>(Wq, Wk, Wv, Wo, wh, wl, n4w);

    cudaFuncSetAttribute(gemm_fp16s_mma,
                         cudaFuncAttributeMaxDynamicSharedMemorySize, GSMEM_B);
    dim3 ggrid(Dd / 128, Mm / 128);
    // launches 2,3: Q,K projections 3-pass -> fp16 hi/lo (Q pre-scaled 1/8)
    gemm_fp16s_mma<<<ggrid, 256, GSMEM_B>>>(xh, xl, wh + 0 * WSZ, wl + 0 * WSZ, bq,
                                            nullptr, qhp, qlp, 0.125f, 1);
    gemm_fp16s_mma<<<ggrid, 256, GSMEM_B>>>(xh, xl, wh + 1 * WSZ, wl + 1 * WSZ, bk,
                                            nullptr, khp, klp, 1.0f, 1);
    // launch 4: V projection 2-pass -> single fp16
    gemm_fp16s_mma<<<ggrid, 256, GSMEM_B>>>(xh, xl, wh + 2 * WSZ, wl + 2 * WSZ, bv,
                                            nullptr, vhp, nullptr, 1.0f, 0);

    // launch 5: fused attention (ncu -s 5 captures this one)
    cudaFuncSetAttribute(attn_mma_kernel,
                         cudaFuncAttributeMaxDynamicSharedMemorySize, AT_SMEM);
    attn_mma_kernel<<<dim3(Tt / 128, Hh, Bb), 256, AT_SMEM>>>(
        qhp, qlp, khp, klp, vhp, mask, chp, clp);

    // launch 6: output projection 2-pass -> fp32
    gemm_fp16s_mma<<<ggrid, 256, GSMEM_B>>>(chp, clp, wh + 3 * WSZ, wl + 3 * WSZ, bo,
                                            out, nullptr, nullptr, 1.0f, 0);
}

// round 9
// speedup vs baseline: 3.5064x; 1.1697x over previous
#include <cuda_runtime.h>
#include <cuda_fp16.h>
#include <cstdint>

// Problem constants
#define Bb  4
#define Tt  2048
#define Dd  1024
#define Hh  16
#define HDh 64
#define Mm  (Bb * Tt)   // 8192 rows

// ---------------------------------------------------------------------------
// Scratch (device globals: allocation-free rule). All fp16.
// ---------------------------------------------------------------------------
__device__ __half g_xh[(size_t)Mm * Dd];
__device__ __half g_xl[(size_t)Mm * Dd];
__device__ __half g_qh[(size_t)Mm * Dd];
__device__ __half g_ql[(size_t)Mm * Dd];
__device__ __half g_kh[(size_t)Mm * Dd];          // K single-rounded
__device__ __half g_vh[(size_t)Mm * Dd];          // V single-rounded
__device__ __half g_ch[(size_t)Mm * Dd];
__device__ __half g_cl[(size_t)Mm * Dd];
__device__ __half g_wh[4 * (size_t)Dd * Dd];
__device__ __half g_wl[4 * (size_t)Dd * Dd];

// ---------------------------------------------------------------------------
// sm_100-base helpers: cp.async + mma.sync fp16 (tcgen05 unavailable here)
// ---------------------------------------------------------------------------
__device__ __forceinline__ uint32_t smem_to_u32(const void* p) {
    uint32_t a;
    asm("{ .reg .u64 t; cvta.to.shared.u64 t, %1; cvt.u32.u64 %0, t; }"
        : "=r"(a) : "l"(p));
    return a;
}
__device__ __forceinline__ void cp_async16(uint32_t smem_addr, const void* gptr) {
    asm volatile("cp.async.cg.shared.global [%0], [%1], 16;"
                 :: "r"(smem_addr), "l"(gptr));
}
__device__ __forceinline__ void cp_commit() {
    asm volatile("cp.async.commit_group;");
}
template <int N>
__device__ __forceinline__ void cp_wait() {
    asm volatile("cp.async.wait_group %0;" :: "n"(N));
}
// D += A*B, m16n8k16 fp16 in / fp32 accum; A row-major, B col-major
__device__ __forceinline__ void mma16816(float* d, const uint32_t* a, const uint32_t* b) {
    asm volatile(
        "mma.sync.aligned.m16n8k16.row.col.f32.f16.f16.f32 "
        "{%0,%1,%2,%3}, {%4,%5,%6,%7}, {%8,%9}, {%0,%1,%2,%3};"
        : "+f"(d[0]), "+f"(d[1]), "+f"(d[2]), "+f"(d[3])
        : "r"(a[0]), "r"(a[1]), "r"(a[2]), "r"(a[3]), "r"(b[0]), "r"(b[1]));
}
__device__ __forceinline__ uint32_t h2_bits(__half2 v) {
    union { __half2 h; uint32_t u; } cv; cv.h = v; return cv.u;
}
// hi/lo split of one float into two fp16
__device__ __forceinline__ void split_h(float v, __half& hi, __half& lo) {
    hi = __float2half_rn(v);
    lo = __float2half_rn(v - __half2float(hi));
}

// ---------------------------------------------------------------------------
// Split kernels (fp32 -> fp16 hi/lo)
// ---------------------------------------------------------------------------
__global__ __launch_bounds__(256) void split_x_kernel(
    const float* __restrict__ src,
    __half* __restrict__ hi, __half* __restrict__ lo, int n4)
{
    int i = blockIdx.x * blockDim.x + threadIdx.x;
    if (i >= n4) return;
    float4 v = ((const float4*)src)[i];
    __half h0, h1, h2, h3, l0, l1, l2, l3;
    split_h(v.x, h0, l0); split_h(v.y, h1, l1);
    split_h(v.z, h2, l2); split_h(v.w, h3, l3);
    union { __half b[4]; uint2 u; } ph, pl;
    ph.b[0] = h0; ph.b[1] = h1; ph.b[2] = h2; ph.b[3] = h3;
    pl.b[0] = l0; pl.b[1] = l1; pl.b[2] = l2; pl.b[3] = l3;
    ((uint2*)hi)[i] = ph.u;
    ((uint2*)lo)[i] = pl.u;
}

// all 4 weight matrices in one launch; dest arrays are contiguous per-matrix
__global__ __launch_bounds__(256) void split_w4_kernel(
    const float* __restrict__ w0, const float* __restrict__ w1,
    const float* __restrict__ w2, const float* __restrict__ w3,
    __half* __restrict__ hi, __half* __restrict__ lo, int n4_each)
{
    int i = blockIdx.x * blockDim.x + threadIdx.x;
    if (i >= 4 * n4_each) return;
    const int m = i / n4_each, j = i - m * n4_each;
    const float* src = (m == 0) ? w0 : (m == 1) ? w1 : (m == 2) ? w2 : w3;
    float4 v = ((const float4*)src)[j];
    __half h0, h1, h2, h3, l0, l1, l2, l3;
    split_h(v.x, h0, l0); split_h(v.y, h1, l1);
    split_h(v.z, h2, l2); split_h(v.w, h3, l3);
    union { __half b[4]; uint2 u; } ph, pl;
    ph.b[0] = h0; ph.b[1] = h1; ph.b[2] = h2; ph.b[3] = h3;
    pl.b[0] = l0; pl.b[1] = l1; pl.b[2] = l2; pl.b[3] = l3;
    ((uint2*)hi)[i] = ph.u;
    ((uint2*)lo)[i] = pl.u;
}

// ---------------------------------------------------------------------------
// fp16 split mma.sync GEMM:  C = A @ W^T + bias.
//   3-pass (use_bl=1): Ah*Bh + Al*Bh + Ah*Bl
//   2-pass (use_bl=0): Ah*Bh + Al*Bh
// __launch_bounds__(256,2): cap 128 regs -> 2 CTAs/SM (occupancy fix, R9).
// ---------------------------------------------------------------------------
#define GPITCH 40
#define GTILE_B (128 * GPITCH * 2)
#define GSTAGE_B (4 * GTILE_B)
#define GSMEM_B (2 * GSTAGE_B)

__global__ __launch_bounds__(256, 2) void gemm_fp16s_mma(
    const __half* __restrict__ Ah, const __half* __restrict__ Al,
    const __half* __restrict__ Bh, const __half* __restrict__ Bl,
    const float* __restrict__ bias, float* __restrict__ Cf32,
    __half* __restrict__ Oh, __half* __restrict__ Ol, float scale, int use_bl)
{
    extern __shared__ __align__(128) uint8_t smem[];
    const int tid  = threadIdx.x;
    const int wid  = tid >> 5;
    const int lane = tid & 31;
    const int wm   = wid & 3;
    const int wn   = wid >> 2;
    const int gm0  = blockIdx.y * 128;
    const int gn0  = blockIdx.x * 128;
    const uint32_t sbase = smem_to_u32(smem);

    const __half* srcs[4] = { Ah, Al, Bh, Bl };

    auto issue = [&](int s, int c) {
        const int k0 = c * 32;
#pragma unroll
        for (int t = 0; t < 4; ++t) {
            if (t == 3 && !use_bl) continue;
            const __half* src = srcs[t];
            const int rbase = (t < 2) ? gm0 : gn0;
#pragma unroll
            for (int j = 0; j < 2; ++j) {
                const int i = tid + j * 256;
                const int row = i >> 2, chunk = i & 3;
                const uint32_t sa = sbase + s * GSTAGE_B + t * GTILE_B
                                  + (uint32_t)(row * GPITCH + chunk * 8) * 2;
                const void* g = src + (size_t)(rbase + row) * Dd + k0 + chunk * 8;
                cp_async16(sa, g);
            }
        }
        cp_commit();
    };

    float acc[2][8][4];
#pragma unroll
    for (int mt = 0; mt < 2; ++mt)
#pragma unroll
        for (int nt = 0; nt < 8; ++nt)
#pragma unroll
            for (int q = 0; q < 4; ++q) acc[mt][nt][q] = 0.f;

    const int r   = lane >> 2;
    const int cp2 = (lane & 3) * 2;

    issue(0, 0);

    for (int c = 0; c < 32; ++c) {
        const int s = c & 1;
        if (c + 1 < 32) { issue((c + 1) & 1, c + 1); cp_wait<1>(); }
        else            { cp_wait<0>(); }
        __syncthreads();

        const uint8_t* stg = smem + s * GSTAGE_B;
        const uint8_t* pAh = stg;
        const uint8_t* pAl = stg + GTILE_B;
        const uint8_t* pBh = stg + 2 * GTILE_B;
        const uint8_t* pBl = stg + 3 * GTILE_B;

#pragma unroll
        for (int ks = 0; ks < 2; ++ks) {
            const int kk = ks * 16;
            uint32_t ah[2][4], al[2][4];
#pragma unroll
            for (int mt = 0; mt < 2; ++mt) {
                const int row = wm * 32 + mt * 16 + r;
                const uint32_t o00 = (uint32_t)(row * GPITCH + kk + cp2) * 2;
                const uint32_t o10 = (uint32_t)((row + 8) * GPITCH + kk + cp2) * 2;
                ah[mt][0] = *(const uint32_t*)(pAh + o00);
                ah[mt][1] = *(const uint32_t*)(pAh + o10);
                ah[mt][2] = *(const uint32_t*)(pAh + o00 + 16);
                ah[mt][3] = *(const uint32_t*)(pAh + o10 + 16);
                al[mt][0] = *(const uint32_t*)(pAl + o00);
                al[mt][1] = *(const uint32_t*)(pAl + o10);
                al[mt][2] = *(const uint32_t*)(pAl + o00 + 16);
                al[mt][3] = *(const uint32_t*)(pAl + o10 + 16);
            }
#pragma unroll
            for (int nt = 0; nt < 8; ++nt) {
                const int n = wn * 64 + nt * 8 + r;
                const uint32_t ob = (uint32_t)(n * GPITCH + kk + cp2) * 2;
                uint32_t bh[2];
                bh[0] = *(const uint32_t*)(pBh + ob);
                bh[1] = *(const uint32_t*)(pBh + ob + 16);
                mma16816(acc[0][nt], ah[0], bh);
                mma16816(acc[1][nt], ah[1], bh);
                mma16816(acc[0][nt], al[0], bh);
                mma16816(acc[1][nt], al[1], bh);
                if (use_bl) {
                    uint32_t bl[2];
                    bl[0] = *(const uint32_t*)(pBl + ob);
                    bl[1] = *(const uint32_t*)(pBl + ob + 16);
                    mma16816(acc[0][nt], ah[0], bl);
                    mma16816(acc[1][nt], ah[1], bl);
                }
            }
        }
        __syncthreads();
    }

    // Epilogue
#pragma unroll
    for (int mt = 0; mt < 2; ++mt) {
        const int row0 = gm0 + wm * 32 + mt * 16 + r;
#pragma unroll
        for (int nt = 0; nt < 8; ++nt) {
            const int col = gn0 + wn * 64 + nt * 8 + cp2;
            const float b0 = bias[col], b1 = bias[col + 1];
            float v0 = acc[mt][nt][0] + b0, v1 = acc[mt][nt][1] + b1;
            float v2 = acc[mt][nt][2] + b0, v3 = acc[mt][nt][3] + b1;
            if (Oh) {
                v0 *= scale; v1 *= scale; v2 *= scale; v3 *= scale;
                __half2 h01 = __floats2half2_rn(v0, v1);
                __half2 h23 = __floats2half2_rn(v2, v3);
                *(uint32_t*)(Oh + (size_t)row0 * Dd + col)       = h2_bits(h01);
                *(uint32_t*)(Oh + (size_t)(row0 + 8) * Dd + col) = h2_bits(h23);
                if (Ol) {
                    __half2 l01 = __floats2half2_rn(
                        v0 - __half2float(__low2half(h01)), v1 - __half2float(__high2half(h01)));
                    __half2 l23 = __floats2half2_rn(
                        v2 - __half2float(__low2half(h23)), v3 - __half2float(__high2half(h23)));
                    *(uint32_t*)(Ol + (size_t)row0 * Dd + col)       = h2_bits(l01);
                    *(uint32_t*)(Ol + (size_t)(row0 + 8) * Dd + col) = h2_bits(l23);
                }
            } else {
                float2 w0, w1;
                w0.x = v0; w0.y = v1; w1.x = v2; w1.y = v3;
                *(float2*)(Cf32 + (size_t)row0 * Dd + col)       = w0;
                *(float2*)(Cf32 + (size_t)(row0 + 8) * Dd + col) = w1;
            }
        }
    }
}

// ---------------------------------------------------------------------------
// Flash attention, fp16 mma.sync.
// S = (Qh+Ql) @ K  (K single fp16 -> 2 MMAs, exact wrt stored K);
// PV = (Ph+Pl) @ Vh (2-pass, V single fp16).
// Grid (T/128, H, B), 256 threads = 8 warps; warp w owns q rows [16w,16w+16).
// Q pre-scaled by 1/8 in the Q projection epilogue.
// ---------------------------------------------------------------------------
#define QPITCH 72     // fp16; pitch%64==8 -> conflict-free frag loads
#define VPITCH 136
#define AT_QH   0
#define AT_QL   18432
#define AT_K0   36864          // + s*18432 (K hi only now)
#define AT_VH   73728
#define AT_BIAS 91136
#define AT_SMEM 91648

__global__ __launch_bounds__(256, 1) void attn_mma_kernel(
    const __half* __restrict__ qh, const __half* __restrict__ ql,
    const __half* __restrict__ kh,
    const __half* __restrict__ vh,
    const int* __restrict__ mask,
    __half* __restrict__ och, __half* __restrict__ ocl)
{
    extern __shared__ __align__(128) uint8_t sm[];
    const uint32_t sb = smem_to_u32(sm);
    const int tid = threadIdx.x, wid = tid >> 5, lane = tid & 31;
    const int r = lane >> 2, c2 = (lane & 3) * 2;
    const int b = blockIdx.z, h = blockIdx.y;
    const int q0 = blockIdx.x * 128;
    const size_t gq = ((size_t)(b * Tt + q0)) * Dd + h * HDh;
    const size_t gk = ((size_t)(b * Tt)) * Dd + h * HDh;
    const int* mb = mask + b * Tt;

    // ---- preamble: stage Q (hi/lo) and K tile 0 via cp.async
#pragma unroll
    for (int j = 0; j < 4; ++j) {
        const int i = tid + j * 256, row = i >> 3, seg = i & 7;
        const uint32_t so = (uint32_t)((row * QPITCH + seg * 8) * 2);
        const size_t go = (size_t)row * Dd + seg * 8;
        cp_async16(sb + AT_QH + so, qh + gq + go);
        cp_async16(sb + AT_QL + so, ql + gq + go);
        cp_async16(sb + AT_K0 + so, kh + gk + go);
    }
    cp_commit();

    // ---- V register prefetch: thread -> kv rows 2vj,2vj+1, hd quarter vq*16
    const int vj = tid >> 2;
    const int vq = tid & 3;
    uint4 vr_h[2][2];
#pragma unroll
    for (int rr = 0; rr < 2; ++rr) {
        const size_t g = ((size_t)(b * Tt + 2 * vj + rr)) * Dd + h * HDh + vq * 16;
        vr_h[rr][0] = *(const uint4*)(vh + g);
        vr_h[rr][1] = *(const uint4*)(vh + g + 8);
    }

    float cacc[8][4];
#pragma unroll
    for (int nt = 0; nt < 8; ++nt)
#pragma unroll
        for (int q = 0; q < 4; ++q) cacc[nt][q] = 0.f;
    float m0 = -1e30f, m1 = -1e30f, l0 = 0.f, l1 = 0.f;
    uint32_t qAh[4][4], qAl[4][4];

    for (int c = 0; c < 16; ++c) {
        const int kv0 = c * 128;
        const int s = c & 1;
        cp_wait<0>();
        __syncthreads();   // K(c) visible; prev iter's Vt/K reads done

        // stage V^T(c) from regs (packed pairs via prmt) + mask bias
#pragma unroll
        for (int w = 0; w < 8; ++w) {
            const uint32_t a0 = ((const uint32_t*)&vr_h[0])[w];
            const uint32_t a1 = ((const uint32_t*)&vr_h[1])[w];
            const int hd = vq * 16 + 2 * w;
            *(uint32_t*)(sm + AT_VH + ((hd)     * VPITCH + 2 * vj) * 2) = __byte_perm(a0, a1, 0x5410);
            *(uint32_t*)(sm + AT_VH + ((hd + 1) * VPITCH + 2 * vj) * 2) = __byte_perm(a0, a1, 0x7632);
        }
        if (tid < 128)
            ((float*)(sm + AT_BIAS))[tid] = (mb[kv0 + tid] == 0) ? -1e30f : 0.f;

        // prefetch V(c+1) into regs
        if (c + 1 < 16) {
#pragma unroll
            for (int rr = 0; rr < 2; ++rr) {
                const size_t g = ((size_t)(b * Tt + kv0 + 128 + 2 * vj + rr)) * Dd + h * HDh + vq * 16;
                vr_h[rr][0] = *(const uint4*)(vh + g);
                vr_h[rr][1] = *(const uint4*)(vh + g + 8);
            }
        }

        if (c == 0) {   // Q A-frags, hoisted
#pragma unroll
            for (int kt = 0; kt < 4; ++kt) {
                const uint32_t o  = (uint32_t)(((wid * 16 + r) * QPITCH + kt * 16 + c2) * 2);
                const uint32_t o8 = o + 8 * QPITCH * 2;
                qAh[kt][0] = *(const uint32_t*)(sm + AT_QH + o);
                qAh[kt][1] = *(const uint32_t*)(sm + AT_QH + o8);
                qAh[kt][2] = *(const uint32_t*)(sm + AT_QH + o + 16);
                qAh[kt][3] = *(const uint32_t*)(sm + AT_QH + o8 + 16);
                qAl[kt][0] = *(const uint32_t*)(sm + AT_QL + o);
                qAl[kt][1] = *(const uint32_t*)(sm + AT_QL + o8);
                qAl[kt][2] = *(const uint32_t*)(sm + AT_QL + o + 16);
                qAl[kt][3] = *(const uint32_t*)(sm + AT_QL + o8 + 16);
            }
        }

        // prefetch K(c+1) -> stage s^1 (safe: all warps past sync above)
        if (c + 1 < 16) {
#pragma unroll
            for (int j = 0; j < 4; ++j) {
                const int i = tid + j * 256, row = i >> 3, seg = i & 7;
                const uint32_t so = (uint32_t)((row * QPITCH + seg * 8) * 2);
                const size_t g = gk + (size_t)(kv0 + 128 + row) * Dd + seg * 8;
                cp_async16(sb + AT_K0 + (s ^ 1) * 18432 + so, kh + g);
            }
        }
        cp_commit();
        __syncthreads();   // Vt(c), bias visible

        // ---- S = (Qh+Ql) K^T  (K single fp16, 2 MMAs)
        const uint8_t* Ksh = sm + AT_K0 + s * 18432;
        float sacc[16][4];
#pragma unroll
        for (int nt = 0; nt < 16; ++nt)
#pragma unroll
            for (int q = 0; q < 4; ++q) sacc[nt][q] = 0.f;
#pragma unroll
        for (int kt = 0; kt < 4; ++kt) {
#pragma unroll
            for (int nt = 0; nt < 16; ++nt) {
                const uint32_t o = (uint32_t)(((nt * 8 + r) * QPITCH + kt * 16 + c2) * 2);
                uint32_t bh2[2];
                bh2[0] = *(const uint32_t*)(Ksh + o);
                bh2[1] = *(const uint32_t*)(Ksh + o + 16);
                mma16816(sacc[nt], qAh[kt], bh2);
                mma16816(sacc[nt], qAl[kt], bh2);
            }
        }

        // ---- mask bias + online softmax
        const float* bias = (const float*)(sm + AT_BIAS);
        float tmax0 = -1e30f, tmax1 = -1e30f;
#pragma unroll
        for (int nt = 0; nt < 16; ++nt) {
            const float2 bv = *(const float2*)(bias + nt * 8 + c2);
            sacc[nt][0] += bv.x; sacc[nt][1] += bv.y;
            sacc[nt][2] += bv.x; sacc[nt][3] += bv.y;
            tmax0 = fmaxf(tmax0, fmaxf(sacc[nt][0], sacc[nt][1]));
            tmax1 = fmaxf(tmax1, fmaxf(sacc[nt][2], sacc[nt][3]));
        }
        tmax0 = fmaxf(tmax0, __shfl_xor_sync(0xffffffffu, tmax0, 1));
        tmax0 = fmaxf(tmax0, __shfl_xor_sync(0xffffffffu, tmax0, 2));
        tmax1 = fmaxf(tmax1, __shfl_xor_sync(0xffffffffu, tmax1, 1));
        tmax1 = fmaxf(tmax1, __shfl_xor_sync(0xffffffffu, tmax1, 2));
        const float mn0 = fmaxf(m0, tmax0), mn1 = fmaxf(m1, tmax1);
        const float al0 = __expf(m0 - mn0), al1 = __expf(m1 - mn1);
        m0 = mn0; m1 = mn1;
        float rs0 = 0.f, rs1 = 0.f;
#pragma unroll
        for (int nt = 0; nt < 16; ++nt) {
            sacc[nt][0] = __expf(sacc[nt][0] - mn0);
            sacc[nt][1] = __expf(sacc[nt][1] - mn0);
            sacc[nt][2] = __expf(sacc[nt][2] - mn1);
            sacc[nt][3] = __expf(sacc[nt][3] - mn1);
            rs0 += sacc[nt][0] + sacc[nt][1];
            rs1 += sacc[nt][2] + sacc[nt][3];
        }
        rs0 += __shfl_xor_sync(0xffffffffu, rs0, 1);
        rs0 += __shfl_xor_sync(0xffffffffu, rs0, 2);
        rs1 += __shfl_xor_sync(0xffffffffu, rs1, 1);
        rs1 += __shfl_xor_sync(0xffffffffu, rs1, 2);
        l0 = l0 * al0 + rs0;
        l1 = l1 * al1 + rs1;
#pragma unroll
        for (int nt = 0; nt < 8; ++nt) {
            cacc[nt][0] *= al0; cacc[nt][1] *= al0;
            cacc[nt][2] *= al1; cacc[nt][3] *= al1;
        }

        // ---- PV: P frags (fp16 hi/lo) x V^T hi (2-pass)
#pragma unroll
        for (int kt = 0; kt < 8; ++kt) {
            uint32_t aPh[4], aPl[4];
#pragma unroll
            for (int u = 0; u < 2; ++u) {
                const float p0 = sacc[2 * kt + u][0], p1 = sacc[2 * kt + u][1];
                const float p2 = sacc[2 * kt + u][2], p3 = sacc[2 * kt + u][3];
                const __half2 h01 = __floats2half2_rn(p0, p1);
                const __half2 h23 = __floats2half2_rn(p2, p3);
                const __half2 q01 = __floats2half2_rn(
                    p0 - __half2float(__low2half(h01)), p1 - __half2float(__high2half(h01)));
                const __half2 q23 = __floats2half2_rn(
                    p2 - __half2float(__low2half(h23)), p3 - __half2float(__high2half(h23)));
                aPh[2 * u + 0] = h2_bits(h01);
                aPh[2 * u + 1] = h2_bits(h23);
                aPl[2 * u + 0] = h2_bits(q01);
                aPl[2 * u + 1] = h2_bits(q23);
            }
#pragma unroll
            for (int nt = 0; nt < 8; ++nt) {
                const uint32_t o = (uint32_t)(((nt * 8 + r) * VPITCH + kt * 16 + c2) * 2);
                uint32_t bh2[2];
                bh2[0] = *(const uint32_t*)(sm + AT_VH + o);
                bh2[1] = *(const uint32_t*)(sm + AT_VH + o + 16);
                mma16816(cacc[nt], aPh, bh2);
                mma16816(cacc[nt], aPl, bh2);
            }
        }
    }

    // ---- epilogue: normalize, split to fp16 hi/lo, write ctx
    const float inv0 = 1.0f / l0, inv1 = 1.0f / l1;
    const int row0 = q0 + wid * 16 + r;
    const size_t ob = ((size_t)(b * Tt) + row0) * Dd + h * HDh;
#pragma unroll
    for (int nt = 0; nt < 8; ++nt) {
        const int col = nt * 8 + c2;
        const float v0 = cacc[nt][0] * inv0, v1 = cacc[nt][1] * inv0;
        const float v2 = cacc[nt][2] * inv1, v3 = cacc[nt][3] * inv1;
        const __half2 h01 = __floats2half2_rn(v0, v1);
        const __half2 h23 = __floats2half2_rn(v2, v3);
        const __half2 q01 = __floats2half2_rn(
            v0 - __half2float(__low2half(h01)), v1 - __half2float(__high2half(h01)));
        const __half2 q23 = __floats2half2_rn(
            v2 - __half2float(__low2half(h23)), v3 - __half2float(__high2half(h23)));
        *(uint32_t*)(och + ob + col)            = h2_bits(h01);
        *(uint32_t*)(ocl + ob + col)            = h2_bits(q01);
        *(uint32_t*)(och + ob + 8 * Dd + col)   = h2_bits(h23);
        *(uint32_t*)(ocl + ob + 8 * Dd + col)   = h2_bits(q23);
    }
}

// ---------------------------------------------------------------------------
extern "C" void kernel_launch(void* const* d_in, const int* in_sizes, int n_in,
                              void* d_out, int out_size)
{
    const float* x  = (const float*)d_in[0];
    const float* Wq = (const float*)d_in[1];
    const float* bq = (const float*)d_in[2];
    const float* Wk = (const float*)d_in[3];
    const float* bk = (const float*)d_in[4];
    const float* Wv = (const float*)d_in[5];
    const float* bv = (const float*)d_in[6];
    const float* Wo = (const float*)d_in[7];
    const float* bo = (const float*)d_in[8];
    const int* mask = (const int*)d_in[9];
    float* out = (float*)d_out;

    __half *xh, *xl, *qhp, *qlp, *khp, *vhp, *chp, *clp, *wh, *wl;
    cudaGetSymbolAddress((void**)&xh, g_xh);
    cudaGetSymbolAddress((void**)&xl, g_xl);
    cudaGetSymbolAddress((void**)&qhp, g_qh);
    cudaGetSymbolAddress((void**)&qlp, g_ql);
    cudaGetSymbolAddress((void**)&khp, g_kh);
    cudaGetSymbolAddress((void**)&vhp, g_vh);
    cudaGetSymbolAddress((void**)&chp, g_ch);
    cudaGetSymbolAddress((void**)&clp, g_cl);
    cudaGetSymbolAddress((void**)&wh, g_wh);
    cudaGetSymbolAddress((void**)&wl, g_wl);

    const size_t WSZ = (size_t)Dd * Dd;
    const int n4x = (Mm * Dd) / 4;
    const int n4w = (int)(WSZ / 4);

    // launch 0: split x; launch 1: split all weights
    split_x_kernel<<<(n4x + 255) / 256, 256>>>(x, xh, xl, n4x);
    split_w4_kernel<<<(4 * n4w + 255) / 256, 256>>>(Wq, Wk, Wv, Wo, wh, wl, n4w);

    cudaFuncSetAttribute(gemm_fp16s_mma,
                         cudaFuncAttributeMaxDynamicSharedMemorySize, GSMEM_B);
    dim3 ggrid(Dd / 128, Mm / 128);
    // launch 2: Q projection 3-pass -> fp16 hi/lo (pre-scaled 1/8)
    gemm_fp16s_mma<<<ggrid, 256, GSMEM_B>>>(xh, xl, wh + 0 * WSZ, wl + 0 * WSZ, bq,
                                            nullptr, qhp, qlp, 0.125f, 1);
    // launches 3,4: K,V projections 2-pass -> single fp16
    gemm_fp16s_mma<<<ggrid, 256, GSMEM_B>>>(xh, xl, wh + 1 * WSZ, wl + 1 * WSZ, bk,
                                            nullptr, khp, nullptr, 1.0f, 0);
    gemm_fp16s_mma<<<ggrid, 256, GSMEM_B>>>(xh, xl, wh + 2 * WSZ, wl + 2 * WSZ, bv,
                                            nullptr, vhp, nullptr, 1.0f, 0);

    // launch 5: fused attention (ncu -s 5 captures this one)
    cudaFuncSetAttribute(attn_mma_kernel,
                         cudaFuncAttributeMaxDynamicSharedMemorySize, AT_SMEM);
    attn_mma_kernel<<<dim3(Tt / 128, Hh, Bb), 256, AT_SMEM>>>(
        qhp, qlp, khp, vhp, mask, chp, clp);

    // launch 6: output projection 2-pass -> fp32
    gemm_fp16s_mma<<<ggrid, 256, GSMEM_B>>>(chp, clp, wh + 3 * WSZ, wl + 3 * WSZ, bo,
                                            out, nullptr, nullptr, 1.0f, 0);
}

// round 11
// speedup vs baseline: 3.6930x; 1.0532x over previous
#include <cuda_runtime.h>
#include <cuda_fp16.h>
#include <cstdint>

// Problem constants
#define Bb  4
#define Tt  2048
#define Dd  1024
#define Hh  16
#define HDh 64
#define Mm  (Bb * Tt)   // 8192 rows

// ---------------------------------------------------------------------------
// Scratch (device globals: allocation-free rule). All fp16.
// ---------------------------------------------------------------------------
__device__ __half g_xh[(size_t)Mm * Dd];
__device__ __half g_xl[(size_t)Mm * Dd];
__device__ __half g_qh[(size_t)Mm * Dd];
__device__ __half g_ql[(size_t)Mm * Dd];
__device__ __half g_kh[(size_t)Mm * Dd];          // K single-rounded
__device__ __half g_vh[(size_t)Mm * Dd];          // V single-rounded
__device__ __half g_ch[(size_t)Mm * Dd];
__device__ __half g_cl[(size_t)Mm * Dd];
__device__ __half g_wh[4 * (size_t)Dd * Dd];
__device__ __half g_wl[4 * (size_t)Dd * Dd];

// ---------------------------------------------------------------------------
// sm_100-base helpers: cp.async + mma.sync fp16 (tcgen05 unavailable here)
// ---------------------------------------------------------------------------
__device__ __forceinline__ uint32_t smem_to_u32(const void* p) {
    uint32_t a;
    asm("{ .reg .u64 t; cvta.to.shared.u64 t, %1; cvt.u32.u64 %0, t; }"
        : "=r"(a) : "l"(p));
    return a;
}
__device__ __forceinline__ void cp_async16(uint32_t smem_addr, const void* gptr) {
    asm volatile("cp.async.cg.shared.global [%0], [%1], 16;"
                 :: "r"(smem_addr), "l"(gptr));
}
__device__ __forceinline__ void cp_commit() {
    asm volatile("cp.async.commit_group;");
}
template <int N>
__device__ __forceinline__ void cp_wait() {
    asm volatile("cp.async.wait_group %0;" :: "n"(N));
}
// D += A*B, m16n8k16 fp16 in / fp32 accum; A row-major, B col-major
__device__ __forceinline__ void mma16816(float* d, const uint32_t* a, const uint32_t* b) {
    asm volatile(
        "mma.sync.aligned.m16n8k16.row.col.f32.f16.f16.f32 "
        "{%0,%1,%2,%3}, {%4,%5,%6,%7}, {%8,%9}, {%0,%1,%2,%3};"
        : "+f"(d[0]), "+f"(d[1]), "+f"(d[2]), "+f"(d[3])
        : "r"(a[0]), "r"(a[1]), "r"(a[2]), "r"(a[3]), "r"(b[0]), "r"(b[1]));
}
__device__ __forceinline__ uint32_t h2_bits(__half2 v) {
    union { __half2 h; uint32_t u; } cv; cv.h = v; return cv.u;
}
// hi/lo split of one float into two fp16
__device__ __forceinline__ void split_h(float v, __half& hi, __half& lo) {
    hi = __float2half_rn(v);
    lo = __float2half_rn(v - __half2float(hi));
}

// ---------------------------------------------------------------------------
// Split kernels (fp32 -> fp16 hi/lo)
// ---------------------------------------------------------------------------
__global__ __launch_bounds__(256) void split_x_kernel(
    const float* __restrict__ src,
    __half* __restrict__ hi, __half* __restrict__ lo, int n4)
{
    int i = blockIdx.x * blockDim.x + threadIdx.x;
    if (i >= n4) return;
    float4 v = ((const float4*)src)[i];
    __half h0, h1, h2, h3, l0, l1, l2, l3;
    split_h(v.x, h0, l0); split_h(v.y, h1, l1);
    split_h(v.z, h2, l2); split_h(v.w, h3, l3);
    union { __half b[4]; uint2 u; } ph, pl;
    ph.b[0] = h0; ph.b[1] = h1; ph.b[2] = h2; ph.b[3] = h3;
    pl.b[0] = l0; pl.b[1] = l1; pl.b[2] = l2; pl.b[3] = l3;
    ((uint2*)hi)[i] = ph.u;
    ((uint2*)lo)[i] = pl.u;
}

// all 4 weight matrices in one launch; dest arrays are contiguous per-matrix
__global__ __launch_bounds__(256) void split_w4_kernel(
    const float* __restrict__ w0, const float* __restrict__ w1,
    const float* __restrict__ w2, const float* __restrict__ w3,
    __half* __restrict__ hi, __half* __restrict__ lo, int n4_each)
{
    int i = blockIdx.x * blockDim.x + threadIdx.x;
    if (i >= 4 * n4_each) return;
    const int m = i / n4_each, j = i - m * n4_each;
    const float* src = (m == 0) ? w0 : (m == 1) ? w1 : (m == 2) ? w2 : w3;
    float4 v = ((const float4*)src)[j];
    __half h0, h1, h2, h3, l0, l1, l2, l3;
    split_h(v.x, h0, l0); split_h(v.y, h1, l1);
    split_h(v.z, h2, l2); split_h(v.w, h3, l3);
    union { __half b[4]; uint2 u; } ph, pl;
    ph.b[0] = h0; ph.b[1] = h1; ph.b[2] = h2; ph.b[3] = h3;
    pl.b[0] = l0; pl.b[1] = l1; pl.b[2] = l2; pl.b[3] = l3;
    ((uint2*)hi)[i] = ph.u;
    ((uint2*)lo)[i] = pl.u;
}

// ---------------------------------------------------------------------------
// fp16 split mma.sync GEMM:  C = A @ W^T + bias.
//   3-pass (use_bl=1): Ah*Bh + Al*Bh + Ah*Bl
//   2-pass (use_bl=0): Ah*Bh + Al*Bh
// __launch_bounds__(256,2): 2 CTAs/SM. R10: MMA issue reordered into passes
// over distinct accumulators (same-acc reuse distance 2 -> 8) to kill HMMA
// RAW stalls.
// ---------------------------------------------------------------------------
#define GPITCH 40
#define GTILE_B (128 * GPITCH * 2)
#define GSTAGE_B (4 * GTILE_B)
#define GSMEM_B (2 * GSTAGE_B)

__global__ __launch_bounds__(256, 2) void gemm_fp16s_mma(
    const __half* __restrict__ Ah, const __half* __restrict__ Al,
    const __half* __restrict__ Bh, const __half* __restrict__ Bl,
    const float* __restrict__ bias, float* __restrict__ Cf32,
    __half* __restrict__ Oh, __half* __restrict__ Ol, float scale, int use_bl)
{
    extern __shared__ __align__(128) uint8_t smem[];
    const int tid  = threadIdx.x;
    const int wid  = tid >> 5;
    const int lane = tid & 31;
    const int wm   = wid & 3;
    const int wn   = wid >> 2;
    const int gm0  = blockIdx.y * 128;
    const int gn0  = blockIdx.x * 128;
    const uint32_t sbase = smem_to_u32(smem);

    const __half* srcs[4] = { Ah, Al, Bh, Bl };

    auto issue = [&](int s, int c) {
        const int k0 = c * 32;
#pragma unroll
        for (int t = 0; t < 4; ++t) {
            if (t == 3 && !use_bl) continue;
            const __half* src = srcs[t];
            const int rbase = (t < 2) ? gm0 : gn0;
#pragma unroll
            for (int j = 0; j < 2; ++j) {
                const int i = tid + j * 256;
                const int row = i >> 2, chunk = i & 3;
                const uint32_t sa = sbase + s * GSTAGE_B + t * GTILE_B
                                  + (uint32_t)(row * GPITCH + chunk * 8) * 2;
                const void* g = src + (size_t)(rbase + row) * Dd + k0 + chunk * 8;
                cp_async16(sa, g);
            }
        }
        cp_commit();
    };

    float acc[2][8][4];
#pragma unroll
    for (int mt = 0; mt < 2; ++mt)
#pragma unroll
        for (int nt = 0; nt < 8; ++nt)
#pragma unroll
            for (int q = 0; q < 4; ++q) acc[mt][nt][q] = 0.f;

    const int r   = lane >> 2;
    const int cp2 = (lane & 3) * 2;

    issue(0, 0);

    for (int c = 0; c < 32; ++c) {
        const int s = c & 1;
        if (c + 1 < 32) { issue((c + 1) & 1, c + 1); cp_wait<1>(); }
        else            { cp_wait<0>(); }
        __syncthreads();

        const uint8_t* stg = smem + s * GSTAGE_B;
        const uint8_t* pAh = stg;
        const uint8_t* pAl = stg + GTILE_B;
        const uint8_t* pBh = stg + 2 * GTILE_B;
        const uint8_t* pBl = stg + 3 * GTILE_B;

#pragma unroll
        for (int ks = 0; ks < 2; ++ks) {
            const int kk = ks * 16;
            uint32_t ah[2][4], al[2][4];
#pragma unroll
            for (int mt = 0; mt < 2; ++mt) {
                const int row = wm * 32 + mt * 16 + r;
                const uint32_t o00 = (uint32_t)(row * GPITCH + kk + cp2) * 2;
                const uint32_t o10 = (uint32_t)((row + 8) * GPITCH + kk + cp2) * 2;
                ah[mt][0] = *(const uint32_t*)(pAh + o00);
                ah[mt][1] = *(const uint32_t*)(pAh + o10);
                ah[mt][2] = *(const uint32_t*)(pAh + o00 + 16);
                ah[mt][3] = *(const uint32_t*)(pAh + o10 + 16);
                al[mt][0] = *(const uint32_t*)(pAl + o00);
                al[mt][1] = *(const uint32_t*)(pAl + o10);
                al[mt][2] = *(const uint32_t*)(pAl + o00 + 16);
                al[mt][3] = *(const uint32_t*)(pAl + o10 + 16);
            }
            // R10: process nt in halves of 4; within each half issue MMAs in
            // passes over 8 distinct accumulators (no RAW at distance < 8).
#pragma unroll
            for (int nh = 0; nh < 2; ++nh) {
                uint32_t bh[4][2], bl[4][2];
#pragma unroll
                for (int nt = 0; nt < 4; ++nt) {
                    const int n = wn * 64 + (nh * 4 + nt) * 8 + r;
                    const uint32_t ob = (uint32_t)(n * GPITCH + kk + cp2) * 2;
                    bh[nt][0] = *(const uint32_t*)(pBh + ob);
                    bh[nt][1] = *(const uint32_t*)(pBh + ob + 16);
                    if (use_bl) {
                        bl[nt][0] = *(const uint32_t*)(pBl + ob);
                        bl[nt][1] = *(const uint32_t*)(pBl + ob + 16);
                    }
                }
#pragma unroll
                for (int nt = 0; nt < 4; ++nt) {
                    mma16816(acc[0][nh * 4 + nt], ah[0], bh[nt]);
                    mma16816(acc[1][nh * 4 + nt], ah[1], bh[nt]);
                }
#pragma unroll
                for (int nt = 0; nt < 4; ++nt) {
                    mma16816(acc[0][nh * 4 + nt], al[0], bh[nt]);
                    mma16816(acc[1][nh * 4 + nt], al[1], bh[nt]);
                }
                if (use_bl) {
#pragma unroll
                    for (int nt = 0; nt < 4; ++nt) {
                        mma16816(acc[0][nh * 4 + nt], ah[0], bl[nt]);
                        mma16816(acc[1][nh * 4 + nt], ah[1], bl[nt]);
                    }
                }
            }
        }
        __syncthreads();
    }

    // Epilogue
#pragma unroll
    for (int mt = 0; mt < 2; ++mt) {
        const int row0 = gm0 + wm * 32 + mt * 16 + r;
#pragma unroll
        for (int nt = 0; nt < 8; ++nt) {
            const int col = gn0 + wn * 64 + nt * 8 + cp2;
            const float b0 = bias[col], b1 = bias[col + 1];
            float v0 = acc[mt][nt][0] + b0, v1 = acc[mt][nt][1] + b1;
            float v2 = acc[mt][nt][2] + b0, v3 = acc[mt][nt][3] + b1;
            if (Oh) {
                v0 *= scale; v1 *= scale; v2 *= scale; v3 *= scale;
                __half2 h01 = __floats2half2_rn(v0, v1);
                __half2 h23 = __floats2half2_rn(v2, v3);
                *(uint32_t*)(Oh + (size_t)row0 * Dd + col)       = h2_bits(h01);
                *(uint32_t*)(Oh + (size_t)(row0 + 8) * Dd + col) = h2_bits(h23);
                if (Ol) {
                    __half2 l01 = __floats2half2_rn(
                        v0 - __half2float(__low2half(h01)), v1 - __half2float(__high2half(h01)));
                    __half2 l23 = __floats2half2_rn(
                        v2 - __half2float(__low2half(h23)), v3 - __half2float(__high2half(h23)));
                    *(uint32_t*)(Ol + (size_t)row0 * Dd + col)       = h2_bits(l01);
                    *(uint32_t*)(Ol + (size_t)(row0 + 8) * Dd + col) = h2_bits(l23);
                }
            } else {
                float2 w0, w1;
                w0.x = v0; w0.y = v1; w1.x = v2; w1.y = v3;
                *(float2*)(Cf32 + (size_t)row0 * Dd + col)       = w0;
                *(float2*)(Cf32 + (size_t)(row0 + 8) * Dd + col) = w1;
            }
        }
    }
}

// ---------------------------------------------------------------------------
// Flash attention, fp16 mma.sync.
// S = (Qh+Ql) @ K (K single fp16); PV = (Ph+Pl) @ Vh.
// R10: MMA passes reordered over distinct accumulators (distance 1 -> 8).
// Grid (T/128, H, B), 256 threads = 8 warps; warp w owns q rows [16w,16w+16).
// Q pre-scaled by 1/8 in the Q projection epilogue.
// ---------------------------------------------------------------------------
#define QPITCH 72     // fp16; pitch%64==8 -> conflict-free frag loads
#define VPITCH 136
#define AT_QH   0
#define AT_QL   18432
#define AT_K0   36864          // + s*18432 (K hi only)
#define AT_VH   73728
#define AT_BIAS 91136
#define AT_SMEM 91648

__global__ __launch_bounds__(256, 1) void attn_mma_kernel(
    const __half* __restrict__ qh, const __half* __restrict__ ql,
    const __half* __restrict__ kh,
    const __half* __restrict__ vh,
    const int* __restrict__ mask,
    __half* __restrict__ och, __half* __restrict__ ocl)
{
    extern __shared__ __align__(128) uint8_t sm[];
    const uint32_t sb = smem_to_u32(sm);
    const int tid = threadIdx.x, wid = tid >> 5, lane = tid & 31;
    const int r = lane >> 2, c2 = (lane & 3) * 2;
    const int b = blockIdx.z, h = blockIdx.y;
    const int q0 = blockIdx.x * 128;
    const size_t gq = ((size_t)(b * Tt + q0)) * Dd + h * HDh;
    const size_t gk = ((size_t)(b * Tt)) * Dd + h * HDh;
    const int* mb = mask + b * Tt;

    // ---- preamble: stage Q (hi/lo) and K tile 0 via cp.async
#pragma unroll
    for (int j = 0; j < 4; ++j) {
        const int i = tid + j * 256, row = i >> 3, seg = i & 7;
        const uint32_t so = (uint32_t)((row * QPITCH + seg * 8) * 2);
        const size_t go = (size_t)row * Dd + seg * 8;
        cp_async16(sb + AT_QH + so, qh + gq + go);
        cp_async16(sb + AT_QL + so, ql + gq + go);
        cp_async16(sb + AT_K0 + so, kh + gk + go);
    }
    cp_commit();

    // ---- V register prefetch: thread -> kv rows 2vj,2vj+1, hd quarter vq*16
    const int vj = tid >> 2;
    const int vq = tid & 3;
    uint4 vr_h[2][2];
#pragma unroll
    for (int rr = 0; rr < 2; ++rr) {
        const size_t g = ((size_t)(b * Tt + 2 * vj + rr)) * Dd + h * HDh + vq * 16;
        vr_h[rr][0] = *(const uint4*)(vh + g);
        vr_h[rr][1] = *(const uint4*)(vh + g + 8);
    }

    float cacc[8][4];
#pragma unroll
    for (int nt = 0; nt < 8; ++nt)
#pragma unroll
        for (int q = 0; q < 4; ++q) cacc[nt][q] = 0.f;
    float m0 = -1e30f, m1 = -1e30f, l0 = 0.f, l1 = 0.f;
    uint32_t qAh[4][4], qAl[4][4];

    for (int c = 0; c < 16; ++c) {
        const int kv0 = c * 128;
        const int s = c & 1;
        cp_wait<0>();
        __syncthreads();   // K(c) visible; prev iter's Vt/K reads done

        // stage V^T(c) from regs (packed pairs via prmt) + mask bias
#pragma unroll
        for (int w = 0; w < 8; ++w) {
            const uint32_t a0 = ((const uint32_t*)&vr_h[0])[w];
            const uint32_t a1 = ((const uint32_t*)&vr_h[1])[w];
            const int hd = vq * 16 + 2 * w;
            *(uint32_t*)(sm + AT_VH + ((hd)     * VPITCH + 2 * vj) * 2) = __byte_perm(a0, a1, 0x5410);
            *(uint32_t*)(sm + AT_VH + ((hd + 1) * VPITCH + 2 * vj) * 2) = __byte_perm(a0, a1, 0x7632);
        }
        if (tid < 128)
            ((float*)(sm + AT_BIAS))[tid] = (mb[kv0 + tid] == 0) ? -1e30f : 0.f;

        // prefetch V(c+1) into regs
        if (c + 1 < 16) {
#pragma unroll
            for (int rr = 0; rr < 2; ++rr) {
                const size_t g = ((size_t)(b * Tt + kv0 + 128 + 2 * vj + rr)) * Dd + h * HDh + vq * 16;
                vr_h[rr][0] = *(const uint4*)(vh + g);
                vr_h[rr][1] = *(const uint4*)(vh + g + 8);
            }
        }

        if (c == 0) {   // Q A-frags, hoisted
#pragma unroll
            for (int kt = 0; kt < 4; ++kt) {
                const uint32_t o  = (uint32_t)(((wid * 16 + r) * QPITCH + kt * 16 + c2) * 2);
                const uint32_t o8 = o + 8 * QPITCH * 2;
                qAh[kt][0] = *(const uint32_t*)(sm + AT_QH + o);
                qAh[kt][1] = *(const uint32_t*)(sm + AT_QH + o8);
                qAh[kt][2] = *(const uint32_t*)(sm + AT_QH + o + 16);
                qAh[kt][3] = *(const uint32_t*)(sm + AT_QH + o8 + 16);
                qAl[kt][0] = *(const uint32_t*)(sm + AT_QL + o);
                qAl[kt][1] = *(const uint32_t*)(sm + AT_QL + o8);
                qAl[kt][2] = *(const uint32_t*)(sm + AT_QL + o + 16);
                qAl[kt][3] = *(const uint32_t*)(sm + AT_QL + o8 + 16);
            }
        }

        // prefetch K(c+1) -> stage s^1 (safe: all warps past sync above)
        if (c + 1 < 16) {
#pragma unroll
            for (int j = 0; j < 4; ++j) {
                const int i = tid + j * 256, row = i >> 3, seg = i & 7;
                const uint32_t so = (uint32_t)((row * QPITCH + seg * 8) * 2);
                const size_t g = gk + (size_t)(kv0 + 128 + row) * Dd + seg * 8;
                cp_async16(sb + AT_K0 + (s ^ 1) * 18432 + so, kh + g);
            }
        }
        cp_commit();
        __syncthreads();   // Vt(c), bias visible

        // ---- S = (Qh+Ql) K^T  (R10: pass-ordered, distance-8 acc reuse)
        const uint8_t* Ksh = sm + AT_K0 + s * 18432;
        float sacc[16][4];
#pragma unroll
        for (int nt = 0; nt < 16; ++nt)
#pragma unroll
            for (int q = 0; q < 4; ++q) sacc[nt][q] = 0.f;
#pragma unroll
        for (int kt = 0; kt < 4; ++kt) {
#pragma unroll
            for (int nh = 0; nh < 2; ++nh) {
                uint32_t bk2[8][2];
#pragma unroll
                for (int nt = 0; nt < 8; ++nt) {
                    const uint32_t o = (uint32_t)((((nh * 8 + nt) * 8 + r) * QPITCH + kt * 16 + c2) * 2);
                    bk2[nt][0] = *(const uint32_t*)(Ksh + o);
                    bk2[nt][1] = *(const uint32_t*)(Ksh + o + 16);
                }
#pragma unroll
                for (int nt = 0; nt < 8; ++nt)
                    mma16816(sacc[nh * 8 + nt], qAh[kt], bk2[nt]);
#pragma unroll
                for (int nt = 0; nt < 8; ++nt)
                    mma16816(sacc[nh * 8 + nt], qAl[kt], bk2[nt]);
            }
        }

        // ---- mask bias + online softmax
        const float* bias = (const float*)(sm + AT_BIAS);
        float tmax0 = -1e30f, tmax1 = -1e30f;
#pragma unroll
        for (int nt = 0; nt < 16; ++nt) {
            const float2 bv = *(const float2*)(bias + nt * 8 + c2);
            sacc[nt][0] += bv.x; sacc[nt][1] += bv.y;
            sacc[nt][2] += bv.x; sacc[nt][3] += bv.y;
            tmax0 = fmaxf(tmax0, fmaxf(sacc[nt][0], sacc[nt][1]));
            tmax1 = fmaxf(tmax1, fmaxf(sacc[nt][2], sacc[nt][3]));
        }
        tmax0 = fmaxf(tmax0, __shfl_xor_sync(0xffffffffu, tmax0, 1));
        tmax0 = fmaxf(tmax0, __shfl_xor_sync(0xffffffffu, tmax0, 2));
        tmax1 = fmaxf(tmax1, __shfl_xor_sync(0xffffffffu, tmax1, 1));
        tmax1 = fmaxf(tmax1, __shfl_xor_sync(0xffffffffu, tmax1, 2));
        const float mn0 = fmaxf(m0, tmax0), mn1 = fmaxf(m1, tmax1);
        const float al0 = __expf(m0 - mn0), al1 = __expf(m1 - mn1);
        m0 = mn0; m1 = mn1;
        float rs0 = 0.f, rs1 = 0.f;
#pragma unroll
        for (int nt = 0; nt < 16; ++nt) {
            sacc[nt][0] = __expf(sacc[nt][0] - mn0);
            sacc[nt][1] = __expf(sacc[nt][1] - mn0);
            sacc[nt][2] = __expf(sacc[nt][2] - mn1);
            sacc[nt][3] = __expf(sacc[nt][3] - mn1);
            rs0 += sacc[nt][0] + sacc[nt][1];
            rs1 += sacc[nt][2] + sacc[nt][3];
        }
        rs0 += __shfl_xor_sync(0xffffffffu, rs0, 1);
        rs0 += __shfl_xor_sync(0xffffffffu, rs0, 2);
        rs1 += __shfl_xor_sync(0xffffffffu, rs1, 1);
        rs1 += __shfl_xor_sync(0xffffffffu, rs1, 2);
        l0 = l0 * al0 + rs0;
        l1 = l1 * al1 + rs1;
#pragma unroll
        for (int nt = 0; nt < 8; ++nt) {
            cacc[nt][0] *= al0; cacc[nt][1] *= al0;
            cacc[nt][2] *= al1; cacc[nt][3] *= al1;
        }

        // ---- PV: P frags (fp16 hi/lo) x V^T hi (R10: pass-ordered)
#pragma unroll
        for (int kt = 0; kt < 8; ++kt) {
            uint32_t aPh[4], aPl[4];
#pragma unroll
            for (int u = 0; u < 2; ++u) {
                const float p0 = sacc[2 * kt + u][0], p1 = sacc[2 * kt + u][1];
                const float p2 = sacc[2 * kt + u][2], p3 = sacc[2 * kt + u][3];
                const __half2 h01 = __floats2half2_rn(p0, p1);
                const __half2 h23 = __floats2half2_rn(p2, p3);
                const __half2 q01 = __floats2half2_rn(
                    p0 - __half2float(__low2half(h01)), p1 - __half2float(__high2half(h01)));
                const __half2 q23 = __floats2half2_rn(
                    p2 - __half2float(__low2half(h23)), p3 - __half2float(__high2half(h23)));
                aPh[2 * u + 0] = h2_bits(h01);
                aPh[2 * u + 1] = h2_bits(h23);
                aPl[2 * u + 0] = h2_bits(q01);
                aPl[2 * u + 1] = h2_bits(q23);
            }
            uint32_t bv2[8][2];
#pragma unroll
            for (int nt = 0; nt < 8; ++nt) {
                const uint32_t o = (uint32_t)(((nt * 8 + r) * VPITCH + kt * 16 + c2) * 2);
                bv2[nt][0] = *(const uint32_t*)(sm + AT_VH + o);
                bv2[nt][1] = *(const uint32_t*)(sm + AT_VH + o + 16);
            }
#pragma unroll
            for (int nt = 0; nt < 8; ++nt)
                mma16816(cacc[nt], aPh, bv2[nt]);
#pragma unroll
            for (int nt = 0; nt < 8; ++nt)
                mma16816(cacc[nt], aPl, bv2[nt]);
        }
    }

    // ---- epilogue: normalize, split to fp16 hi/lo, write ctx
    const float inv0 = 1.0f / l0, inv1 = 1.0f / l1;
    const int row0 = q0 + wid * 16 + r;
    const size_t ob = ((size_t)(b * Tt) + row0) * Dd + h * HDh;
#pragma unroll
    for (int nt = 0; nt < 8; ++nt) {
        const int col = nt * 8 + c2;
        const float v0 = cacc[nt][0] * inv0, v1 = cacc[nt][1] * inv0;
        const float v2 = cacc[nt][2] * inv1, v3 = cacc[nt][3] * inv1;
        const __half2 h01 = __floats2half2_rn(v0, v1);
        const __half2 h23 = __floats2half2_rn(v2, v3);
        const __half2 q01 = __floats2half2_rn(
            v0 - __half2float(__low2half(h01)), v1 - __half2float(__high2half(h01)));
        const __half2 q23 = __floats2half2_rn(
            v2 - __half2float(__low2half(h23)), v3 - __half2float(__high2half(h23)));
        *(uint32_t*)(och + ob + col)            = h2_bits(h01);
        *(uint32_t*)(ocl + ob + col)            = h2_bits(q01);
        *(uint32_t*)(och + ob + 8 * Dd + col)   = h2_bits(h23);
        *(uint32_t*)(ocl + ob + 8 * Dd + col)   = h2_bits(q23);
    }
}

// ---------------------------------------------------------------------------
extern "C" void kernel_launch(void* const* d_in, const int* in_sizes, int n_in,
                              void* d_out, int out_size)
{
    const float* x  = (const float*)d_in[0];
    const float* Wq = (const float*)d_in[1];
    const float* bq = (const float*)d_in[2];
    const float* Wk = (const float*)d_in[3];
    const float* bk = (const float*)d_in[4];
    const float* Wv = (const float*)d_in[5];
    const float* bv = (const float*)d_in[6];
    const float* Wo = (const float*)d_in[7];
    const float* bo = (const float*)d_in[8];
    const int* mask = (const int*)d_in[9];
    float* out = (float*)d_out;

    __half *xh, *xl, *qhp, *qlp, *khp, *vhp, *chp, *clp, *wh, *wl;
    cudaGetSymbolAddress((void**)&xh, g_xh);
    cudaGetSymbolAddress((void**)&xl, g_xl);
    cudaGetSymbolAddress((void**)&qhp, g_qh);
    cudaGetSymbolAddress((void**)&qlp, g_ql);
    cudaGetSymbolAddress((void**)&khp, g_kh);
    cudaGetSymbolAddress((void**)&vhp, g_vh);
    cudaGetSymbolAddress((void**)&chp, g_ch);
    cudaGetSymbolAddress((void**)&clp, g_cl);
    cudaGetSymbolAddress((void**)&wh, g_wh);
    cudaGetSymbolAddress((void**)&wl, g_wl);

    const size_t WSZ = (size_t)Dd * Dd;
    const int n4x = (Mm * Dd) / 4;
    const int n4w = (int)(WSZ / 4);

    // launch 0: split x; launch 1: split all weights
    split_x_kernel<<<(n4x + 255) / 256, 256>>>(x, xh, xl, n4x);
    split_w4_kernel<<<(4 * n4w + 255) / 256, 256>>>(Wq, Wk, Wv, Wo, wh, wl, n4w);

    cudaFuncSetAttribute(gemm_fp16s_mma,
                         cudaFuncAttributeMaxDynamicSharedMemorySize, GSMEM_B);
    dim3 ggrid(Dd / 128, Mm / 128);
    // launch 2: Q projection 3-pass -> fp16 hi/lo (pre-scaled 1/8)
    gemm_fp16s_mma<<<ggrid, 256, GSMEM_B>>>(xh, xl, wh + 0 * WSZ, wl + 0 * WSZ, bq,
                                            nullptr, qhp, qlp, 0.125f, 1);
    // launches 3,4: K,V projections 2-pass -> single fp16
    gemm_fp16s_mma<<<ggrid, 256, GSMEM_B>>>(xh, xl, wh + 1 * WSZ, wl + 1 * WSZ, bk,
                                            nullptr, khp, nullptr, 1.0f, 0);
    gemm_fp16s_mma<<<ggrid, 256, GSMEM_B>>>(xh, xl, wh + 2 * WSZ, wl + 2 * WSZ, bv,
                                            nullptr, vhp, nullptr, 1.0f, 0);

    // launch 5: fused attention (ncu -s 5 captures this one)
    cudaFuncSetAttribute(attn_mma_kernel,
                         cudaFuncAttributeMaxDynamicSharedMemorySize, AT_SMEM);
    attn_mma_kernel<<<dim3(Tt / 128, Hh, Bb), 256, AT_SMEM>>>(
        qhp, qlp, khp, vhp, mask, chp, clp);

    // launch 6: output projection 2-pass -> fp32
    gemm_fp16s_mma<<<ggrid, 256, GSMEM_B>>>(chp, clp, wh + 3 * WSZ, wl + 3 * WSZ, bo,
                                            out, nullptr, nullptr, 1.0f, 0);
}

// round 12
// speedup vs baseline: 4.0216x; 1.0890x over previous
#include <cuda_runtime.h>
#include <cuda_fp16.h>
#include <cstdint>

// Problem constants
#define Bb  4
#define Tt  2048
#define Dd  1024
#define Hh  16
#define HDh 64
#define Mm  (Bb * Tt)   // 8192 rows

// ---------------------------------------------------------------------------
// Scratch (device globals: allocation-free rule). All fp16.
// ---------------------------------------------------------------------------
__device__ __half g_xh[(size_t)Mm * Dd];
__device__ __half g_xl[(size_t)Mm * Dd];
__device__ __half g_qh[(size_t)Mm * Dd];
__device__ __half g_ql[(size_t)Mm * Dd];
__device__ __half g_kh[(size_t)Mm * Dd];          // K single-rounded
__device__ __half g_vh[(size_t)Mm * Dd];          // V single-rounded
__device__ __half g_ch[(size_t)Mm * Dd];
__device__ __half g_cl[(size_t)Mm * Dd];
__device__ __half g_wh[4 * (size_t)Dd * Dd];
__device__ __half g_wl[4 * (size_t)Dd * Dd];

// ---------------------------------------------------------------------------
// sm_100-base helpers: cp.async + mma.sync fp16 (tcgen05 unavailable here)
// ---------------------------------------------------------------------------
__device__ __forceinline__ uint32_t smem_to_u32(const void* p) {
    uint32_t a;
    asm("{ .reg .u64 t; cvta.to.shared.u64 t, %1; cvt.u32.u64 %0, t; }"
        : "=r"(a) : "l"(p));
    return a;
}
__device__ __forceinline__ void cp_async16(uint32_t smem_addr, const void* gptr) {
    asm volatile("cp.async.cg.shared.global [%0], [%1], 16;"
                 :: "r"(smem_addr), "l"(gptr));
}
__device__ __forceinline__ void cp_commit() {
    asm volatile("cp.async.commit_group;");
}
template <int N>
__device__ __forceinline__ void cp_wait() {
    asm volatile("cp.async.wait_group %0;" :: "n"(N));
}
// D += A*B, m16n8k16 fp16 in / fp32 accum; A row-major, B col-major
__device__ __forceinline__ void mma16816(float* d, const uint32_t* a, const uint32_t* b) {
    asm volatile(
        "mma.sync.aligned.m16n8k16.row.col.f32.f16.f16.f32 "
        "{%0,%1,%2,%3}, {%4,%5,%6,%7}, {%8,%9}, {%0,%1,%2,%3};"
        : "+f"(d[0]), "+f"(d[1]), "+f"(d[2]), "+f"(d[3])
        : "r"(a[0]), "r"(a[1]), "r"(a[2]), "r"(a[3]), "r"(b[0]), "r"(b[1]));
}
__device__ __forceinline__ uint32_t h2_bits(__half2 v) {
    union { __half2 h; uint32_t u; } cv; cv.h = v; return cv.u;
}
// hi/lo split of one float into two fp16
__device__ __forceinline__ void split_h(float v, __half& hi, __half& lo) {
    hi = __float2half_rn(v);
    lo = __float2half_rn(v - __half2float(hi));
}

// ---------------------------------------------------------------------------
// Split kernels (fp32 -> fp16 hi/lo)
// ---------------------------------------------------------------------------
__global__ __launch_bounds__(256) void split_x_kernel(
    const float* __restrict__ src,
    __half* __restrict__ hi, __half* __restrict__ lo, int n4)
{
    int i = blockIdx.x * blockDim.x + threadIdx.x;
    if (i >= n4) return;
    float4 v = ((const float4*)src)[i];
    __half h0, h1, h2, h3, l0, l1, l2, l3;
    split_h(v.x, h0, l0); split_h(v.y, h1, l1);
    split_h(v.z, h2, l2); split_h(v.w, h3, l3);
    union { __half b[4]; uint2 u; } ph, pl;
    ph.b[0] = h0; ph.b[1] = h1; ph.b[2] = h2; ph.b[3] = h3;
    pl.b[0] = l0; pl.b[1] = l1; pl.b[2] = l2; pl.b[3] = l3;
    ((uint2*)hi)[i] = ph.u;
    ((uint2*)lo)[i] = pl.u;
}

// all 4 weight matrices in one launch; dest arrays are contiguous per-matrix
__global__ __launch_bounds__(256) void split_w4_kernel(
    const float* __restrict__ w0, const float* __restrict__ w1,
    const float* __restrict__ w2, const float* __restrict__ w3,
    __half* __restrict__ hi, __half* __restrict__ lo, int n4_each)
{
    int i = blockIdx.x * blockDim.x + threadIdx.x;
    if (i >= 4 * n4_each) return;
    const int m = i / n4_each, j = i - m * n4_each;
    const float* src = (m == 0) ? w0 : (m == 1) ? w1 : (m == 2) ? w2 : w3;
    float4 v = ((const float4*)src)[j];
    __half h0, h1, h2, h3, l0, l1, l2, l3;
    split_h(v.x, h0, l0); split_h(v.y, h1, l1);
    split_h(v.z, h2, l2); split_h(v.w, h3, l3);
    union { __half b[4]; uint2 u; } ph, pl;
    ph.b[0] = h0; ph.b[1] = h1; ph.b[2] = h2; ph.b[3] = h3;
    pl.b[0] = l0; pl.b[1] = l1; pl.b[2] = l2; pl.b[3] = l3;
    ((uint2*)hi)[i] = ph.u;
    ((uint2*)lo)[i] = pl.u;
}

// ---------------------------------------------------------------------------
// 3-pass fp16 split GEMM (Q projection): C = (Ah+Al) @ (Bh+Bl)^T + bias,
// dropping Al*Bl. BK=32, double-buffered, single sync per chunk (R12).
// Output: fp16 hi/lo, scaled.
// ---------------------------------------------------------------------------
#define GPITCH 40
#define GTILE_B (128 * GPITCH * 2)
#define GSTAGE_B (4 * GTILE_B)
#define GSMEM_B (2 * GSTAGE_B)

__global__ __launch_bounds__(256, 2) void gemm3p_bk32(
    const __half* __restrict__ Ah, const __half* __restrict__ Al,
    const __half* __restrict__ Bh, const __half* __restrict__ Bl,
    const float* __restrict__ bias,
    __half* __restrict__ Oh, __half* __restrict__ Ol, float scale)
{
    extern __shared__ __align__(128) uint8_t smem[];
    const int tid  = threadIdx.x;
    const int wid  = tid >> 5;
    const int lane = tid & 31;
    const int wm   = wid & 3;
    const int wn   = wid >> 2;
    const int gm0  = blockIdx.y * 128;
    const int gn0  = blockIdx.x * 128;
    const uint32_t sbase = smem_to_u32(smem);

    const __half* srcs[4] = { Ah, Al, Bh, Bl };

    auto issue = [&](int s, int c) {
        const int k0 = c * 32;
#pragma unroll
        for (int t = 0; t < 4; ++t) {
            const __half* src = srcs[t];
            const int rbase = (t < 2) ? gm0 : gn0;
#pragma unroll
            for (int j = 0; j < 2; ++j) {
                const int i = tid + j * 256;
                const int row = i >> 2, chunk = i & 3;
                const uint32_t sa = sbase + s * GSTAGE_B + t * GTILE_B
                                  + (uint32_t)(row * GPITCH + chunk * 8) * 2;
                const void* g = src + (size_t)(rbase + row) * Dd + k0 + chunk * 8;
                cp_async16(sa, g);
            }
        }
        cp_commit();
    };

    float acc[2][8][4];
#pragma unroll
    for (int mt = 0; mt < 2; ++mt)
#pragma unroll
        for (int nt = 0; nt < 8; ++nt)
#pragma unroll
            for (int q = 0; q < 4; ++q) acc[mt][nt][q] = 0.f;

    const int r   = lane >> 2;
    const int cp2 = (lane & 3) * 2;

    issue(0, 0);

    for (int c = 0; c < 32; ++c) {
        const int s = c & 1;
        cp_wait<0>();
        __syncthreads();   // chunk c data visible AND all warps done reading s^1
        if (c + 1 < 32) issue(s ^ 1, c + 1);

        const uint8_t* stg = smem + s * GSTAGE_B;
        const uint8_t* pAh = stg;
        const uint8_t* pAl = stg + GTILE_B;
        const uint8_t* pBh = stg + 2 * GTILE_B;
        const uint8_t* pBl = stg + 3 * GTILE_B;

#pragma unroll
        for (int ks = 0; ks < 2; ++ks) {
            const int kk = ks * 16;
            uint32_t ah[2][4], al[2][4];
#pragma unroll
            for (int mt = 0; mt < 2; ++mt) {
                const int row = wm * 32 + mt * 16 + r;
                const uint32_t o00 = (uint32_t)(row * GPITCH + kk + cp2) * 2;
                const uint32_t o10 = (uint32_t)((row + 8) * GPITCH + kk + cp2) * 2;
                ah[mt][0] = *(const uint32_t*)(pAh + o00);
                ah[mt][1] = *(const uint32_t*)(pAh + o10);
                ah[mt][2] = *(const uint32_t*)(pAh + o00 + 16);
                ah[mt][3] = *(const uint32_t*)(pAh + o10 + 16);
                al[mt][0] = *(const uint32_t*)(pAl + o00);
                al[mt][1] = *(const uint32_t*)(pAl + o10);
                al[mt][2] = *(const uint32_t*)(pAl + o00 + 16);
                al[mt][3] = *(const uint32_t*)(pAl + o10 + 16);
            }
#pragma unroll
            for (int nh = 0; nh < 2; ++nh) {
                uint32_t bh[4][2], bl[4][2];
#pragma unroll
                for (int nt = 0; nt < 4; ++nt) {
                    const int n = wn * 64 + (nh * 4 + nt) * 8 + r;
                    const uint32_t ob = (uint32_t)(n * GPITCH + kk + cp2) * 2;
                    bh[nt][0] = *(const uint32_t*)(pBh + ob);
                    bh[nt][1] = *(const uint32_t*)(pBh + ob + 16);
                    bl[nt][0] = *(const uint32_t*)(pBl + ob);
                    bl[nt][1] = *(const uint32_t*)(pBl + ob + 16);
                }
#pragma unroll
                for (int nt = 0; nt < 4; ++nt) {
                    mma16816(acc[0][nh * 4 + nt], ah[0], bh[nt]);
                    mma16816(acc[1][nh * 4 + nt], ah[1], bh[nt]);
                }
#pragma unroll
                for (int nt = 0; nt < 4; ++nt) {
                    mma16816(acc[0][nh * 4 + nt], al[0], bh[nt]);
                    mma16816(acc[1][nh * 4 + nt], al[1], bh[nt]);
                }
#pragma unroll
                for (int nt = 0; nt < 4; ++nt) {
                    mma16816(acc[0][nh * 4 + nt], ah[0], bl[nt]);
                    mma16816(acc[1][nh * 4 + nt], ah[1], bl[nt]);
                }
            }
        }
    }

    // Epilogue: scaled fp16 hi/lo
#pragma unroll
    for (int mt = 0; mt < 2; ++mt) {
        const int row0 = gm0 + wm * 32 + mt * 16 + r;
#pragma unroll
        for (int nt = 0; nt < 8; ++nt) {
            const int col = gn0 + wn * 64 + nt * 8 + cp2;
            const float b0 = bias[col], b1 = bias[col + 1];
            float v0 = (acc[mt][nt][0] + b0) * scale, v1 = (acc[mt][nt][1] + b1) * scale;
            float v2 = (acc[mt][nt][2] + b0) * scale, v3 = (acc[mt][nt][3] + b1) * scale;
            __half2 h01 = __floats2half2_rn(v0, v1);
            __half2 h23 = __floats2half2_rn(v2, v3);
            __half2 l01 = __floats2half2_rn(
                v0 - __half2float(__low2half(h01)), v1 - __half2float(__high2half(h01)));
            __half2 l23 = __floats2half2_rn(
                v2 - __half2float(__low2half(h23)), v3 - __half2float(__high2half(h23)));
            *(uint32_t*)(Oh + (size_t)row0 * Dd + col)       = h2_bits(h01);
            *(uint32_t*)(Ol + (size_t)row0 * Dd + col)       = h2_bits(l01);
            *(uint32_t*)(Oh + (size_t)(row0 + 8) * Dd + col) = h2_bits(h23);
            *(uint32_t*)(Ol + (size_t)(row0 + 8) * Dd + col) = h2_bits(l23);
        }
    }
}

// ---------------------------------------------------------------------------
// 2-pass fp16 split GEMM (K/V/O projections): C = (Ah+Al) @ Bh^T + bias.
// R12: BK=64 (3 tiles/stage, 110.6 KB smem, still 2 CTAs/SM), single sync
// per chunk. Output: fp16 single (Oh) or fp32 (Cf32).
// ---------------------------------------------------------------------------
#define G2PITCH 72
#define G2TILE_B (128 * G2PITCH * 2)      // 18432
#define G2STAGE_B (3 * G2TILE_B)          // 55296
#define G2SMEM_B (2 * G2STAGE_B)          // 110592

__global__ __launch_bounds__(256, 2) void gemm2p_bk64(
    const __half* __restrict__ Ah, const __half* __restrict__ Al,
    const __half* __restrict__ Bh,
    const float* __restrict__ bias,
    float* __restrict__ Cf32, __half* __restrict__ Oh)
{
    extern __shared__ __align__(128) uint8_t smem[];
    const int tid  = threadIdx.x;
    const int wid  = tid >> 5;
    const int lane = tid & 31;
    const int wm   = wid & 3;
    const int wn   = wid >> 2;
    const int gm0  = blockIdx.y * 128;
    const int gn0  = blockIdx.x * 128;
    const uint32_t sbase = smem_to_u32(smem);

    const __half* srcs[3] = { Ah, Al, Bh };

    auto issue = [&](int s, int c) {
        const int k0 = c * 64;
#pragma unroll
        for (int t = 0; t < 3; ++t) {
            const __half* src = srcs[t];
            const int rbase = (t < 2) ? gm0 : gn0;
#pragma unroll
            for (int j = 0; j < 4; ++j) {
                const int i = tid + j * 256;           // 0..1023
                const int row = i >> 3, seg = i & 7;   // 8x16B per 128B row
                const uint32_t sa = sbase + s * G2STAGE_B + t * G2TILE_B
                                  + (uint32_t)(row * G2PITCH + seg * 8) * 2;
                const void* g = src + (size_t)(rbase + row) * Dd + k0 + seg * 8;
                cp_async16(sa, g);
            }
        }
        cp_commit();
    };

    float acc[2][8][4];
#pragma unroll
    for (int mt = 0; mt < 2; ++mt)
#pragma unroll
        for (int nt = 0; nt < 8; ++nt)
#pragma unroll
            for (int q = 0; q < 4; ++q) acc[mt][nt][q] = 0.f;

    const int r   = lane >> 2;
    const int cp2 = (lane & 3) * 2;

    issue(0, 0);

    for (int c = 0; c < 16; ++c) {
        const int s = c & 1;
        cp_wait<0>();
        __syncthreads();   // chunk c data visible AND all warps done reading s^1
        if (c + 1 < 16) issue(s ^ 1, c + 1);

        const uint8_t* stg = smem + s * G2STAGE_B;
        const uint8_t* pAh = stg;
        const uint8_t* pAl = stg + G2TILE_B;
        const uint8_t* pBh = stg + 2 * G2TILE_B;

#pragma unroll
        for (int ks = 0; ks < 4; ++ks) {
            const int kk = ks * 16;
            uint32_t ah[2][4], al[2][4];
#pragma unroll
            for (int mt = 0; mt < 2; ++mt) {
                const int row = wm * 32 + mt * 16 + r;
                const uint32_t o00 = (uint32_t)(row * G2PITCH + kk + cp2) * 2;
                const uint32_t o10 = (uint32_t)((row + 8) * G2PITCH + kk + cp2) * 2;
                ah[mt][0] = *(const uint32_t*)(pAh + o00);
                ah[mt][1] = *(const uint32_t*)(pAh + o10);
                ah[mt][2] = *(const uint32_t*)(pAh + o00 + 16);
                ah[mt][3] = *(const uint32_t*)(pAh + o10 + 16);
                al[mt][0] = *(const uint32_t*)(pAl + o00);
                al[mt][1] = *(const uint32_t*)(pAl + o10);
                al[mt][2] = *(const uint32_t*)(pAl + o00 + 16);
                al[mt][3] = *(const uint32_t*)(pAl + o10 + 16);
            }
#pragma unroll
            for (int nh = 0; nh < 2; ++nh) {
                uint32_t bh[4][2];
#pragma unroll
                for (int nt = 0; nt < 4; ++nt) {
                    const int n = wn * 64 + (nh * 4 + nt) * 8 + r;
                    const uint32_t ob = (uint32_t)(n * G2PITCH + kk + cp2) * 2;
                    bh[nt][0] = *(const uint32_t*)(pBh + ob);
                    bh[nt][1] = *(const uint32_t*)(pBh + ob + 16);
                }
#pragma unroll
                for (int nt = 0; nt < 4; ++nt) {
                    mma16816(acc[0][nh * 4 + nt], ah[0], bh[nt]);
                    mma16816(acc[1][nh * 4 + nt], ah[1], bh[nt]);
                }
#pragma unroll
                for (int nt = 0; nt < 4; ++nt) {
                    mma16816(acc[0][nh * 4 + nt], al[0], bh[nt]);
                    mma16816(acc[1][nh * 4 + nt], al[1], bh[nt]);
                }
            }
        }
    }

    // Epilogue
#pragma unroll
    for (int mt = 0; mt < 2; ++mt) {
        const int row0 = gm0 + wm * 32 + mt * 16 + r;
#pragma unroll
        for (int nt = 0; nt < 8; ++nt) {
            const int col = gn0 + wn * 64 + nt * 8 + cp2;
            const float b0 = bias[col], b1 = bias[col + 1];
            float v0 = acc[mt][nt][0] + b0, v1 = acc[mt][nt][1] + b1;
            float v2 = acc[mt][nt][2] + b0, v3 = acc[mt][nt][3] + b1;
            if (Cf32) {
                float2 w0, w1;
                w0.x = v0; w0.y = v1; w1.x = v2; w1.y = v3;
                *(float2*)(Cf32 + (size_t)row0 * Dd + col)       = w0;
                *(float2*)(Cf32 + (size_t)(row0 + 8) * Dd + col) = w1;
            } else {
                __half2 h01 = __floats2half2_rn(v0, v1);
                __half2 h23 = __floats2half2_rn(v2, v3);
                *(uint32_t*)(Oh + (size_t)row0 * Dd + col)       = h2_bits(h01);
                *(uint32_t*)(Oh + (size_t)(row0 + 8) * Dd + col) = h2_bits(h23);
            }
        }
    }
}

// ---------------------------------------------------------------------------
// Flash attention, fp16 mma.sync (unchanged from R11 — at the HMMA ceiling).
// S = (Qh+Ql) @ K (K single fp16); PV = (Ph+Pl) @ Vh.
// Grid (T/128, H, B), 256 threads = 8 warps; warp w owns q rows [16w,16w+16).
// Q pre-scaled by 1/8 in the Q projection epilogue.
// ---------------------------------------------------------------------------
#define QPITCH 72     // fp16; pitch%64==8 -> conflict-free frag loads
#define VPITCH 136
#define AT_QH   0
#define AT_QL   18432
#define AT_K0   36864          // + s*18432 (K hi only)
#define AT_VH   73728
#define AT_BIAS 91136
#define AT_SMEM 91648

__global__ __launch_bounds__(256, 1) void attn_mma_kernel(
    const __half* __restrict__ qh, const __half* __restrict__ ql,
    const __half* __restrict__ kh,
    const __half* __restrict__ vh,
    const int* __restrict__ mask,
    __half* __restrict__ och, __half* __restrict__ ocl)
{
    extern __shared__ __align__(128) uint8_t sm[];
    const uint32_t sb = smem_to_u32(sm);
    const int tid = threadIdx.x, wid = tid >> 5, lane = tid & 31;
    const int r = lane >> 2, c2 = (lane & 3) * 2;
    const int b = blockIdx.z, h = blockIdx.y;
    const int q0 = blockIdx.x * 128;
    const size_t gq = ((size_t)(b * Tt + q0)) * Dd + h * HDh;
    const size_t gk = ((size_t)(b * Tt)) * Dd + h * HDh;
    const int* mb = mask + b * Tt;

    // ---- preamble: stage Q (hi/lo) and K tile 0 via cp.async
#pragma unroll
    for (int j = 0; j < 4; ++j) {
        const int i = tid + j * 256, row = i >> 3, seg = i & 7;
        const uint32_t so = (uint32_t)((row * QPITCH + seg * 8) * 2);
        const size_t go = (size_t)row * Dd + seg * 8;
        cp_async16(sb + AT_QH + so, qh + gq + go);
        cp_async16(sb + AT_QL + so, ql + gq + go);
        cp_async16(sb + AT_K0 + so, kh + gk + go);
    }
    cp_commit();

    // ---- V register prefetch: thread -> kv rows 2vj,2vj+1, hd quarter vq*16
    const int vj = tid >> 2;
    const int vq = tid & 3;
    uint4 vr_h[2][2];
#pragma unroll
    for (int rr = 0; rr < 2; ++rr) {
        const size_t g = ((size_t)(b * Tt + 2 * vj + rr)) * Dd + h * HDh + vq * 16;
        vr_h[rr][0] = *(const uint4*)(vh + g);
        vr_h[rr][1] = *(const uint4*)(vh + g + 8);
    }

    float cacc[8][4];
#pragma unroll
    for (int nt = 0; nt < 8; ++nt)
#pragma unroll
        for (int q = 0; q < 4; ++q) cacc[nt][q] = 0.f;
    float m0 = -1e30f, m1 = -1e30f, l0 = 0.f, l1 = 0.f;
    uint32_t qAh[4][4], qAl[4][4];

    for (int c = 0; c < 16; ++c) {
        const int kv0 = c * 128;
        const int s = c & 1;
        cp_wait<0>();
        __syncthreads();   // K(c) visible; prev iter's Vt/K reads done

        // stage V^T(c) from regs (packed pairs via prmt) + mask bias
#pragma unroll
        for (int w = 0; w < 8; ++w) {
            const uint32_t a0 = ((const uint32_t*)&vr_h[0])[w];
            const uint32_t a1 = ((const uint32_t*)&vr_h[1])[w];
            const int hd = vq * 16 + 2 * w;
            *(uint32_t*)(sm + AT_VH + ((hd)     * VPITCH + 2 * vj) * 2) = __byte_perm(a0, a1, 0x5410);
            *(uint32_t*)(sm + AT_VH + ((hd + 1) * VPITCH + 2 * vj) * 2) = __byte_perm(a0, a1, 0x7632);
        }
        if (tid < 128)
            ((float*)(sm + AT_BIAS))[tid] = (mb[kv0 + tid] == 0) ? -1e30f : 0.f;

        // prefetch V(c+1) into regs
        if (c + 1 < 16) {
#pragma unroll
            for (int rr = 0; rr < 2; ++rr) {
                const size_t g = ((size_t)(b * Tt + kv0 + 128 + 2 * vj + rr)) * Dd + h * HDh + vq * 16;
                vr_h[rr][0] = *(const uint4*)(vh + g);
                vr_h[rr][1] = *(const uint4*)(vh + g + 8);
            }
        }

        if (c == 0) {   // Q A-frags, hoisted
#pragma unroll
            for (int kt = 0; kt < 4; ++kt) {
                const uint32_t o  = (uint32_t)(((wid * 16 + r) * QPITCH + kt * 16 + c2) * 2);
                const uint32_t o8 = o + 8 * QPITCH * 2;
                qAh[kt][0] = *(const uint32_t*)(sm + AT_QH + o);
                qAh[kt][1] = *(const uint32_t*)(sm + AT_QH + o8);
                qAh[kt][2] = *(const uint32_t*)(sm + AT_QH + o + 16);
                qAh[kt][3] = *(const uint32_t*)(sm + AT_QH + o8 + 16);
                qAl[kt][0] = *(const uint32_t*)(sm + AT_QL + o);
                qAl[kt][1] = *(const uint32_t*)(sm + AT_QL + o8);
                qAl[kt][2] = *(const uint32_t*)(sm + AT_QL + o + 16);
                qAl[kt][3] = *(const uint32_t*)(sm + AT_QL + o8 + 16);
            }
        }

        // prefetch K(c+1) -> stage s^1 (safe: all warps past sync above)
        if (c + 1 < 16) {
#pragma unroll
            for (int j = 0; j < 4; ++j) {
                const int i = tid + j * 256, row = i >> 3, seg = i & 7;
                const uint32_t so = (uint32_t)((row * QPITCH + seg * 8) * 2);
                const size_t g = gk + (size_t)(kv0 + 128 + row) * Dd + seg * 8;
                cp_async16(sb + AT_K0 + (s ^ 1) * 18432 + so, kh + g);
            }
        }
        cp_commit();
        __syncthreads();   // Vt(c), bias visible

        // ---- S = (Qh+Ql) K^T  (pass-ordered, distance-8 acc reuse)
        const uint8_t* Ksh = sm + AT_K0 + s * 18432;
        float sacc[16][4];
#pragma unroll
        for (int nt = 0; nt < 16; ++nt)
#pragma unroll
            for (int q = 0; q < 4; ++q) sacc[nt][q] = 0.f;
#pragma unroll
        for (int kt = 0; kt < 4; ++kt) {
#pragma unroll
            for (int nh = 0; nh < 2; ++nh) {
                uint32_t bk2[8][2];
#pragma unroll
                for (int nt = 0; nt < 8; ++nt) {
                    const uint32_t o = (uint32_t)((((nh * 8 + nt) * 8 + r) * QPITCH + kt * 16 + c2) * 2);
                    bk2[nt][0] = *(const uint32_t*)(Ksh + o);
                    bk2[nt][1] = *(const uint32_t*)(Ksh + o + 16);
                }
#pragma unroll
                for (int nt = 0; nt < 8; ++nt)
                    mma16816(sacc[nh * 8 + nt], qAh[kt], bk2[nt]);
#pragma unroll
                for (int nt = 0; nt < 8; ++nt)
                    mma16816(sacc[nh * 8 + nt], qAl[kt], bk2[nt]);
            }
        }

        // ---- mask bias + online softmax
        const float* bias = (const float*)(sm + AT_BIAS);
        float tmax0 = -1e30f, tmax1 = -1e30f;
#pragma unroll
        for (int nt = 0; nt < 16; ++nt) {
            const float2 bv = *(const float2*)(bias + nt * 8 + c2);
            sacc[nt][0] += bv.x; sacc[nt][1] += bv.y;
            sacc[nt][2] += bv.x; sacc[nt][3] += bv.y;
            tmax0 = fmaxf(tmax0, fmaxf(sacc[nt][0], sacc[nt][1]));
            tmax1 = fmaxf(tmax1, fmaxf(sacc[nt][2], sacc[nt][3]));
        }
        tmax0 = fmaxf(tmax0, __shfl_xor_sync(0xffffffffu, tmax0, 1));
        tmax0 = fmaxf(tmax0, __shfl_xor_sync(0xffffffffu, tmax0, 2));
        tmax1 = fmaxf(tmax1, __shfl_xor_sync(0xffffffffu, tmax1, 1));
        tmax1 = fmaxf(tmax1, __shfl_xor_sync(0xffffffffu, tmax1, 2));
        const float mn0 = fmaxf(m0, tmax0), mn1 = fmaxf(m1, tmax1);
        const float al0 = __expf(m0 - mn0), al1 = __expf(m1 - mn1);
        m0 = mn0; m1 = mn1;
        float rs0 = 0.f, rs1 = 0.f;
#pragma unroll
        for (int nt = 0; nt < 16; ++nt) {
            sacc[nt][0] = __expf(sacc[nt][0] - mn0);
            sacc[nt][1] = __expf(sacc[nt][1] - mn0);
            sacc[nt][2] = __expf(sacc[nt][2] - mn1);
            sacc[nt][3] = __expf(sacc[nt][3] - mn1);
            rs0 += sacc[nt][0] + sacc[nt][1];
            rs1 += sacc[nt][2] + sacc[nt][3];
        }
        rs0 += __shfl_xor_sync(0xffffffffu, rs0, 1);
        rs0 += __shfl_xor_sync(0xffffffffu, rs0, 2);
        rs1 += __shfl_xor_sync(0xffffffffu, rs1, 1);
        rs1 += __shfl_xor_sync(0xffffffffu, rs1, 2);
        l0 = l0 * al0 + rs0;
        l1 = l1 * al1 + rs1;
#pragma unroll
        for (int nt = 0; nt < 8; ++nt) {
            cacc[nt][0] *= al0; cacc[nt][1] *= al0;
            cacc[nt][2] *= al1; cacc[nt][3] *= al1;
        }

        // ---- PV: P frags (fp16 hi/lo) x V^T hi (pass-ordered)
#pragma unroll
        for (int kt = 0; kt < 8; ++kt) {
            uint32_t aPh[4], aPl[4];
#pragma unroll
            for (int u = 0; u < 2; ++u) {
                const float p0 = sacc[2 * kt + u][0], p1 = sacc[2 * kt + u][1];
                const float p2 = sacc[2 * kt + u][2], p3 = sacc[2 * kt + u][3];
                const __half2 h01 = __floats2half2_rn(p0, p1);
                const __half2 h23 = __floats2half2_rn(p2, p3);
                const __half2 q01 = __floats2half2_rn(
                    p0 - __half2float(__low2half(h01)), p1 - __half2float(__high2half(h01)));
                const __half2 q23 = __floats2half2_rn(
                    p2 - __half2float(__low2half(h23)), p3 - __half2float(__high2half(h23)));
                aPh[2 * u + 0] = h2_bits(h01);
                aPh[2 * u + 1] = h2_bits(h23);
                aPl[2 * u + 0] = h2_bits(q01);
                aPl[2 * u + 1] = h2_bits(q23);
            }
            uint32_t bv2[8][2];
#pragma unroll
            for (int nt = 0; nt < 8; ++nt) {
                const uint32_t o = (uint32_t)(((nt * 8 + r) * VPITCH + kt * 16 + c2) * 2);
                bv2[nt][0] = *(const uint32_t*)(sm + AT_VH + o);
                bv2[nt][1] = *(const uint32_t*)(sm + AT_VH + o + 16);
            }
#pragma unroll
            for (int nt = 0; nt < 8; ++nt)
                mma16816(cacc[nt], aPh, bv2[nt]);
#pragma unroll
            for (int nt = 0; nt < 8; ++nt)
                mma16816(cacc[nt], aPl, bv2[nt]);
        }
    }

    // ---- epilogue: normalize, split to fp16 hi/lo, write ctx
    const float inv0 = 1.0f / l0, inv1 = 1.0f / l1;
    const int row0 = q0 + wid * 16 + r;
    const size_t ob = ((size_t)(b * Tt) + row0) * Dd + h * HDh;
#pragma unroll
    for (int nt = 0; nt < 8; ++nt) {
        const int col = nt * 8 + c2;
        const float v0 = cacc[nt][0] * inv0, v1 = cacc[nt][1] * inv0;
        const float v2 = cacc[nt][2] * inv1, v3 = cacc[nt][3] * inv1;
        const __half2 h01 = __floats2half2_rn(v0, v1);
        const __half2 h23 = __floats2half2_rn(v2, v3);
        const __half2 q01 = __floats2half2_rn(
            v0 - __half2float(__low2half(h01)), v1 - __half2float(__high2half(h01)));
        const __half2 q23 = __floats2half2_rn(
            v2 - __half2float(__low2half(h23)), v3 - __half2float(__high2half(h23)));
        *(uint32_t*)(och + ob + col)            = h2_bits(h01);
        *(uint32_t*)(ocl + ob + col)            = h2_bits(q01);
        *(uint32_t*)(och + ob + 8 * Dd + col)   = h2_bits(h23);
        *(uint32_t*)(ocl + ob + 8 * Dd + col)   = h2_bits(q23);
    }
}

// ---------------------------------------------------------------------------
extern "C" void kernel_launch(void* const* d_in, const int* in_sizes, int n_in,
                              void* d_out, int out_size)
{
    const float* x  = (const float*)d_in[0];
    const float* Wq = (const float*)d_in[1];
    const float* bq = (const float*)d_in[2];
    const float* Wk = (const float*)d_in[3];
    const float* bk = (const float*)d_in[4];
    const float* Wv = (const float*)d_in[5];
    const float* bv = (const float*)d_in[6];
    const float* Wo = (const float*)d_in[7];
    const float* bo = (const float*)d_in[8];
    const int* mask = (const int*)d_in[9];
    float* out = (float*)d_out;

    __half *xh, *xl, *qhp, *qlp, *khp, *vhp, *chp, *clp, *wh, *wl;
    cudaGetSymbolAddress((void**)&xh, g_xh);
    cudaGetSymbolAddress((void**)&xl, g_xl);
    cudaGetSymbolAddress((void**)&qhp, g_qh);
    cudaGetSymbolAddress((void**)&qlp, g_ql);
    cudaGetSymbolAddress((void**)&khp, g_kh);
    cudaGetSymbolAddress((void**)&vhp, g_vh);
    cudaGetSymbolAddress((void**)&chp, g_ch);
    cudaGetSymbolAddress((void**)&clp, g_cl);
    cudaGetSymbolAddress((void**)&wh, g_wh);
    cudaGetSymbolAddress((void**)&wl, g_wl);

    const size_t WSZ = (size_t)Dd * Dd;
    const int n4x = (Mm * Dd) / 4;
    const int n4w = (int)(WSZ / 4);

    // splits
    split_x_kernel<<<(n4x + 255) / 256, 256>>>(x, xh, xl, n4x);
    split_w4_kernel<<<(4 * n4w + 255) / 256, 256>>>(Wq, Wk, Wv, Wo, wh, wl, n4w);

    cudaFuncSetAttribute(gemm3p_bk32,
                         cudaFuncAttributeMaxDynamicSharedMemorySize, GSMEM_B);
    cudaFuncSetAttribute(gemm2p_bk64,
                         cudaFuncAttributeMaxDynamicSharedMemorySize, G2SMEM_B);
    dim3 ggrid(Dd / 128, Mm / 128);

    // Q projection: 3-pass BK32 -> fp16 hi/lo, pre-scaled 1/8
    gemm3p_bk32<<<ggrid, 256, GSMEM_B>>>(xh, xl, wh + 0 * WSZ, wl + 0 * WSZ, bq,
                                         qhp, qlp, 0.125f);
    // K,V projections: 2-pass BK64 -> single fp16
    gemm2p_bk64<<<ggrid, 256, G2SMEM_B>>>(xh, xl, wh + 1 * WSZ, bk, nullptr, khp);
    gemm2p_bk64<<<ggrid, 256, G2SMEM_B>>>(xh, xl, wh + 2 * WSZ, bv, nullptr, vhp);

    // fused attention
    cudaFuncSetAttribute(attn_mma_kernel,
                         cudaFuncAttributeMaxDynamicSharedMemorySize, AT_SMEM);
    attn_mma_kernel<<<dim3(Tt / 128, Hh, Bb), 256, AT_SMEM>>>(
        qhp, qlp, khp, vhp, mask, chp, clp);

    // Output projection: 2-pass BK64 -> fp32
    gemm2p_bk64<<<ggrid, 256, G2SMEM_B>>>(chp, clp, wh + 3 * WSZ, bo, out, nullptr);
}

// round 13
// speedup vs baseline: 4.3262x; 1.0758x over previous
#include <cuda_runtime.h>
#include <cuda_fp16.h>
#include <cstdint>

// Problem constants
#define Bb  4
#define Tt  2048
#define Dd  1024
#define Hh  16
#define HDh 64
#define Mm  (Bb * Tt)   // 8192 rows

// ---------------------------------------------------------------------------
// Scratch (device globals: allocation-free rule). All fp16.
// ---------------------------------------------------------------------------
__device__ __half g_xh[(size_t)Mm * Dd];
__device__ __half g_xl[(size_t)Mm * Dd];
__device__ __half g_qh[(size_t)Mm * Dd];
__device__ __half g_ql[(size_t)Mm * Dd];
__device__ __half g_kh[(size_t)Mm * Dd];          // K single-rounded
__device__ __half g_vh[(size_t)Mm * Dd];          // V single-rounded
__device__ __half g_ch[(size_t)Mm * Dd];
__device__ __half g_cl[(size_t)Mm * Dd];
__device__ __half g_wh[4 * (size_t)Dd * Dd];
__device__ __half g_wl[4 * (size_t)Dd * Dd];

// ---------------------------------------------------------------------------
// sm_100-base helpers: cp.async + mma.sync fp16 (tcgen05 unavailable here)
// ---------------------------------------------------------------------------
__device__ __forceinline__ uint32_t smem_to_u32(const void* p) {
    uint32_t a;
    asm("{ .reg .u64 t; cvta.to.shared.u64 t, %1; cvt.u32.u64 %0, t; }"
        : "=r"(a) : "l"(p));
    return a;
}
__device__ __forceinline__ void cp_async16(uint32_t smem_addr, const void* gptr) {
    asm volatile("cp.async.cg.shared.global [%0], [%1], 16;"
                 :: "r"(smem_addr), "l"(gptr));
}
__device__ __forceinline__ void cp_commit() {
    asm volatile("cp.async.commit_group;");
}
template <int N>
__device__ __forceinline__ void cp_wait() {
    asm volatile("cp.async.wait_group %0;" :: "n"(N));
}
// D += A*B, m16n8k16 fp16 in / fp32 accum; A row-major, B col-major
__device__ __forceinline__ void mma16816(float* d, const uint32_t* a, const uint32_t* b) {
    asm volatile(
        "mma.sync.aligned.m16n8k16.row.col.f32.f16.f16.f32 "
        "{%0,%1,%2,%3}, {%4,%5,%6,%7}, {%8,%9}, {%0,%1,%2,%3};"
        : "+f"(d[0]), "+f"(d[1]), "+f"(d[2]), "+f"(d[3])
        : "r"(a[0]), "r"(a[1]), "r"(a[2]), "r"(a[3]), "r"(b[0]), "r"(b[1]));
}
__device__ __forceinline__ uint32_t h2_bits(__half2 v) {
    union { __half2 h; uint32_t u; } cv; cv.h = v; return cv.u;
}
// hi/lo split of one float into two fp16
__device__ __forceinline__ void split_h(float v, __half& hi, __half& lo) {
    hi = __float2half_rn(v);
    lo = __float2half_rn(v - __half2float(hi));
}

// ---------------------------------------------------------------------------
// Split kernels (fp32 -> fp16 hi/lo)
// ---------------------------------------------------------------------------
__global__ __launch_bounds__(256) void split_x_kernel(
    const float* __restrict__ src,
    __half* __restrict__ hi, __half* __restrict__ lo, int n4)
{
    int i = blockIdx.x * blockDim.x + threadIdx.x;
    if (i >= n4) return;
    float4 v = ((const float4*)src)[i];
    __half h0, h1, h2, h3, l0, l1, l2, l3;
    split_h(v.x, h0, l0); split_h(v.y, h1, l1);
    split_h(v.z, h2, l2); split_h(v.w, h3, l3);
    union { __half b[4]; uint2 u; } ph, pl;
    ph.b[0] = h0; ph.b[1] = h1; ph.b[2] = h2; ph.b[3] = h3;
    pl.b[0] = l0; pl.b[1] = l1; pl.b[2] = l2; pl.b[3] = l3;
    ((uint2*)hi)[i] = ph.u;
    ((uint2*)lo)[i] = pl.u;
}

// all 4 weight matrices in one launch; dest arrays are contiguous per-matrix
__global__ __launch_bounds__(256) void split_w4_kernel(
    const float* __restrict__ w0, const float* __restrict__ w1,
    const float* __restrict__ w2, const float* __restrict__ w3,
    __half* __restrict__ hi, __half* __restrict__ lo, int n4_each)
{
    int i = blockIdx.x * blockDim.x + threadIdx.x;
    if (i >= 4 * n4_each) return;
    const int m = i / n4_each, j = i - m * n4_each;
    const float* src = (m == 0) ? w0 : (m == 1) ? w1 : (m == 2) ? w2 : w3;
    float4 v = ((const float4*)src)[j];
    __half h0, h1, h2, h3, l0, l1, l2, l3;
    split_h(v.x, h0, l0); split_h(v.y, h1, l1);
    split_h(v.z, h2, l2); split_h(v.w, h3, l3);
    union { __half b[4]; uint2 u; } ph, pl;
    ph.b[0] = h0; ph.b[1] = h1; ph.b[2] = h2; ph.b[3] = h3;
    pl.b[0] = l0; pl.b[1] = l1; pl.b[2] = l2; pl.b[3] = l3;
    ((uint2*)hi)[i] = ph.u;
    ((uint2*)lo)[i] = pl.u;
}

// ---------------------------------------------------------------------------
// 3-pass fp16 split GEMM (Q projection): C = (Ah+Al) @ (Bh+Bl)^T + bias,
// dropping Al*Bl. BK=32, double-buffered, single sync per chunk.
// Output: fp16 hi/lo, scaled.
// ---------------------------------------------------------------------------
#define GPITCH 40
#define GTILE_B (128 * GPITCH * 2)
#define GSTAGE_B (4 * GTILE_B)
#define GSMEM_B (2 * GSTAGE_B)

__global__ __launch_bounds__(256, 2) void gemm3p_bk32(
    const __half* __restrict__ Ah, const __half* __restrict__ Al,
    const __half* __restrict__ Bh, const __half* __restrict__ Bl,
    const float* __restrict__ bias,
    __half* __restrict__ Oh, __half* __restrict__ Ol, float scale)
{
    extern __shared__ __align__(128) uint8_t smem[];
    const int tid  = threadIdx.x;
    const int wid  = tid >> 5;
    const int lane = tid & 31;
    const int wm   = wid & 3;
    const int wn   = wid >> 2;
    const int gm0  = blockIdx.y * 128;
    const int gn0  = blockIdx.x * 128;
    const uint32_t sbase = smem_to_u32(smem);

    const __half* srcs[4] = { Ah, Al, Bh, Bl };

    auto issue = [&](int s, int c) {
        const int k0 = c * 32;
#pragma unroll
        for (int t = 0; t < 4; ++t) {
            const __half* src = srcs[t];
            const int rbase = (t < 2) ? gm0 : gn0;
#pragma unroll
            for (int j = 0; j < 2; ++j) {
                const int i = tid + j * 256;
                const int row = i >> 2, chunk = i & 3;
                const uint32_t sa = sbase + s * GSTAGE_B + t * GTILE_B
                                  + (uint32_t)(row * GPITCH + chunk * 8) * 2;
                const void* g = src + (size_t)(rbase + row) * Dd + k0 + chunk * 8;
                cp_async16(sa, g);
            }
        }
        cp_commit();
    };

    float acc[2][8][4];
#pragma unroll
    for (int mt = 0; mt < 2; ++mt)
#pragma unroll
        for (int nt = 0; nt < 8; ++nt)
#pragma unroll
            for (int q = 0; q < 4; ++q) acc[mt][nt][q] = 0.f;

    const int r   = lane >> 2;
    const int cp2 = (lane & 3) * 2;

    issue(0, 0);

    for (int c = 0; c < 32; ++c) {
        const int s = c & 1;
        cp_wait<0>();
        __syncthreads();   // chunk c data visible AND all warps done reading s^1
        if (c + 1 < 32) issue(s ^ 1, c + 1);

        const uint8_t* stg = smem + s * GSTAGE_B;
        const uint8_t* pAh = stg;
        const uint8_t* pAl = stg + GTILE_B;
        const uint8_t* pBh = stg + 2 * GTILE_B;
        const uint8_t* pBl = stg + 3 * GTILE_B;

#pragma unroll
        for (int ks = 0; ks < 2; ++ks) {
            const int kk = ks * 16;
            uint32_t ah[2][4], al[2][4];
#pragma unroll
            for (int mt = 0; mt < 2; ++mt) {
                const int row = wm * 32 + mt * 16 + r;
                const uint32_t o00 = (uint32_t)(row * GPITCH + kk + cp2) * 2;
                const uint32_t o10 = (uint32_t)((row + 8) * GPITCH + kk + cp2) * 2;
                ah[mt][0] = *(const uint32_t*)(pAh + o00);
                ah[mt][1] = *(const uint32_t*)(pAh + o10);
                ah[mt][2] = *(const uint32_t*)(pAh + o00 + 16);
                ah[mt][3] = *(const uint32_t*)(pAh + o10 + 16);
                al[mt][0] = *(const uint32_t*)(pAl + o00);
                al[mt][1] = *(const uint32_t*)(pAl + o10);
                al[mt][2] = *(const uint32_t*)(pAl + o00 + 16);
                al[mt][3] = *(const uint32_t*)(pAl + o10 + 16);
            }
#pragma unroll
            for (int nh = 0; nh < 2; ++nh) {
                uint32_t bh[4][2], bl[4][2];
#pragma unroll
                for (int nt = 0; nt < 4; ++nt) {
                    const int n = wn * 64 + (nh * 4 + nt) * 8 + r;
                    const uint32_t ob = (uint32_t)(n * GPITCH + kk + cp2) * 2;
                    bh[nt][0] = *(const uint32_t*)(pBh + ob);
                    bh[nt][1] = *(const uint32_t*)(pBh + ob + 16);
                    bl[nt][0] = *(const uint32_t*)(pBl + ob);
                    bl[nt][1] = *(const uint32_t*)(pBl + ob + 16);
                }
#pragma unroll
                for (int nt = 0; nt < 4; ++nt) {
                    mma16816(acc[0][nh * 4 + nt], ah[0], bh[nt]);
                    mma16816(acc[1][nh * 4 + nt], ah[1], bh[nt]);
                }
#pragma unroll
                for (int nt = 0; nt < 4; ++nt) {
                    mma16816(acc[0][nh * 4 + nt], al[0], bh[nt]);
                    mma16816(acc[1][nh * 4 + nt], al[1], bh[nt]);
                }
#pragma unroll
                for (int nt = 0; nt < 4; ++nt) {
                    mma16816(acc[0][nh * 4 + nt], ah[0], bl[nt]);
                    mma16816(acc[1][nh * 4 + nt], ah[1], bl[nt]);
                }
            }
        }
    }

    // Epilogue: scaled fp16 hi/lo
#pragma unroll
    for (int mt = 0; mt < 2; ++mt) {
        const int row0 = gm0 + wm * 32 + mt * 16 + r;
#pragma unroll
        for (int nt = 0; nt < 8; ++nt) {
            const int col = gn0 + wn * 64 + nt * 8 + cp2;
            const float b0 = bias[col], b1 = bias[col + 1];
            float v0 = (acc[mt][nt][0] + b0) * scale, v1 = (acc[mt][nt][1] + b1) * scale;
            float v2 = (acc[mt][nt][2] + b0) * scale, v3 = (acc[mt][nt][3] + b1) * scale;
            __half2 h01 = __floats2half2_rn(v0, v1);
            __half2 h23 = __floats2half2_rn(v2, v3);
            __half2 l01 = __floats2half2_rn(
                v0 - __half2float(__low2half(h01)), v1 - __half2float(__high2half(h01)));
            __half2 l23 = __floats2half2_rn(
                v2 - __half2float(__low2half(h23)), v3 - __half2float(__high2half(h23)));
            *(uint32_t*)(Oh + (size_t)row0 * Dd + col)       = h2_bits(h01);
            *(uint32_t*)(Ol + (size_t)row0 * Dd + col)       = h2_bits(l01);
            *(uint32_t*)(Oh + (size_t)(row0 + 8) * Dd + col) = h2_bits(h23);
            *(uint32_t*)(Ol + (size_t)(row0 + 8) * Dd + col) = h2_bits(l23);
        }
    }
}

// ---------------------------------------------------------------------------
// 2-pass fp16 split GEMM (K/V/O projections): C = (Ah+Al) @ Bh^T + bias.
// BK=64 (3 tiles/stage, 110.6 KB smem, 2 CTAs/SM), single sync per chunk.
// Output: fp16 single (Oh) or fp32 (Cf32).
// ---------------------------------------------------------------------------
#define G2PITCH 72
#define G2TILE_B (128 * G2PITCH * 2)      // 18432
#define G2STAGE_B (3 * G2TILE_B)          // 55296
#define G2SMEM_B (2 * G2STAGE_B)          // 110592

__global__ __launch_bounds__(256, 2) void gemm2p_bk64(
    const __half* __restrict__ Ah, const __half* __restrict__ Al,
    const __half* __restrict__ Bh,
    const float* __restrict__ bias,
    float* __restrict__ Cf32, __half* __restrict__ Oh)
{
    extern __shared__ __align__(128) uint8_t smem[];
    const int tid  = threadIdx.x;
    const int wid  = tid >> 5;
    const int lane = tid & 31;
    const int wm   = wid & 3;
    const int wn   = wid >> 2;
    const int gm0  = blockIdx.y * 128;
    const int gn0  = blockIdx.x * 128;
    const uint32_t sbase = smem_to_u32(smem);

    const __half* srcs[3] = { Ah, Al, Bh };

    auto issue = [&](int s, int c) {
        const int k0 = c * 64;
#pragma unroll
        for (int t = 0; t < 3; ++t) {
            const __half* src = srcs[t];
            const int rbase = (t < 2) ? gm0 : gn0;
#pragma unroll
            for (int j = 0; j < 4; ++j) {
                const int i = tid + j * 256;           // 0..1023
                const int row = i >> 3, seg = i & 7;   // 8x16B per 128B row
                const uint32_t sa = sbase + s * G2STAGE_B + t * G2TILE_B
                                  + (uint32_t)(row * G2PITCH + seg * 8) * 2;
                const void* g = src + (size_t)(rbase + row) * Dd + k0 + seg * 8;
                cp_async16(sa, g);
            }
        }
        cp_commit();
    };

    float acc[2][8][4];
#pragma unroll
    for (int mt = 0; mt < 2; ++mt)
#pragma unroll
        for (int nt = 0; nt < 8; ++nt)
#pragma unroll
            for (int q = 0; q < 4; ++q) acc[mt][nt][q] = 0.f;

    const int r   = lane >> 2;
    const int cp2 = (lane & 3) * 2;

    issue(0, 0);

    for (int c = 0; c < 16; ++c) {
        const int s = c & 1;
        cp_wait<0>();
        __syncthreads();   // chunk c data visible AND all warps done reading s^1
        if (c + 1 < 16) issue(s ^ 1, c + 1);

        const uint8_t* stg = smem + s * G2STAGE_B;
        const uint8_t* pAh = stg;
        const uint8_t* pAl = stg + G2TILE_B;
        const uint8_t* pBh = stg + 2 * G2TILE_B;

#pragma unroll
        for (int ks = 0; ks < 4; ++ks) {
            const int kk = ks * 16;
            uint32_t ah[2][4], al[2][4];
#pragma unroll
            for (int mt = 0; mt < 2; ++mt) {
                const int row = wm * 32 + mt * 16 + r;
                const uint32_t o00 = (uint32_t)(row * G2PITCH + kk + cp2) * 2;
                const uint32_t o10 = (uint32_t)((row + 8) * G2PITCH + kk + cp2) * 2;
                ah[mt][0] = *(const uint32_t*)(pAh + o00);
                ah[mt][1] = *(const uint32_t*)(pAh + o10);
                ah[mt][2] = *(const uint32_t*)(pAh + o00 + 16);
                ah[mt][3] = *(const uint32_t*)(pAh + o10 + 16);
                al[mt][0] = *(const uint32_t*)(pAl + o00);
                al[mt][1] = *(const uint32_t*)(pAl + o10);
                al[mt][2] = *(const uint32_t*)(pAl + o00 + 16);
                al[mt][3] = *(const uint32_t*)(pAl + o10 + 16);
            }
#pragma unroll
            for (int nh = 0; nh < 2; ++nh) {
                uint32_t bh[4][2];
#pragma unroll
                for (int nt = 0; nt < 4; ++nt) {
                    const int n = wn * 64 + (nh * 4 + nt) * 8 + r;
                    const uint32_t ob = (uint32_t)(n * G2PITCH + kk + cp2) * 2;
                    bh[nt][0] = *(const uint32_t*)(pBh + ob);
                    bh[nt][1] = *(const uint32_t*)(pBh + ob + 16);
                }
#pragma unroll
                for (int nt = 0; nt < 4; ++nt) {
                    mma16816(acc[0][nh * 4 + nt], ah[0], bh[nt]);
                    mma16816(acc[1][nh * 4 + nt], ah[1], bh[nt]);
                }
#pragma unroll
                for (int nt = 0; nt < 4; ++nt) {
                    mma16816(acc[0][nh * 4 + nt], al[0], bh[nt]);
                    mma16816(acc[1][nh * 4 + nt], al[1], bh[nt]);
                }
            }
        }
    }

    // Epilogue
#pragma unroll
    for (int mt = 0; mt < 2; ++mt) {
        const int row0 = gm0 + wm * 32 + mt * 16 + r;
#pragma unroll
        for (int nt = 0; nt < 8; ++nt) {
            const int col = gn0 + wn * 64 + nt * 8 + cp2;
            const float b0 = bias[col], b1 = bias[col + 1];
            float v0 = acc[mt][nt][0] + b0, v1 = acc[mt][nt][1] + b1;
            float v2 = acc[mt][nt][2] + b0, v3 = acc[mt][nt][3] + b1;
            if (Cf32) {
                float2 w0, w1;
                w0.x = v0; w0.y = v1; w1.x = v2; w1.y = v3;
                *(float2*)(Cf32 + (size_t)row0 * Dd + col)       = w0;
                *(float2*)(Cf32 + (size_t)(row0 + 8) * Dd + col) = w1;
            } else {
                __half2 h01 = __floats2half2_rn(v0, v1);
                __half2 h23 = __floats2half2_rn(v2, v3);
                *(uint32_t*)(Oh + (size_t)row0 * Dd + col)       = h2_bits(h01);
                *(uint32_t*)(Oh + (size_t)(row0 + 8) * Dd + col) = h2_bits(h23);
            }
        }
    }
}

// ---------------------------------------------------------------------------
// Flash attention, fp16 mma.sync.
// S = (Qh+Ql) @ K (K single fp16, 2 MMAs);
// R13: PV = Ph @ Vh (P single-rounded fp16, 1 MMA pass; Pl dropped —
// error ~2.8e-4 relative, unamplified; l stays exact fp32).
// Grid (T/128, H, B), 256 threads = 8 warps; warp w owns q rows [16w,16w+16).
// Q pre-scaled by 1/8 in the Q projection epilogue.
// ---------------------------------------------------------------------------
#define QPITCH 72     // fp16; pitch%64==8 -> conflict-free frag loads
#define VPITCH 136
#define AT_QH   0
#define AT_QL   18432
#define AT_K0   36864          // + s*18432 (K hi only)
#define AT_VH   73728
#define AT_BIAS 91136
#define AT_SMEM 91648

__global__ __launch_bounds__(256, 1) void attn_mma_kernel(
    const __half* __restrict__ qh, const __half* __restrict__ ql,
    const __half* __restrict__ kh,
    const __half* __restrict__ vh,
    const int* __restrict__ mask,
    __half* __restrict__ och, __half* __restrict__ ocl)
{
    extern __shared__ __align__(128) uint8_t sm[];
    const uint32_t sb = smem_to_u32(sm);
    const int tid = threadIdx.x, wid = tid >> 5, lane = tid & 31;
    const int r = lane >> 2, c2 = (lane & 3) * 2;
    const int b = blockIdx.z, h = blockIdx.y;
    const int q0 = blockIdx.x * 128;
    const size_t gq = ((size_t)(b * Tt + q0)) * Dd + h * HDh;
    const size_t gk = ((size_t)(b * Tt)) * Dd + h * HDh;
    const int* mb = mask + b * Tt;

    // ---- preamble: stage Q (hi/lo) and K tile 0 via cp.async
#pragma unroll
    for (int j = 0; j < 4; ++j) {
        const int i = tid + j * 256, row = i >> 3, seg = i & 7;
        const uint32_t so = (uint32_t)((row * QPITCH + seg * 8) * 2);
        const size_t go = (size_t)row * Dd + seg * 8;
        cp_async16(sb + AT_QH + so, qh + gq + go);
        cp_async16(sb + AT_QL + so, ql + gq + go);
        cp_async16(sb + AT_K0 + so, kh + gk + go);
    }
    cp_commit();

    // ---- V register prefetch: thread -> kv rows 2vj,2vj+1, hd quarter vq*16
    const int vj = tid >> 2;
    const int vq = tid & 3;
    uint4 vr_h[2][2];
#pragma unroll
    for (int rr = 0; rr < 2; ++rr) {
        const size_t g = ((size_t)(b * Tt + 2 * vj + rr)) * Dd + h * HDh + vq * 16;
        vr_h[rr][0] = *(const uint4*)(vh + g);
        vr_h[rr][1] = *(const uint4*)(vh + g + 8);
    }

    float cacc[8][4];
#pragma unroll
    for (int nt = 0; nt < 8; ++nt)
#pragma unroll
        for (int q = 0; q < 4; ++q) cacc[nt][q] = 0.f;
    float m0 = -1e30f, m1 = -1e30f, l0 = 0.f, l1 = 0.f;
    uint32_t qAh[4][4], qAl[4][4];

    for (int c = 0; c < 16; ++c) {
        const int kv0 = c * 128;
        const int s = c & 1;
        cp_wait<0>();
        __syncthreads();   // K(c) visible; prev iter's Vt/K reads done

        // stage V^T(c) from regs (packed pairs via prmt) + mask bias
#pragma unroll
        for (int w = 0; w < 8; ++w) {
            const uint32_t a0 = ((const uint32_t*)&vr_h[0])[w];
            const uint32_t a1 = ((const uint32_t*)&vr_h[1])[w];
            const int hd = vq * 16 + 2 * w;
            *(uint32_t*)(sm + AT_VH + ((hd)     * VPITCH + 2 * vj) * 2) = __byte_perm(a0, a1, 0x5410);
            *(uint32_t*)(sm + AT_VH + ((hd + 1) * VPITCH + 2 * vj) * 2) = __byte_perm(a0, a1, 0x7632);
        }
        if (tid < 128)
            ((float*)(sm + AT_BIAS))[tid] = (mb[kv0 + tid] == 0) ? -1e30f : 0.f;

        // prefetch V(c+1) into regs
        if (c + 1 < 16) {
#pragma unroll
            for (int rr = 0; rr < 2; ++rr) {
                const size_t g = ((size_t)(b * Tt + kv0 + 128 + 2 * vj + rr)) * Dd + h * HDh + vq * 16;
                vr_h[rr][0] = *(const uint4*)(vh + g);
                vr_h[rr][1] = *(const uint4*)(vh + g + 8);
            }
        }

        if (c == 0) {   // Q A-frags, hoisted
#pragma unroll
            for (int kt = 0; kt < 4; ++kt) {
                const uint32_t o  = (uint32_t)(((wid * 16 + r) * QPITCH + kt * 16 + c2) * 2);
                const uint32_t o8 = o + 8 * QPITCH * 2;
                qAh[kt][0] = *(const uint32_t*)(sm + AT_QH + o);
                qAh[kt][1] = *(const uint32_t*)(sm + AT_QH + o8);
                qAh[kt][2] = *(const uint32_t*)(sm + AT_QH + o + 16);
                qAh[kt][3] = *(const uint32_t*)(sm + AT_QH + o8 + 16);
                qAl[kt][0] = *(const uint32_t*)(sm + AT_QL + o);
                qAl[kt][1] = *(const uint32_t*)(sm + AT_QL + o8);
                qAl[kt][2] = *(const uint32_t*)(sm + AT_QL + o + 16);
                qAl[kt][3] = *(const uint32_t*)(sm + AT_QL + o8 + 16);
            }
        }

        // prefetch K(c+1) -> stage s^1 (safe: all warps past sync above)
        if (c + 1 < 16) {
#pragma unroll
            for (int j = 0; j < 4; ++j) {
                const int i = tid + j * 256, row = i >> 3, seg = i & 7;
                const uint32_t so = (uint32_t)((row * QPITCH + seg * 8) * 2);
                const size_t g = gk + (size_t)(kv0 + 128 + row) * Dd + seg * 8;
                cp_async16(sb + AT_K0 + (s ^ 1) * 18432 + so, kh + g);
            }
        }
        cp_commit();
        __syncthreads();   // Vt(c), bias visible

        // ---- S = (Qh+Ql) K^T  (pass-ordered, distance-8 acc reuse)
        const uint8_t* Ksh = sm + AT_K0 + s * 18432;
        float sacc[16][4];
#pragma unroll
        for (int nt = 0; nt < 16; ++nt)
#pragma unroll
            for (int q = 0; q < 4; ++q) sacc[nt][q] = 0.f;
#pragma unroll
        for (int kt = 0; kt < 4; ++kt) {
#pragma unroll
            for (int nh = 0; nh < 2; ++nh) {
                uint32_t bk2[8][2];
#pragma unroll
                for (int nt = 0; nt < 8; ++nt) {
                    const uint32_t o = (uint32_t)((((nh * 8 + nt) * 8 + r) * QPITCH + kt * 16 + c2) * 2);
                    bk2[nt][0] = *(const uint32_t*)(Ksh + o);
                    bk2[nt][1] = *(const uint32_t*)(Ksh + o + 16);
                }
#pragma unroll
                for (int nt = 0; nt < 8; ++nt)
                    mma16816(sacc[nh * 8 + nt], qAh[kt], bk2[nt]);
#pragma unroll
                for (int nt = 0; nt < 8; ++nt)
                    mma16816(sacc[nh * 8 + nt], qAl[kt], bk2[nt]);
            }
        }

        // ---- mask bias + online softmax
        const float* bias = (const float*)(sm + AT_BIAS);
        float tmax0 = -1e30f, tmax1 = -1e30f;
#pragma unroll
        for (int nt = 0; nt < 16; ++nt) {
            const float2 bv = *(const float2*)(bias + nt * 8 + c2);
            sacc[nt][0] += bv.x; sacc[nt][1] += bv.y;
            sacc[nt][2] += bv.x; sacc[nt][3] += bv.y;
            tmax0 = fmaxf(tmax0, fmaxf(sacc[nt][0], sacc[nt][1]));
            tmax1 = fmaxf(tmax1, fmaxf(sacc[nt][2], sacc[nt][3]));
        }
        tmax0 = fmaxf(tmax0, __shfl_xor_sync(0xffffffffu, tmax0, 1));
        tmax0 = fmaxf(tmax0, __shfl_xor_sync(0xffffffffu, tmax0, 2));
        tmax1 = fmaxf(tmax1, __shfl_xor_sync(0xffffffffu, tmax1, 1));
        tmax1 = fmaxf(tmax1, __shfl_xor_sync(0xffffffffu, tmax1, 2));
        const float mn0 = fmaxf(m0, tmax0), mn1 = fmaxf(m1, tmax1);
        const float al0 = __expf(m0 - mn0), al1 = __expf(m1 - mn1);
        m0 = mn0; m1 = mn1;
        float rs0 = 0.f, rs1 = 0.f;
#pragma unroll
        for (int nt = 0; nt < 16; ++nt) {
            sacc[nt][0] = __expf(sacc[nt][0] - mn0);
            sacc[nt][1] = __expf(sacc[nt][1] - mn0);
            sacc[nt][2] = __expf(sacc[nt][2] - mn1);
            sacc[nt][3] = __expf(sacc[nt][3] - mn1);
            rs0 += sacc[nt][0] + sacc[nt][1];
            rs1 += sacc[nt][2] + sacc[nt][3];
        }
        rs0 += __shfl_xor_sync(0xffffffffu, rs0, 1);
        rs0 += __shfl_xor_sync(0xffffffffu, rs0, 2);
        rs1 += __shfl_xor_sync(0xffffffffu, rs1, 1);
        rs1 += __shfl_xor_sync(0xffffffffu, rs1, 2);
        l0 = l0 * al0 + rs0;
        l1 = l1 * al1 + rs1;
#pragma unroll
        for (int nt = 0; nt < 8; ++nt) {
            cacc[nt][0] *= al0; cacc[nt][1] *= al0;
            cacc[nt][2] *= al1; cacc[nt][3] *= al1;
        }

        // ---- PV: P (single fp16) x V^T (R13: one pass, Pl dropped)
#pragma unroll
        for (int kt = 0; kt < 8; ++kt) {
            uint32_t aPh[4];
#pragma unroll
            for (int u = 0; u < 2; ++u) {
                const float p0 = sacc[2 * kt + u][0], p1 = sacc[2 * kt + u][1];
                const float p2 = sacc[2 * kt + u][2], p3 = sacc[2 * kt + u][3];
                aPh[2 * u + 0] = h2_bits(__floats2half2_rn(p0, p1));
                aPh[2 * u + 1] = h2_bits(__floats2half2_rn(p2, p3));
            }
            uint32_t bv2[8][2];
#pragma unroll
            for (int nt = 0; nt < 8; ++nt) {
                const uint32_t o = (uint32_t)(((nt * 8 + r) * VPITCH + kt * 16 + c2) * 2);
                bv2[nt][0] = *(const uint32_t*)(sm + AT_VH + o);
                bv2[nt][1] = *(const uint32_t*)(sm + AT_VH + o + 16);
            }
#pragma unroll
            for (int nt = 0; nt < 8; ++nt)
                mma16816(cacc[nt], aPh, bv2[nt]);
        }
    }

    // ---- epilogue: normalize, split to fp16 hi/lo, write ctx
    const float inv0 = 1.0f / l0, inv1 = 1.0f / l1;
    const int row0 = q0 + wid * 16 + r;
    const size_t ob = ((size_t)(b * Tt) + row0) * Dd + h * HDh;
#pragma unroll
    for (int nt = 0; nt < 8; ++nt) {
        const int col = nt * 8 + c2;
        const float v0 = cacc[nt][0] * inv0, v1 = cacc[nt][1] * inv0;
        const float v2 = cacc[nt][2] * inv1, v3 = cacc[nt][3] * inv1;
        const __half2 h01 = __floats2half2_rn(v0, v1);
        const __half2 h23 = __floats2half2_rn(v2, v3);
        const __half2 q01 = __floats2half2_rn(
            v0 - __half2float(__low2half(h01)), v1 - __half2float(__high2half(h01)));
        const __half2 q23 = __floats2half2_rn(
            v2 - __half2float(__low2half(h23)), v3 - __half2float(__high2half(h23)));
        *(uint32_t*)(och + ob + col)            = h2_bits(h01);
        *(uint32_t*)(ocl + ob + col)            = h2_bits(q01);
        *(uint32_t*)(och + ob + 8 * Dd + col)   = h2_bits(h23);
        *(uint32_t*)(ocl + ob + 8 * Dd + col)   = h2_bits(q23);
    }
}

// ---------------------------------------------------------------------------
extern "C" void kernel_launch(void* const* d_in, const int* in_sizes, int n_in,
                              void* d_out, int out_size)
{
    const float* x  = (const float*)d_in[0];
    const float* Wq = (const float*)d_in[1];
    const float* bq = (const float*)d_in[2];
    const float* Wk = (const float*)d_in[3];
    const float* bk = (const float*)d_in[4];
    const float* Wv = (const float*)d_in[5];
    const float* bv = (const float*)d_in[6];
    const float* Wo = (const float*)d_in[7];
    const float* bo = (const float*)d_in[8];
    const int* mask = (const int*)d_in[9];
    float* out = (float*)d_out;

    __half *xh, *xl, *qhp, *qlp, *khp, *vhp, *chp, *clp, *wh, *wl;
    cudaGetSymbolAddress((void**)&xh, g_xh);
    cudaGetSymbolAddress((void**)&xl, g_xl);
    cudaGetSymbolAddress((void**)&qhp, g_qh);
    cudaGetSymbolAddress((void**)&qlp, g_ql);
    cudaGetSymbolAddress((void**)&khp, g_kh);
    cudaGetSymbolAddress((void**)&vhp, g_vh);
    cudaGetSymbolAddress((void**)&chp, g_ch);
    cudaGetSymbolAddress((void**)&clp, g_cl);
    cudaGetSymbolAddress((void**)&wh, g_wh);
    cudaGetSymbolAddress((void**)&wl, g_wl);

    const size_t WSZ = (size_t)Dd * Dd;
    const int n4x = (Mm * Dd) / 4;
    const int n4w = (int)(WSZ / 4);

    // splits
    split_x_kernel<<<(n4x + 255) / 256, 256>>>(x, xh, xl, n4x);
    split_w4_kernel<<<(4 * n4w + 255) / 256, 256>>>(Wq, Wk, Wv, Wo, wh, wl, n4w);

    cudaFuncSetAttribute(gemm3p_bk32,
                         cudaFuncAttributeMaxDynamicSharedMemorySize, GSMEM_B);
    cudaFuncSetAttribute(gemm2p_bk64,
                         cudaFuncAttributeMaxDynamicSharedMemorySize, G2SMEM_B);
    dim3 ggrid(Dd / 128, Mm / 128);

    // Q projection: 3-pass BK32 -> fp16 hi/lo, pre-scaled 1/8
    gemm3p_bk32<<<ggrid, 256, GSMEM_B>>>(xh, xl, wh + 0 * WSZ, wl + 0 * WSZ, bq,
                                         qhp, qlp, 0.125f);
    // K,V projections: 2-pass BK64 -> single fp16
    gemm2p_bk64<<<ggrid, 256, G2SMEM_B>>>(xh, xl, wh + 1 * WSZ, bk, nullptr, khp);
    gemm2p_bk64<<<ggrid, 256, G2SMEM_B>>>(xh, xl, wh + 2 * WSZ, bv, nullptr, vhp);

    // fused attention
    cudaFuncSetAttribute(attn_mma_kernel,
                         cudaFuncAttributeMaxDynamicSharedMemorySize, AT_SMEM);
    attn_mma_kernel<<<dim3(Tt / 128, Hh, Bb), 256, AT_SMEM>>>(
        qhp, qlp, khp, vhp, mask, chp, clp);

    // Output projection: 2-pass BK64 -> fp32
    gemm2p_bk64<<<ggrid, 256, G2SMEM_B>>>(chp, clp, wh + 3 * WSZ, bo, out, nullptr);
}